// round 2
// baseline (speedup 1.0000x reference)
#include <cuda_runtime.h>
#include <math.h>

#define NN 50000
#define EE 1600000
#define IND 128
#define DD 64
#define G3 192
#define BN_EPS 1e-5f
#define SLOPE 0.2f

// ---------------- scratch (static __device__: no allocation) ----------------
__device__ float g_h0[NN * DD];
__device__ float g_h[NN * DD];
__device__ float g_xt[NN * DD];
__device__ float g_m[NN * DD];
__device__ float g_gi[NN * G3];
__device__ float g_gh[NN * G3];
__device__ float g_adst[NN];
__device__ float g_asrc[NN];
__device__ float g_dinv[NN];
__device__ int   g_cnt[NN];
__device__ int   g_rowstart[NN];
__device__ int   g_cursor[NN];
__device__ int   g_csrc[EE];
__device__ float g_ceb[EE];
__device__ float g_expd[EE];
__device__ float g_wihT[DD * G3];
__device__ float g_whhT[DD * G3];
__device__ float g_bnsum[DD];
__device__ float g_bnsumsq[DD];

// ---------------- generic register-tiled GEMM ----------------
// C[n_rows, P] = A[n_rows, K] @ W[K, P] (+bias[col]) (+extra[row,col])
// block tile: 128 rows x 64 cols, K chunked by 64.
// As stored k-major with XOR swizzle -> conflict-free STS and LDS.
template <int K>
__global__ void __launch_bounds__(256) gemm_kernel(
    const float* __restrict__ A, const float* __restrict__ W,
    const float* __restrict__ bias, const float* __restrict__ extra,
    float* __restrict__ C, int n_rows, int P)
{
    __shared__ float As[64 * 128];   // 32KB
    __shared__ float Ws[64 * 64];    // 16KB  (total 48KB exactly)

    const int t  = threadIdx.x;
    const int n0 = blockIdx.x * 128;
    const int c0 = blockIdx.y * 64;
    const int tn = t & 15;       // 16 row groups
    const int tc = t >> 4;       // 16 col groups

    float acc[8][4];
#pragma unroll
    for (int i = 0; i < 8; ++i)
#pragma unroll
        for (int j = 0; j < 4; ++j) acc[i][j] = 0.f;

    for (int k0 = 0; k0 < K; k0 += 64) {
        __syncthreads();
        // load A tile (transposed into smem, swizzled)
#pragma unroll
        for (int r = 0; r < 32; ++r) {
            int idx = t + 256 * r;
            int nn = idx >> 6, kk = idx & 63;
            int row = n0 + nn;
            float v = (row < n_rows) ? A[row * K + k0 + kk] : 0.f;
            As[kk * 128 + (nn ^ (kk & 31))] = v;
        }
        // load W tile
#pragma unroll
        for (int r = 0; r < 16; ++r) {
            int idx = t + 256 * r;
            int kk = idx >> 6, jj = idx & 63;
            Ws[kk * 64 + jj] = W[(k0 + kk) * P + c0 + jj];
        }
        __syncthreads();

#pragma unroll 16
        for (int kk = 0; kk < 64; ++kk) {
            float a[8], w[4];
#pragma unroll
            for (int i = 0; i < 8; ++i)
                a[i] = As[kk * 128 + ((tn + 16 * i) ^ (kk & 31))];
#pragma unroll
            for (int j = 0; j < 4; ++j)
                w[j] = Ws[kk * 64 + tc * 4 + j];
#pragma unroll
            for (int i = 0; i < 8; ++i)
#pragma unroll
                for (int j = 0; j < 4; ++j)
                    acc[i][j] = fmaf(a[i], w[j], acc[i][j]);
        }
    }

#pragma unroll
    for (int i = 0; i < 8; ++i) {
        int row = n0 + tn + 16 * i;
        if (row < n_rows) {
#pragma unroll
            for (int j = 0; j < 4; ++j) {
                int col = c0 + tc * 4 + j;
                float v = acc[i][j];
                if (bias)  v += bias[col];
                if (extra) v += extra[row * P + col];
                C[row * P + col] = v;
            }
        }
    }
}

// ---------------- small kernels ----------------
__global__ void init_kernel()
{
    int i = blockIdx.x * blockDim.x + threadIdx.x;
    int T = gridDim.x * blockDim.x;
    for (int k = i; k < NN; k += T) g_cnt[k] = 0;
    if (i < DD) { g_bnsum[i] = 0.f; g_bnsumsq[i] = 0.f; }
}

__global__ void bn_stats_kernel()
{
    int t = blockIdx.x * blockDim.x + threadIdx.x;
    int col = t & 63;
    int r0 = t >> 6;
    int rs = (gridDim.x * blockDim.x) >> 6;
    float s = 0.f, ss = 0.f;
    for (int r = r0; r < NN; r += rs) {
        float v = g_h0[r * DD + col];
        s += v; ss += v * v;
    }
    atomicAdd(&g_bnsum[col], s);
    atomicAdd(&g_bnsumsq[col], ss);
}

__global__ void bn_apply_kernel(const float* __restrict__ bn_g,
                                const float* __restrict__ bn_b)
{
    int i = blockIdx.x * blockDim.x + threadIdx.x;
    int T = gridDim.x * blockDim.x;
    const float invn = 1.f / (float)NN;
    for (int k = i; k < NN * DD; k += T) {
        int c = k & 63;
        float mu  = g_bnsum[c] * invn;
        float var = g_bnsumsq[c] * invn - mu * mu;
        float v = (g_h0[k] - mu) * rsqrtf(var + BN_EPS) * bn_g[c] + bn_b[c];
        g_h[k] = v > 0.f ? v : 0.f;
    }
}

__global__ void transpose_kernel(const float* __restrict__ wih,
                                 const float* __restrict__ whh)
{
    int i = blockIdx.x * blockDim.x + threadIdx.x;
    if (i < G3 * DD) {
        int j = i >> 6, k = i & 63;          // wih[j][k], j<192, k<64
        g_wihT[k * G3 + j] = wih[i];
        g_whhT[k * G3 + j] = whh[i];
    }
}

__global__ void hist_kernel(const int* __restrict__ eidx)
{
    int i = blockIdx.x * blockDim.x + threadIdx.x;
    int T = gridDim.x * blockDim.x;
    for (int e = i; e < EE; e += T)
        atomicAdd(&g_cnt[eidx[EE + e]], 1);
}

__global__ void scan_kernel()
{
    __shared__ int sh[1024];
    int t = threadIdx.x;
    const int chunk = (NN + 1023) / 1024;
    int beg = t * chunk;
    int end = beg + chunk; if (end > NN) end = NN;
    int s = 0;
    for (int i = beg; i < end && i < NN; ++i) s += g_cnt[i];
    sh[t] = s;
    __syncthreads();
    for (int off = 1; off < 1024; off <<= 1) {
        int v = (t >= off) ? sh[t - off] : 0;
        __syncthreads();
        sh[t] += v;
        __syncthreads();
    }
    int run = (t > 0) ? sh[t - 1] : 0;
    for (int i = beg; i < end && i < NN; ++i) {
        g_rowstart[i] = run;
        g_cursor[i]   = run;
        run += g_cnt[i];
    }
}

__global__ void scatter_kernel(const int* __restrict__ eidx,
                               const float* __restrict__ edge_attr,
                               const float* __restrict__ att_edge)
{
    float a0 = att_edge[0], a1 = att_edge[1], a2 = att_edge[2];
    int i = blockIdx.x * blockDim.x + threadIdx.x;
    int T = gridDim.x * blockDim.x;
    for (int e = i; e < EE; e += T) {
        int d = eidx[EE + e];
        int s = eidx[e];
        int pos = atomicAdd(&g_cursor[d], 1);
        g_csrc[pos] = s;
        g_ceb[pos] = edge_attr[e * 3 + 0] * a0 + edge_attr[e * 3 + 1] * a1 +
                     edge_attr[e * 3 + 2] * a2;
    }
}

__global__ void attn_node_kernel(const float* __restrict__ att_dst,
                                 const float* __restrict__ att_src)
{
    int n = blockIdx.x * 8 + (threadIdx.x >> 5);
    int lane = threadIdx.x & 31;
    if (n >= NN) return;
    float x0 = g_xt[n * DD + lane], x1 = g_xt[n * DD + 32 + lane];
    float vd = x0 * att_dst[lane] + x1 * att_dst[32 + lane];
    float vs = x0 * att_src[lane] + x1 * att_src[32 + lane];
#pragma unroll
    for (int o = 16; o; o >>= 1) {
        vd += __shfl_xor_sync(0xffffffffu, vd, o);
        vs += __shfl_xor_sync(0xffffffffu, vs, o);
    }
    if (lane == 0) { g_adst[n] = vd; g_asrc[n] = vs; }
}

__global__ void attn_alpha_kernel()
{
    int n = blockIdx.x * 8 + (threadIdx.x >> 5);
    int lane = threadIdx.x & 31;
    if (n >= NN) return;
    int deg = g_cnt[n], s0 = g_rowstart[n];
    float adst = g_adst[n];
    float vmax = -1e30f;
    for (int j = lane; j < deg; j += 32) {
        float l = adst + g_asrc[g_csrc[s0 + j]] + g_ceb[s0 + j];
        l = l >= 0.f ? l : SLOPE * l;
        vmax = fmaxf(vmax, l);
    }
#pragma unroll
    for (int o = 16; o; o >>= 1)
        vmax = fmaxf(vmax, __shfl_xor_sync(0xffffffffu, vmax, o));
    float sum = 0.f;
    for (int j = lane; j < deg; j += 32) {
        float l = adst + g_asrc[g_csrc[s0 + j]] + g_ceb[s0 + j];
        l = l >= 0.f ? l : SLOPE * l;
        float e = __expf(l - vmax);
        g_expd[s0 + j] = e;
        sum += e;
    }
#pragma unroll
    for (int o = 16; o; o >>= 1)
        sum += __shfl_xor_sync(0xffffffffu, sum, o);
    if (lane == 0) g_dinv[n] = 1.f / sum;
}

__global__ void aggregate_kernel()
{
    int n = blockIdx.x * 8 + (threadIdx.x >> 5);
    int lane = threadIdx.x & 31;
    if (n >= NN) return;
    int deg = g_cnt[n], s0 = g_rowstart[n];
    const float2* xt2 = (const float2*)g_xt;
    float ax = 0.f, ay = 0.f;
    int j = 0;
    for (; j + 4 <= deg; j += 4) {
        float w0 = g_expd[s0 + j + 0], w1 = g_expd[s0 + j + 1];
        float w2 = g_expd[s0 + j + 2], w3 = g_expd[s0 + j + 3];
        int i0 = g_csrc[s0 + j + 0], i1 = g_csrc[s0 + j + 1];
        int i2 = g_csrc[s0 + j + 2], i3 = g_csrc[s0 + j + 3];
        float2 v0 = xt2[i0 * 32 + lane];
        float2 v1 = xt2[i1 * 32 + lane];
        float2 v2 = xt2[i2 * 32 + lane];
        float2 v3 = xt2[i3 * 32 + lane];
        ax += w0 * v0.x + w1 * v1.x + w2 * v2.x + w3 * v3.x;
        ay += w0 * v0.y + w1 * v1.y + w2 * v2.y + w3 * v3.y;
    }
    for (; j < deg; ++j) {
        float w = g_expd[s0 + j];
        int si = g_csrc[s0 + j];
        float2 v = xt2[si * 32 + lane];
        ax += w * v.x; ay += w * v.y;
    }
    float dinv = (deg > 0) ? g_dinv[n] : 0.f;
    float2 o;
    o.x = fmaxf(ax * dinv, 0.f);
    o.y = fmaxf(ay * dinv, 0.f);
    ((float2*)g_m)[n * 32 + lane] = o;
}

__global__ void gates_kernel()
{
    int i = blockIdx.x * blockDim.x + threadIdx.x;
    int T = gridDim.x * blockDim.x;
    for (int k = i; k < NN * DD; k += T) {
        int nrow = k >> 6, d = k & 63;
        const float* gi = g_gi + nrow * G3;
        const float* gh = g_gh + nrow * G3;
        float r = 1.f / (1.f + __expf(-(gi[d]       + gh[d])));
        float z = 1.f / (1.f + __expf(-(gi[d + 64]  + gh[d + 64])));
        float t = tanhf(gi[d + 128] + r * gh[d + 128]);
        float h = g_h[k];
        g_h[k] = (1.f - z) * t + z * h;
    }
}

// ---------------- launch ----------------
extern "C" void kernel_launch(void* const* d_in, const int* in_sizes, int n_in,
                              void* d_out, int out_size)
{
    const float* x        = (const float*)d_in[0];
    const float* edge_at  = (const float*)d_in[1];
    const float* mlp_w    = (const float*)d_in[2];
    const float* mlp_b    = (const float*)d_in[3];
    const float* bn_g     = (const float*)d_in[4];
    const float* bn_b     = (const float*)d_in[5];
    const float* conv_w   = (const float*)d_in[6];
    const float* att_dst  = (const float*)d_in[7];
    const float* att_src  = (const float*)d_in[8];
    const float* att_edge = (const float*)d_in[9];
    const float* w_ih     = (const float*)d_in[10];
    const float* w_hh     = (const float*)d_in[11];
    const float* b_ih     = (const float*)d_in[12];
    const float* b_hh     = (const float*)d_in[13];
    const float* lin_w    = (const float*)d_in[14];
    const float* lin_b    = (const float*)d_in[15];
    const int*   eidx     = (const int*)d_in[16];   // int32: JAX x64 disabled
    float* out = (float*)d_out;

    float *p_h0, *p_h, *p_xt, *p_m, *p_gi, *p_gh, *p_wihT, *p_whhT;
    cudaGetSymbolAddress((void**)&p_h0,   g_h0);
    cudaGetSymbolAddress((void**)&p_h,    g_h);
    cudaGetSymbolAddress((void**)&p_xt,   g_xt);
    cudaGetSymbolAddress((void**)&p_m,    g_m);
    cudaGetSymbolAddress((void**)&p_gi,   g_gi);
    cudaGetSymbolAddress((void**)&p_gh,   g_gh);
    cudaGetSymbolAddress((void**)&p_wihT, g_wihT);
    cudaGetSymbolAddress((void**)&p_whhT, g_whhT);

    const int GB = (NN + 127) / 128;       // 391 row blocks
    const int WPB = (NN + 7) / 8;          // 6250 warp-per-node blocks

    init_kernel<<<64, 256>>>();
    gemm_kernel<IND><<<dim3(GB, 1), 256>>>(x, mlp_w, mlp_b, nullptr, p_h0, NN, DD);
    bn_stats_kernel<<<256, 256>>>();
    bn_apply_kernel<<<512, 256>>>(bn_g, bn_b);
    transpose_kernel<<<(G3 * DD + 255) / 256, 256>>>(w_ih, w_hh);
    hist_kernel<<<2048, 256>>>(eidx);
    scan_kernel<<<1, 1024>>>();
    scatter_kernel<<<2048, 256>>>(eidx, edge_at, att_edge);

    for (int step = 0; step < 3; ++step) {
        gemm_kernel<DD><<<dim3(GB, 1), 256>>>(p_h, conv_w, nullptr, nullptr, p_xt, NN, DD);
        attn_node_kernel<<<WPB, 256>>>(att_dst, att_src);
        attn_alpha_kernel<<<WPB, 256>>>();
        aggregate_kernel<<<WPB, 256>>>();
        gemm_kernel<DD><<<dim3(GB, 3), 256>>>(p_m, p_wihT, b_ih, nullptr, p_gi, NN, G3);
        gemm_kernel<DD><<<dim3(GB, 3), 256>>>(p_h, p_whhT, b_hh, nullptr, p_gh, NN, G3);
        gates_kernel<<<512, 256>>>();
    }

    gemm_kernel<IND><<<dim3(GB, 1), 256>>>(x, lin_w, lin_b, p_h, out, NN, DD);
}

// round 3
// speedup vs baseline: 1.6974x; 1.6974x over previous
#include <cuda_runtime.h>
#include <math.h>
#include <stdint.h>

#define NN 50000
#define EE 1600000
#define IND 128
#define DD 64
#define G3 192
#define BN_EPS 1e-5f
#define SLOPE 0.2f

// ---------------- scratch (static __device__: no allocation) ----------------
__device__ float g_h0[NN * DD];
__device__ float g_h[NN * DD];
__device__ float g_xt[NN * DD];
__device__ float g_m[NN * DD];
__device__ float g_gi[NN * G3];
__device__ float g_gh[NN * G3];
__device__ float g_adst[NN];
__device__ float g_asrc[NN];
__device__ float g_dinv[NN];
__device__ int   g_cnt[NN];
__device__ int   g_rowstart[NN];
__device__ int   g_cursor[NN];
__device__ int   g_csrc[EE];
__device__ float g_ceb[EE];
__device__ float g_expd[EE];
__device__ float g_wihT[DD * G3];
__device__ float g_whhT[DD * G3];
__device__ float g_bnsum[DD];
__device__ float g_bnsumsq[DD];

// ---------------- tf32 helpers ----------------
__device__ __forceinline__ unsigned f2tf(float x) {
    unsigned r;
    asm("cvt.rna.tf32.f32 %0, %1;" : "=r"(r) : "f"(x));
    return r;
}

__device__ __forceinline__ void mma_tf32(float c[4], const unsigned a[4],
                                         const unsigned b[2]) {
    asm volatile(
        "mma.sync.aligned.m16n8k8.row.col.f32.tf32.tf32.f32 "
        "{%0,%1,%2,%3}, {%4,%5,%6,%7}, {%8,%9}, {%0,%1,%2,%3};"
        : "+f"(c[0]), "+f"(c[1]), "+f"(c[2]), "+f"(c[3])
        : "r"(a[0]), "r"(a[1]), "r"(a[2]), "r"(a[3]),
          "r"(b[0]), "r"(b[1]));
}

// ---------------- tf32 tensor-core GEMM ----------------
// C[n_rows, P] = A[n_rows, K] @ W[K, P] (+bias[col])
// block tile 128x64, 8 warps of 32x32, K staged in chunks of 64.
template <int K>
__global__ void __launch_bounds__(256) gemm_tf32_kernel(
    const float* __restrict__ A, const float* __restrict__ W,
    const float* __restrict__ bias, float* __restrict__ C,
    int n_rows, int P)
{
    __shared__ uint4 As4[16 * 128];      // 32KB: [kh][m ^ (kh&7)] tf32 bits
    __shared__ unsigned Ws[64 * 64];     // 16KB: [k][n ^ ((k&3)<<3)]

    const int t    = threadIdx.x;
    const int lane = t & 31;
    const int wid  = t >> 5;
    const int warp_m = wid & 3;          // 0..3 -> 32 rows each
    const int warp_n = wid >> 2;         // 0..1 -> 32 cols each
    const int n0 = blockIdx.x * 128;
    const int c0 = blockIdx.y * 64;

    float acc[2][4][4];
#pragma unroll
    for (int mf = 0; mf < 2; ++mf)
#pragma unroll
        for (int nf = 0; nf < 4; ++nf)
#pragma unroll
            for (int r = 0; r < 4; ++r) acc[mf][nf][r] = 0.f;

    const unsigned* Asw = reinterpret_cast<const unsigned*>(As4);
    const int rr = lane >> 2, kl = lane & 3;

    for (int k0 = 0; k0 < K; k0 += 64) {
        __syncthreads();
        // stage A: 128 rows x 16 float4 along K
#pragma unroll
        for (int i = 0; i < 8; ++i) {
            int idx = t + 256 * i;            // 0..2047
            int m  = idx >> 4;
            int kh = idx & 15;
            int row = n0 + m;
            float4 v = make_float4(0.f, 0.f, 0.f, 0.f);
            if (row < n_rows)
                v = *(const float4*)(A + (size_t)row * K + k0 + kh * 4);
            As4[kh * 128 + (m ^ (kh & 7))] =
                make_uint4(f2tf(v.x), f2tf(v.y), f2tf(v.z), f2tf(v.w));
        }
        // stage W: 64 k-rows x 64 cols, swizzled
#pragma unroll
        for (int i = 0; i < 4; ++i) {
            int idx = t + 256 * i;            // 0..1023
            int kk = idx >> 4;
            int n4 = (idx & 15) << 2;
            float4 v = *(const float4*)(W + (size_t)(k0 + kk) * P + c0 + n4);
            int nsw = n4 ^ ((kk & 3) << 3);
            Ws[kk * 64 + nsw + 0] = f2tf(v.x);
            Ws[kk * 64 + nsw + 1] = f2tf(v.y);
            Ws[kk * 64 + nsw + 2] = f2tf(v.z);
            Ws[kk * 64 + nsw + 3] = f2tf(v.w);
        }
        __syncthreads();

#pragma unroll
        for (int ks = 0; ks < 8; ++ks) {
            const int kh0 = ks * 2;
            unsigned a[2][4];
#pragma unroll
            for (int mf = 0; mf < 2; ++mf) {
                int mb = warp_m * 32 + mf * 16 + rr;
                a[mf][0] = Asw[(kh0 * 128 + (mb ^ (kh0 & 7))) * 4 + kl];
                a[mf][1] = Asw[(kh0 * 128 + ((mb + 8) ^ (kh0 & 7))) * 4 + kl];
                a[mf][2] = Asw[((kh0 + 1) * 128 + (mb ^ ((kh0 + 1) & 7))) * 4 + kl];
                a[mf][3] = Asw[((kh0 + 1) * 128 + ((mb + 8) ^ ((kh0 + 1) & 7))) * 4 + kl];
            }
            unsigned b[4][2];
            const int kA = ks * 8 + kl;
            const int kB = kA + 4;
            const int swc = (kl << 3);
#pragma unroll
            for (int nf = 0; nf < 4; ++nf) {
                int n = warp_n * 32 + nf * 8 + rr;
                b[nf][0] = Ws[kA * 64 + (n ^ swc)];
                b[nf][1] = Ws[kB * 64 + (n ^ swc)];
            }
#pragma unroll
            for (int mf = 0; mf < 2; ++mf)
#pragma unroll
                for (int nf = 0; nf < 4; ++nf)
                    mma_tf32(acc[mf][nf], a[mf], b[nf]);
        }
    }

    // epilogue
#pragma unroll
    for (int mf = 0; mf < 2; ++mf) {
        int row = n0 + warp_m * 32 + mf * 16 + rr;
#pragma unroll
        for (int nf = 0; nf < 4; ++nf) {
            int col = c0 + warp_n * 32 + nf * 8 + (lane & 3) * 2;
            float b0v = 0.f, b1v = 0.f;
            if (bias) { b0v = bias[col]; b1v = bias[col + 1]; }
            if (row < n_rows) {
                float2 o = make_float2(acc[mf][nf][0] + b0v, acc[mf][nf][1] + b1v);
                *(float2*)(C + (size_t)row * P + col) = o;
            }
            if (row + 8 < n_rows) {
                float2 o = make_float2(acc[mf][nf][2] + b0v, acc[mf][nf][3] + b1v);
                *(float2*)(C + (size_t)(row + 8) * P + col) = o;
            }
        }
    }
}

// ---------------- fp32 register-tiled GEMM (final output only) ----------------
template <int K>
__global__ void __launch_bounds__(256) gemm_kernel(
    const float* __restrict__ A, const float* __restrict__ W,
    const float* __restrict__ bias, const float* __restrict__ extra,
    float* __restrict__ C, int n_rows, int P)
{
    __shared__ float As[64 * 128];
    __shared__ float Wsm[64 * 64];

    const int t  = threadIdx.x;
    const int n0 = blockIdx.x * 128;
    const int c0 = blockIdx.y * 64;
    const int tn = t & 15;
    const int tc = t >> 4;

    float acc[8][4];
#pragma unroll
    for (int i = 0; i < 8; ++i)
#pragma unroll
        for (int j = 0; j < 4; ++j) acc[i][j] = 0.f;

    for (int k0 = 0; k0 < K; k0 += 64) {
        __syncthreads();
#pragma unroll
        for (int r = 0; r < 32; ++r) {
            int idx = t + 256 * r;
            int nn = idx >> 6, kk = idx & 63;
            int row = n0 + nn;
            float v = (row < n_rows) ? A[row * K + k0 + kk] : 0.f;
            As[kk * 128 + (nn ^ (kk & 31))] = v;
        }
#pragma unroll
        for (int r = 0; r < 16; ++r) {
            int idx = t + 256 * r;
            int kk = idx >> 6, jj = idx & 63;
            Wsm[kk * 64 + jj] = W[(k0 + kk) * P + c0 + jj];
        }
        __syncthreads();

#pragma unroll 16
        for (int kk = 0; kk < 64; ++kk) {
            float a[8], w[4];
#pragma unroll
            for (int i = 0; i < 8; ++i)
                a[i] = As[kk * 128 + ((tn + 16 * i) ^ (kk & 31))];
#pragma unroll
            for (int j = 0; j < 4; ++j)
                w[j] = Wsm[kk * 64 + tc * 4 + j];
#pragma unroll
            for (int i = 0; i < 8; ++i)
#pragma unroll
                for (int j = 0; j < 4; ++j)
                    acc[i][j] = fmaf(a[i], w[j], acc[i][j]);
        }
    }

#pragma unroll
    for (int i = 0; i < 8; ++i) {
        int row = n0 + tn + 16 * i;
        if (row < n_rows) {
#pragma unroll
            for (int j = 0; j < 4; ++j) {
                int col = c0 + tc * 4 + j;
                float v = acc[i][j];
                if (bias)  v += bias[col];
                if (extra) v += extra[row * P + col];
                C[row * P + col] = v;
            }
        }
    }
}

// ---------------- small kernels ----------------
__global__ void init_kernel()
{
    int i = blockIdx.x * blockDim.x + threadIdx.x;
    int T = gridDim.x * blockDim.x;
    for (int k = i; k < NN; k += T) g_cnt[k] = 0;
    if (i < DD) { g_bnsum[i] = 0.f; g_bnsumsq[i] = 0.f; }
}

__global__ void bn_stats_kernel()
{
    int t = blockIdx.x * blockDim.x + threadIdx.x;
    int col = t & 63;
    int r0 = t >> 6;
    int rs = (gridDim.x * blockDim.x) >> 6;
    float s = 0.f, ss = 0.f;
    for (int r = r0; r < NN; r += rs) {
        float v = g_h0[r * DD + col];
        s += v; ss += v * v;
    }
    atomicAdd(&g_bnsum[col], s);
    atomicAdd(&g_bnsumsq[col], ss);
}

__global__ void bn_apply_kernel(const float* __restrict__ bn_g,
                                const float* __restrict__ bn_b)
{
    int i = blockIdx.x * blockDim.x + threadIdx.x;
    int T = gridDim.x * blockDim.x;
    const float invn = 1.f / (float)NN;
    for (int k = i; k < NN * DD; k += T) {
        int c = k & 63;
        float mu  = g_bnsum[c] * invn;
        float var = g_bnsumsq[c] * invn - mu * mu;
        float v = (g_h0[k] - mu) * rsqrtf(var + BN_EPS) * bn_g[c] + bn_b[c];
        g_h[k] = v > 0.f ? v : 0.f;
    }
}

__global__ void transpose_kernel(const float* __restrict__ wih,
                                 const float* __restrict__ whh)
{
    int i = blockIdx.x * blockDim.x + threadIdx.x;
    if (i < G3 * DD) {
        int j = i >> 6, k = i & 63;
        g_wihT[k * G3 + j] = wih[i];
        g_whhT[k * G3 + j] = whh[i];
    }
}

__global__ void hist_kernel(const int* __restrict__ eidx)
{
    int i = blockIdx.x * blockDim.x + threadIdx.x;
    int T = gridDim.x * blockDim.x;
    for (int e = i; e < EE; e += T)
        atomicAdd(&g_cnt[eidx[EE + e]], 1);
}

__global__ void scan_kernel()
{
    __shared__ int sh[1024];
    int t = threadIdx.x;
    const int chunk = (NN + 1023) / 1024;
    int beg = t * chunk;
    int end = beg + chunk; if (end > NN) end = NN;
    int s = 0;
    for (int i = beg; i < end && i < NN; ++i) s += g_cnt[i];
    sh[t] = s;
    __syncthreads();
    for (int off = 1; off < 1024; off <<= 1) {
        int v = (t >= off) ? sh[t - off] : 0;
        __syncthreads();
        sh[t] += v;
        __syncthreads();
    }
    int run = (t > 0) ? sh[t - 1] : 0;
    for (int i = beg; i < end && i < NN; ++i) {
        g_rowstart[i] = run;
        g_cursor[i]   = run;
        run += g_cnt[i];
    }
}

__global__ void scatter_kernel(const int* __restrict__ eidx,
                               const float* __restrict__ edge_attr,
                               const float* __restrict__ att_edge)
{
    float a0 = att_edge[0], a1 = att_edge[1], a2 = att_edge[2];
    int i = blockIdx.x * blockDim.x + threadIdx.x;
    int T = gridDim.x * blockDim.x;
    for (int e = i; e < EE; e += T) {
        int d = eidx[EE + e];
        int s = eidx[e];
        int pos = atomicAdd(&g_cursor[d], 1);
        g_csrc[pos] = s;
        g_ceb[pos] = edge_attr[e * 3 + 0] * a0 + edge_attr[e * 3 + 1] * a1 +
                     edge_attr[e * 3 + 2] * a2;
    }
}

__global__ void attn_node_kernel(const float* __restrict__ att_dst,
                                 const float* __restrict__ att_src)
{
    int n = blockIdx.x * 8 + (threadIdx.x >> 5);
    int lane = threadIdx.x & 31;
    if (n >= NN) return;
    float x0 = g_xt[n * DD + lane], x1 = g_xt[n * DD + 32 + lane];
    float vd = x0 * att_dst[lane] + x1 * att_dst[32 + lane];
    float vs = x0 * att_src[lane] + x1 * att_src[32 + lane];
#pragma unroll
    for (int o = 16; o; o >>= 1) {
        vd += __shfl_xor_sync(0xffffffffu, vd, o);
        vs += __shfl_xor_sync(0xffffffffu, vs, o);
    }
    if (lane == 0) { g_adst[n] = vd; g_asrc[n] = vs; }
}

__global__ void attn_alpha_kernel()
{
    int n = blockIdx.x * 8 + (threadIdx.x >> 5);
    int lane = threadIdx.x & 31;
    if (n >= NN) return;
    int deg = g_cnt[n], s0 = g_rowstart[n];
    float adst = g_adst[n];
    float vmax = -1e30f;
    for (int j = lane; j < deg; j += 32) {
        float l = adst + g_asrc[g_csrc[s0 + j]] + g_ceb[s0 + j];
        l = l >= 0.f ? l : SLOPE * l;
        g_expd[s0 + j] = l;                 // stash logit (no 2nd gather)
        vmax = fmaxf(vmax, l);
    }
#pragma unroll
    for (int o = 16; o; o >>= 1)
        vmax = fmaxf(vmax, __shfl_xor_sync(0xffffffffu, vmax, o));
    float sum = 0.f;
    for (int j = lane; j < deg; j += 32) {
        float e = __expf(g_expd[s0 + j] - vmax);
        g_expd[s0 + j] = e;
        sum += e;
    }
#pragma unroll
    for (int o = 16; o; o >>= 1)
        sum += __shfl_xor_sync(0xffffffffu, sum, o);
    if (lane == 0) g_dinv[n] = 1.f / sum;
}

__global__ void aggregate_kernel()
{
    int n = blockIdx.x * 8 + (threadIdx.x >> 5);
    int lane = threadIdx.x & 31;
    if (n >= NN) return;
    int deg = g_cnt[n], s0 = g_rowstart[n];
    const float2* xt2 = (const float2*)g_xt;
    float ax = 0.f, ay = 0.f;
    int j = 0;
    for (; j + 4 <= deg; j += 4) {
        float w0 = g_expd[s0 + j + 0], w1 = g_expd[s0 + j + 1];
        float w2 = g_expd[s0 + j + 2], w3 = g_expd[s0 + j + 3];
        int i0 = g_csrc[s0 + j + 0], i1 = g_csrc[s0 + j + 1];
        int i2 = g_csrc[s0 + j + 2], i3 = g_csrc[s0 + j + 3];
        float2 v0 = xt2[i0 * 32 + lane];
        float2 v1 = xt2[i1 * 32 + lane];
        float2 v2 = xt2[i2 * 32 + lane];
        float2 v3 = xt2[i3 * 32 + lane];
        ax += w0 * v0.x + w1 * v1.x + w2 * v2.x + w3 * v3.x;
        ay += w0 * v0.y + w1 * v1.y + w2 * v2.y + w3 * v3.y;
    }
    for (; j < deg; ++j) {
        float w = g_expd[s0 + j];
        int si = g_csrc[s0 + j];
        float2 v = xt2[si * 32 + lane];
        ax += w * v.x; ay += w * v.y;
    }
    float dinv = (deg > 0) ? g_dinv[n] : 0.f;
    float2 o;
    o.x = fmaxf(ax * dinv, 0.f);
    o.y = fmaxf(ay * dinv, 0.f);
    ((float2*)g_m)[n * 32 + lane] = o;
}

__global__ void gates_kernel()
{
    int i = blockIdx.x * blockDim.x + threadIdx.x;
    int T = gridDim.x * blockDim.x;
    for (int k = i; k < NN * DD; k += T) {
        int nrow = k >> 6, d = k & 63;
        const float* gi = g_gi + nrow * G3;
        const float* gh = g_gh + nrow * G3;
        float r = 1.f / (1.f + __expf(-(gi[d]       + gh[d])));
        float z = 1.f / (1.f + __expf(-(gi[d + 64]  + gh[d + 64])));
        float t = tanhf(gi[d + 128] + r * gh[d + 128]);
        float h = g_h[k];
        g_h[k] = (1.f - z) * t + z * h;
    }
}

// ---------------- launch ----------------
extern "C" void kernel_launch(void* const* d_in, const int* in_sizes, int n_in,
                              void* d_out, int out_size)
{
    const float* x        = (const float*)d_in[0];
    const float* edge_at  = (const float*)d_in[1];
    const float* mlp_w    = (const float*)d_in[2];
    const float* mlp_b    = (const float*)d_in[3];
    const float* bn_g     = (const float*)d_in[4];
    const float* bn_b     = (const float*)d_in[5];
    const float* conv_w   = (const float*)d_in[6];
    const float* att_dst  = (const float*)d_in[7];
    const float* att_src  = (const float*)d_in[8];
    const float* att_edge = (const float*)d_in[9];
    const float* w_ih     = (const float*)d_in[10];
    const float* w_hh     = (const float*)d_in[11];
    const float* b_ih     = (const float*)d_in[12];
    const float* b_hh     = (const float*)d_in[13];
    const float* lin_w    = (const float*)d_in[14];
    const float* lin_b    = (const float*)d_in[15];
    const int*   eidx     = (const int*)d_in[16];   // int32 (JAX x64 disabled)
    float* out = (float*)d_out;

    float *p_h0, *p_h, *p_xt, *p_m, *p_gi, *p_gh, *p_wihT, *p_whhT;
    cudaGetSymbolAddress((void**)&p_h0,   g_h0);
    cudaGetSymbolAddress((void**)&p_h,    g_h);
    cudaGetSymbolAddress((void**)&p_xt,   g_xt);
    cudaGetSymbolAddress((void**)&p_m,    g_m);
    cudaGetSymbolAddress((void**)&p_gi,   g_gi);
    cudaGetSymbolAddress((void**)&p_gh,   g_gh);
    cudaGetSymbolAddress((void**)&p_wihT, g_wihT);
    cudaGetSymbolAddress((void**)&p_whhT, g_whhT);

    const int GB  = (NN + 127) / 128;      // 391 row blocks
    const int WPB = (NN + 7) / 8;          // 6250 warp-per-node blocks

    init_kernel<<<64, 256>>>();
    gemm_tf32_kernel<IND><<<dim3(GB, 1), 256>>>(x, mlp_w, mlp_b, p_h0, NN, DD);
    bn_stats_kernel<<<256, 256>>>();
    bn_apply_kernel<<<512, 256>>>(bn_g, bn_b);
    transpose_kernel<<<(G3 * DD + 255) / 256, 256>>>(w_ih, w_hh);
    hist_kernel<<<2048, 256>>>(eidx);
    scan_kernel<<<1, 1024>>>();
    scatter_kernel<<<2048, 256>>>(eidx, edge_at, att_edge);

    for (int step = 0; step < 3; ++step) {
        gemm_tf32_kernel<DD><<<dim3(GB, 1), 256>>>(p_h, conv_w, nullptr, p_xt, NN, DD);
        attn_node_kernel<<<WPB, 256>>>(att_dst, att_src);
        attn_alpha_kernel<<<WPB, 256>>>();
        aggregate_kernel<<<WPB, 256>>>();
        gemm_tf32_kernel<DD><<<dim3(GB, 3), 256>>>(p_m, p_wihT, b_ih, p_gi, NN, G3);
        gemm_tf32_kernel<DD><<<dim3(GB, 3), 256>>>(p_h, p_whhT, b_hh, p_gh, NN, G3);
        gates_kernel<<<512, 256>>>();
    }

    // final output GEMM stays fp32 for precision margin (forms output directly)
    gemm_kernel<IND><<<dim3(GB, 1), 256>>>(x, lin_w, lin_b, p_h, out, NN, DD);
}

// round 4
// speedup vs baseline: 1.8869x; 1.1117x over previous
#include <cuda_runtime.h>
#include <cuda_fp16.h>
#include <math.h>
#include <stdint.h>

#define NN 50000
#define EE 1600000
#define IND 128
#define DD 64
#define G3 192
#define BN_EPS 1e-5f
#define SLOPE 0.2f

// ---------------- scratch (static __device__: no allocation) ----------------
__device__ float  g_h0[NN * DD];
__device__ float  g_h[NN * DD];
__device__ __half g_xth[NN * DD];
__device__ float  g_m[NN * DD];
__device__ float  g_gi[NN * G3];
__device__ float  g_gh[NN * G3];
__device__ float  g_adst[NN];
__device__ float  g_asrc[NN];
__device__ int    g_cnt[NN];
__device__ int    g_rowstart[NN];
__device__ int    g_cursor[NN];
__device__ int    g_csrc[EE];
__device__ float  g_ceb[EE];
__device__ float  g_expd[EE];
__device__ float  g_wihT[DD * G3];
__device__ float  g_whhT[DD * G3];
__device__ float  g_bnsum[DD];
__device__ float  g_bnsumsq[DD];

// ---------------- tf32 helpers ----------------
__device__ __forceinline__ unsigned f2tf(float x) {
    unsigned r;
    asm("cvt.rna.tf32.f32 %0, %1;" : "=r"(r) : "f"(x));
    return r;
}

__device__ __forceinline__ void mma_tf32(float c[4], const unsigned a[4],
                                         const unsigned b[2]) {
    asm volatile(
        "mma.sync.aligned.m16n8k8.row.col.f32.tf32.tf32.f32 "
        "{%0,%1,%2,%3}, {%4,%5,%6,%7}, {%8,%9}, {%0,%1,%2,%3};"
        : "+f"(c[0]), "+f"(c[1]), "+f"(c[2]), "+f"(c[3])
        : "r"(a[0]), "r"(a[1]), "r"(a[2]), "r"(a[3]),
          "r"(b[0]), "r"(b[1]));
}

// ---------------- tf32 GEMM, K=128 (embed & final) ----------------
// C = A[n,128] @ W[128,P] (+bias) (+extra)
__global__ void __launch_bounds__(256) gemm128_tf32_kernel(
    const float* __restrict__ A, const float* __restrict__ W,
    const float* __restrict__ bias, const float* __restrict__ extra,
    float* __restrict__ C, int n_rows, int P)
{
    __shared__ uint4 As4[16 * 128];
    __shared__ unsigned Ws[64 * 64];

    const int t    = threadIdx.x;
    const int lane = t & 31;
    const int wid  = t >> 5;
    const int warp_m = wid & 3;
    const int warp_n = wid >> 2;
    const int n0 = blockIdx.x * 128;
    const int c0 = blockIdx.y * 64;

    float acc[2][4][4];
#pragma unroll
    for (int mf = 0; mf < 2; ++mf)
#pragma unroll
        for (int nf = 0; nf < 4; ++nf)
#pragma unroll
            for (int r = 0; r < 4; ++r) acc[mf][nf][r] = 0.f;

    const unsigned* Asw = reinterpret_cast<const unsigned*>(As4);
    const int rr = lane >> 2, kl = lane & 3;

    for (int k0 = 0; k0 < 128; k0 += 64) {
        __syncthreads();
#pragma unroll
        for (int i = 0; i < 8; ++i) {
            int idx = t + 256 * i;
            int m  = idx >> 4;
            int kh = idx & 15;
            int row = n0 + m;
            float4 v = make_float4(0.f, 0.f, 0.f, 0.f);
            if (row < n_rows)
                v = *(const float4*)(A + (size_t)row * 128 + k0 + kh * 4);
            As4[kh * 128 + (m ^ (kh & 7))] =
                make_uint4(f2tf(v.x), f2tf(v.y), f2tf(v.z), f2tf(v.w));
        }
#pragma unroll
        for (int i = 0; i < 4; ++i) {
            int idx = t + 256 * i;
            int kk = idx >> 4;
            int n4 = (idx & 15) << 2;
            float4 v = *(const float4*)(W + (size_t)(k0 + kk) * P + c0 + n4);
            int nsw = n4 ^ ((kk & 3) << 3);
            Ws[kk * 64 + nsw + 0] = f2tf(v.x);
            Ws[kk * 64 + nsw + 1] = f2tf(v.y);
            Ws[kk * 64 + nsw + 2] = f2tf(v.z);
            Ws[kk * 64 + nsw + 3] = f2tf(v.w);
        }
        __syncthreads();

#pragma unroll
        for (int ks = 0; ks < 8; ++ks) {
            const int kh0 = ks * 2;
            unsigned a[2][4];
#pragma unroll
            for (int mf = 0; mf < 2; ++mf) {
                int mb = warp_m * 32 + mf * 16 + rr;
                a[mf][0] = Asw[(kh0 * 128 + (mb ^ (kh0 & 7))) * 4 + kl];
                a[mf][1] = Asw[(kh0 * 128 + ((mb + 8) ^ (kh0 & 7))) * 4 + kl];
                a[mf][2] = Asw[((kh0 + 1) * 128 + (mb ^ ((kh0 + 1) & 7))) * 4 + kl];
                a[mf][3] = Asw[((kh0 + 1) * 128 + ((mb + 8) ^ ((kh0 + 1) & 7))) * 4 + kl];
            }
            unsigned b[4][2];
            const int kA = ks * 8 + kl;
            const int kB = kA + 4;
            const int swc = (kl << 3);
#pragma unroll
            for (int nf = 0; nf < 4; ++nf) {
                int n = warp_n * 32 + nf * 8 + rr;
                b[nf][0] = Ws[kA * 64 + (n ^ swc)];
                b[nf][1] = Ws[kB * 64 + (n ^ swc)];
            }
#pragma unroll
            for (int mf = 0; mf < 2; ++mf)
#pragma unroll
                for (int nf = 0; nf < 4; ++nf)
                    mma_tf32(acc[mf][nf], a[mf], b[nf]);
        }
    }

#pragma unroll
    for (int mf = 0; mf < 2; ++mf) {
        int row = n0 + warp_m * 32 + mf * 16 + rr;
#pragma unroll
        for (int nf = 0; nf < 4; ++nf) {
            int col = c0 + warp_n * 32 + nf * 8 + (lane & 3) * 2;
            float b0v = 0.f, b1v = 0.f;
            if (bias) { b0v = bias[col]; b1v = bias[col + 1]; }
            if (row < n_rows) {
                float e0 = extra ? extra[(size_t)row * P + col] : 0.f;
                float e1 = extra ? extra[(size_t)row * P + col + 1] : 0.f;
                float2 o = make_float2(acc[mf][nf][0] + b0v + e0,
                                       acc[mf][nf][1] + b1v + e1);
                *(float2*)(C + (size_t)row * P + col) = o;
            }
            if (row + 8 < n_rows) {
                float e0 = extra ? extra[(size_t)(row + 8) * P + col] : 0.f;
                float e1 = extra ? extra[(size_t)(row + 8) * P + col + 1] : 0.f;
                float2 o = make_float2(acc[mf][nf][2] + b0v + e0,
                                       acc[mf][nf][3] + b1v + e1);
                *(float2*)(C + (size_t)(row + 8) * P + col) = o;
            }
        }
    }
}

// ---------------- tf32 GEMM, K=64, NP column panels, optional half output --
// Stages A once, loops NP 64-wide column panels of W.
template <int NP, bool OUT_HALF>
__global__ void __launch_bounds__(256) gemm64_tf32_kernel(
    const float* __restrict__ A, const float* __restrict__ W,
    const float* __restrict__ bias, float* __restrict__ C,
    __half* __restrict__ Ch, int n_rows, int P)
{
    __shared__ uint4 As4[16 * 128];
    __shared__ unsigned Ws[64 * 64];

    const int t    = threadIdx.x;
    const int lane = t & 31;
    const int wid  = t >> 5;
    const int warp_m = wid & 3;
    const int warp_n = wid >> 2;
    const int n0 = blockIdx.x * 128;

    const unsigned* Asw = reinterpret_cast<const unsigned*>(As4);
    const int rr = lane >> 2, kl = lane & 3;

    // stage A once (K=64)
#pragma unroll
    for (int i = 0; i < 8; ++i) {
        int idx = t + 256 * i;
        int m  = idx >> 4;
        int kh = idx & 15;
        int row = n0 + m;
        float4 v = make_float4(0.f, 0.f, 0.f, 0.f);
        if (row < n_rows)
            v = *(const float4*)(A + (size_t)row * 64 + kh * 4);
        As4[kh * 128 + (m ^ (kh & 7))] =
            make_uint4(f2tf(v.x), f2tf(v.y), f2tf(v.z), f2tf(v.w));
    }

#pragma unroll
    for (int p = 0; p < NP; ++p) {
        const int c0 = p * 64;
        if (p > 0) __syncthreads();
#pragma unroll
        for (int i = 0; i < 4; ++i) {
            int idx = t + 256 * i;
            int kk = idx >> 4;
            int n4 = (idx & 15) << 2;
            float4 v = *(const float4*)(W + (size_t)kk * P + c0 + n4);
            int nsw = n4 ^ ((kk & 3) << 3);
            Ws[kk * 64 + nsw + 0] = f2tf(v.x);
            Ws[kk * 64 + nsw + 1] = f2tf(v.y);
            Ws[kk * 64 + nsw + 2] = f2tf(v.z);
            Ws[kk * 64 + nsw + 3] = f2tf(v.w);
        }
        __syncthreads();

        float acc[2][4][4];
#pragma unroll
        for (int mf = 0; mf < 2; ++mf)
#pragma unroll
            for (int nf = 0; nf < 4; ++nf)
#pragma unroll
                for (int r = 0; r < 4; ++r) acc[mf][nf][r] = 0.f;

#pragma unroll
        for (int ks = 0; ks < 8; ++ks) {
            const int kh0 = ks * 2;
            unsigned a[2][4];
#pragma unroll
            for (int mf = 0; mf < 2; ++mf) {
                int mb = warp_m * 32 + mf * 16 + rr;
                a[mf][0] = Asw[(kh0 * 128 + (mb ^ (kh0 & 7))) * 4 + kl];
                a[mf][1] = Asw[(kh0 * 128 + ((mb + 8) ^ (kh0 & 7))) * 4 + kl];
                a[mf][2] = Asw[((kh0 + 1) * 128 + (mb ^ ((kh0 + 1) & 7))) * 4 + kl];
                a[mf][3] = Asw[((kh0 + 1) * 128 + ((mb + 8) ^ ((kh0 + 1) & 7))) * 4 + kl];
            }
            unsigned b[4][2];
            const int kA = ks * 8 + kl;
            const int kB = kA + 4;
            const int swc = (kl << 3);
#pragma unroll
            for (int nf = 0; nf < 4; ++nf) {
                int n = warp_n * 32 + nf * 8 + rr;
                b[nf][0] = Ws[kA * 64 + (n ^ swc)];
                b[nf][1] = Ws[kB * 64 + (n ^ swc)];
            }
#pragma unroll
            for (int mf = 0; mf < 2; ++mf)
#pragma unroll
                for (int nf = 0; nf < 4; ++nf)
                    mma_tf32(acc[mf][nf], a[mf], b[nf]);
        }

#pragma unroll
        for (int mf = 0; mf < 2; ++mf) {
            int row = n0 + warp_m * 32 + mf * 16 + rr;
#pragma unroll
            for (int nf = 0; nf < 4; ++nf) {
                int col = c0 + warp_n * 32 + nf * 8 + (lane & 3) * 2;
                float b0v = 0.f, b1v = 0.f;
                if (bias) { b0v = bias[col]; b1v = bias[col + 1]; }
                if (OUT_HALF) {
                    if (row < n_rows)
                        *(__half2*)(Ch + (size_t)row * P + col) =
                            __floats2half2_rn(acc[mf][nf][0] + b0v,
                                              acc[mf][nf][1] + b1v);
                    if (row + 8 < n_rows)
                        *(__half2*)(Ch + (size_t)(row + 8) * P + col) =
                            __floats2half2_rn(acc[mf][nf][2] + b0v,
                                              acc[mf][nf][3] + b1v);
                } else {
                    if (row < n_rows)
                        *(float2*)(C + (size_t)row * P + col) =
                            make_float2(acc[mf][nf][0] + b0v,
                                        acc[mf][nf][1] + b1v);
                    if (row + 8 < n_rows)
                        *(float2*)(C + (size_t)(row + 8) * P + col) =
                            make_float2(acc[mf][nf][2] + b0v,
                                        acc[mf][nf][3] + b1v);
                }
            }
        }
    }
}

// ---------------- small kernels ----------------
__global__ void init_kernel()
{
    int i = blockIdx.x * blockDim.x + threadIdx.x;
    int T = gridDim.x * blockDim.x;
    for (int k = i; k < NN; k += T) g_cnt[k] = 0;
    if (i < DD) { g_bnsum[i] = 0.f; g_bnsumsq[i] = 0.f; }
}

__global__ void bn_stats_kernel()
{
    int t = blockIdx.x * blockDim.x + threadIdx.x;
    int col = t & 63;
    int r0 = t >> 6;
    int rs = (gridDim.x * blockDim.x) >> 6;
    float s = 0.f, ss = 0.f;
    for (int r = r0; r < NN; r += rs) {
        float v = g_h0[r * DD + col];
        s += v; ss += v * v;
    }
    atomicAdd(&g_bnsum[col], s);
    atomicAdd(&g_bnsumsq[col], ss);
}

__global__ void bn_apply_kernel(const float* __restrict__ bn_g,
                                const float* __restrict__ bn_b)
{
    int i = blockIdx.x * blockDim.x + threadIdx.x;
    int T = gridDim.x * blockDim.x;
    const float invn = 1.f / (float)NN;
    for (int k = i; k < NN * DD; k += T) {
        int c = k & 63;
        float mu  = g_bnsum[c] * invn;
        float var = g_bnsumsq[c] * invn - mu * mu;
        float v = (g_h0[k] - mu) * rsqrtf(var + BN_EPS) * bn_g[c] + bn_b[c];
        g_h[k] = v > 0.f ? v : 0.f;
    }
}

__global__ void transpose_kernel(const float* __restrict__ wih,
                                 const float* __restrict__ whh)
{
    int i = blockIdx.x * blockDim.x + threadIdx.x;
    if (i < G3 * DD) {
        int j = i >> 6, k = i & 63;
        g_wihT[k * G3 + j] = wih[i];
        g_whhT[k * G3 + j] = whh[i];
    }
}

__global__ void hist_kernel(const int* __restrict__ eidx)
{
    int i = blockIdx.x * blockDim.x + threadIdx.x;
    int T = gridDim.x * blockDim.x;
    for (int e = i; e < EE; e += T)
        atomicAdd(&g_cnt[eidx[EE + e]], 1);
}

__global__ void scan_kernel()
{
    __shared__ int sh[1024];
    int t = threadIdx.x;
    const int chunk = (NN + 1023) / 1024;
    int beg = t * chunk;
    int end = beg + chunk; if (end > NN) end = NN;
    int s = 0;
#pragma unroll 4
    for (int i = beg; i < end; ++i) s += g_cnt[i];
    sh[t] = s;
    __syncthreads();
    for (int off = 1; off < 1024; off <<= 1) {
        int v = (t >= off) ? sh[t - off] : 0;
        __syncthreads();
        sh[t] += v;
        __syncthreads();
    }
    int run = (t > 0) ? sh[t - 1] : 0;
    for (int i = beg; i < end; ++i) {
        g_rowstart[i] = run;
        g_cursor[i]   = run;
        run += g_cnt[i];
    }
}

__global__ void scatter_kernel(const int* __restrict__ eidx,
                               const float* __restrict__ edge_attr,
                               const float* __restrict__ att_edge)
{
    float a0 = att_edge[0], a1 = att_edge[1], a2 = att_edge[2];
    int i = blockIdx.x * blockDim.x + threadIdx.x;
    int T = gridDim.x * blockDim.x;
    for (int e = i; e < EE; e += T) {
        int d = eidx[EE + e];
        int s = eidx[e];
        int pos = atomicAdd(&g_cursor[d], 1);
        g_csrc[pos] = s;
        g_ceb[pos] = edge_attr[e * 3 + 0] * a0 + edge_attr[e * 3 + 1] * a1 +
                     edge_attr[e * 3 + 2] * a2;
    }
}

__global__ void attn_node_kernel(const float* __restrict__ att_dst,
                                 const float* __restrict__ att_src)
{
    int n = blockIdx.x * 8 + (threadIdx.x >> 5);
    int lane = threadIdx.x & 31;
    if (n >= NN) return;
    const __half2* x2 = (const __half2*)g_xth;
    float2 v  = __half22float2(x2[n * 32 + lane]);
    float2 ad = ((const float2*)att_dst)[lane];
    float2 as = ((const float2*)att_src)[lane];
    float vd = v.x * ad.x + v.y * ad.y;
    float vs = v.x * as.x + v.y * as.y;
#pragma unroll
    for (int o = 16; o; o >>= 1) {
        vd += __shfl_xor_sync(0xffffffffu, vd, o);
        vs += __shfl_xor_sync(0xffffffffu, vs, o);
    }
    if (lane == 0) { g_adst[n] = vd; g_asrc[n] = vs; }
}

// fused softmax + weighted aggregation, warp per node
__global__ void __launch_bounds__(256) attn_agg_kernel()
{
    __shared__ float sw[8 * 64];
    __shared__ int   ssi[8 * 64];

    int wslot = threadIdx.x >> 5;
    int n = blockIdx.x * 8 + wslot;
    int lane = threadIdx.x & 31;
    if (n >= NN) return;
    int deg = g_cnt[n], s0 = g_rowstart[n];
    float adst = g_adst[n];

    // pass 1: logits -> stash, warp max
    float vmax = -1e30f;
    for (int j = lane; j < deg; j += 32) {
        float l = adst + g_asrc[g_csrc[s0 + j]] + g_ceb[s0 + j];
        l = l >= 0.f ? l : SLOPE * l;
        g_expd[s0 + j] = l;
        vmax = fmaxf(vmax, l);
    }
#pragma unroll
    for (int o = 16; o; o >>= 1)
        vmax = fmaxf(vmax, __shfl_xor_sync(0xffffffffu, vmax, o));

    // pass 2: chunked exp + gather-aggregate
    const __half2* xh2 = (const __half2*)g_xth;
    float* swp = sw + wslot * 64;
    int*   sip = ssi + wslot * 64;
    float sum = 0.f, ax = 0.f, ay = 0.f;

    for (int c0 = 0; c0 < deg; c0 += 64) {
        int cnt = deg - c0; if (cnt > 64) cnt = 64;
        __syncwarp();
#pragma unroll
        for (int u = 0; u < 2; ++u) {
            int j = c0 + lane + 32 * u;
            if (j < deg) {
                float e = __expf(g_expd[s0 + j] - vmax);
                sum += e;
                swp[lane + 32 * u] = e;
                sip[lane + 32 * u] = g_csrc[s0 + j];
            }
        }
        __syncwarp();
        int j = 0;
        for (; j + 4 <= cnt; j += 4) {
            float w0 = swp[j + 0], w1 = swp[j + 1];
            float w2 = swp[j + 2], w3 = swp[j + 3];
            int i0 = sip[j + 0], i1 = sip[j + 1];
            int i2 = sip[j + 2], i3 = sip[j + 3];
            float2 v0 = __half22float2(xh2[i0 * 32 + lane]);
            float2 v1 = __half22float2(xh2[i1 * 32 + lane]);
            float2 v2 = __half22float2(xh2[i2 * 32 + lane]);
            float2 v3 = __half22float2(xh2[i3 * 32 + lane]);
            ax += w0 * v0.x + w1 * v1.x + w2 * v2.x + w3 * v3.x;
            ay += w0 * v0.y + w1 * v1.y + w2 * v2.y + w3 * v3.y;
        }
        for (; j < cnt; ++j) {
            float w = swp[j];
            float2 v = __half22float2(xh2[sip[j] * 32 + lane]);
            ax += w * v.x; ay += w * v.y;
        }
    }

#pragma unroll
    for (int o = 16; o; o >>= 1)
        sum += __shfl_xor_sync(0xffffffffu, sum, o);
    float dinv = (deg > 0) ? 1.f / sum : 0.f;
    float2 o;
    o.x = fmaxf(ax * dinv, 0.f);
    o.y = fmaxf(ay * dinv, 0.f);
    ((float2*)g_m)[n * 32 + lane] = o;
}

__global__ void gates_kernel()
{
    int i = blockIdx.x * blockDim.x + threadIdx.x;
    int T = gridDim.x * blockDim.x;
    for (int k = i; k < NN * DD; k += T) {
        int nrow = k >> 6, d = k & 63;
        const float* gi = g_gi + nrow * G3;
        const float* gh = g_gh + nrow * G3;
        float r = 1.f / (1.f + __expf(-(gi[d]       + gh[d])));
        float z = 1.f / (1.f + __expf(-(gi[d + 64]  + gh[d + 64])));
        float t = tanhf(gi[d + 128] + r * gh[d + 128]);
        float h = g_h[k];
        g_h[k] = (1.f - z) * t + z * h;
    }
}

// ---------------- launch ----------------
extern "C" void kernel_launch(void* const* d_in, const int* in_sizes, int n_in,
                              void* d_out, int out_size)
{
    const float* x        = (const float*)d_in[0];
    const float* edge_at  = (const float*)d_in[1];
    const float* mlp_w    = (const float*)d_in[2];
    const float* mlp_b    = (const float*)d_in[3];
    const float* bn_g     = (const float*)d_in[4];
    const float* bn_b     = (const float*)d_in[5];
    const float* conv_w   = (const float*)d_in[6];
    const float* att_dst  = (const float*)d_in[7];
    const float* att_src  = (const float*)d_in[8];
    const float* att_edge = (const float*)d_in[9];
    const float* w_ih     = (const float*)d_in[10];
    const float* w_hh     = (const float*)d_in[11];
    const float* b_ih     = (const float*)d_in[12];
    const float* b_hh     = (const float*)d_in[13];
    const float* lin_w    = (const float*)d_in[14];
    const float* lin_b    = (const float*)d_in[15];
    const int*   eidx     = (const int*)d_in[16];   // int32 (JAX x64 disabled)
    float* out = (float*)d_out;

    float *p_h0, *p_h, *p_m, *p_gi, *p_gh, *p_wihT, *p_whhT;
    __half *p_xth;
    cudaGetSymbolAddress((void**)&p_h0,   g_h0);
    cudaGetSymbolAddress((void**)&p_h,    g_h);
    cudaGetSymbolAddress((void**)&p_xth,  g_xth);
    cudaGetSymbolAddress((void**)&p_m,    g_m);
    cudaGetSymbolAddress((void**)&p_gi,   g_gi);
    cudaGetSymbolAddress((void**)&p_gh,   g_gh);
    cudaGetSymbolAddress((void**)&p_wihT, g_wihT);
    cudaGetSymbolAddress((void**)&p_whhT, g_whhT);

    const int GB  = (NN + 127) / 128;      // 391 row blocks
    const int WPB = (NN + 7) / 8;          // 6250 warp-per-node blocks

    init_kernel<<<64, 256>>>();
    gemm128_tf32_kernel<<<dim3(GB, 1), 256>>>(x, mlp_w, mlp_b, nullptr, p_h0, NN, DD);
    bn_stats_kernel<<<256, 256>>>();
    bn_apply_kernel<<<512, 256>>>(bn_g, bn_b);
    transpose_kernel<<<(G3 * DD + 255) / 256, 256>>>(w_ih, w_hh);
    hist_kernel<<<2048, 256>>>(eidx);
    scan_kernel<<<1, 1024>>>();
    scatter_kernel<<<2048, 256>>>(eidx, edge_at, att_edge);

    for (int step = 0; step < 3; ++step) {
        gemm64_tf32_kernel<1, true><<<GB, 256>>>(p_h, conv_w, nullptr, nullptr,
                                                 p_xth, NN, DD);
        attn_node_kernel<<<WPB, 256>>>(att_dst, att_src);
        attn_agg_kernel<<<WPB, 256>>>();
        gemm64_tf32_kernel<3, false><<<GB, 256>>>(p_m, p_wihT, b_ih, p_gi,
                                                  nullptr, NN, G3);
        gemm64_tf32_kernel<3, false><<<GB, 256>>>(p_h, p_whhT, b_hh, p_gh,
                                                  nullptr, NN, G3);
        gates_kernel<<<512, 256>>>();
    }

    // final: x @ lin_w + lin_b + h  (tf32, fused epilogue add)
    gemm128_tf32_kernel<<<dim3(GB, 1), 256>>>(x, lin_w, lin_b, p_h, out, NN, DD);
}

// round 5
// speedup vs baseline: 2.2732x; 1.2047x over previous
#include <cuda_runtime.h>
#include <cuda_fp16.h>
#include <math.h>
#include <stdint.h>

#define NN 50000
#define EE 1600000
#define IND 128
#define DD 64
#define G3 192
#define BN_EPS 1e-5f
#define SLOPE 0.2f

// ---------------- scratch (static __device__: no allocation) ----------------
__device__ float  g_h0[NN * DD];
__device__ float  g_h[NN * DD];
__device__ __half g_xth[NN * DD];
__device__ float  g_m[NN * DD];
__device__ float  g_adst[NN];
__device__ float  g_asrc[NN];
__device__ int    g_cnt[NN];
__device__ int    g_rowstart[NN];
__device__ int    g_cursor[NN];
__device__ int    g_csrc[EE];
__device__ float  g_ceb[EE];
__device__ float  g_expd[EE];
__device__ float  g_wihT[DD * G3];
__device__ float  g_whhT[DD * G3];
__device__ float  g_bnsum[DD];
__device__ float  g_bnsumsq[DD];

// ---------------- tf32 helpers ----------------
__device__ __forceinline__ unsigned f2tf(float x) {
    unsigned r;
    asm("cvt.rna.tf32.f32 %0, %1;" : "=r"(r) : "f"(x));
    return r;
}

__device__ __forceinline__ void mma_tf32(float c[4], const unsigned a[4],
                                         const unsigned b[2]) {
    asm volatile(
        "mma.sync.aligned.m16n8k8.row.col.f32.tf32.tf32.f32 "
        "{%0,%1,%2,%3}, {%4,%5,%6,%7}, {%8,%9}, {%0,%1,%2,%3};"
        : "+f"(c[0]), "+f"(c[1]), "+f"(c[2]), "+f"(c[3])
        : "r"(a[0]), "r"(a[1]), "r"(a[2]), "r"(a[3]),
          "r"(b[0]), "r"(b[1]));
}

__device__ __forceinline__ float sigf(float x) {
    return 1.f / (1.f + __expf(-x));
}

// ---------------- tf32 GEMM, K=128 (embed & final) ----------------
__global__ void __launch_bounds__(256) gemm128_tf32_kernel(
    const float* __restrict__ A, const float* __restrict__ W,
    const float* __restrict__ bias, const float* __restrict__ extra,
    float* __restrict__ C, int n_rows, int P)
{
    __shared__ uint4 As4[16 * 128];
    __shared__ unsigned Ws[64 * 64];

    const int t    = threadIdx.x;
    const int lane = t & 31;
    const int wid  = t >> 5;
    const int warp_m = wid & 3;
    const int warp_n = wid >> 2;
    const int n0 = blockIdx.x * 128;
    const int c0 = blockIdx.y * 64;

    float acc[2][4][4];
#pragma unroll
    for (int mf = 0; mf < 2; ++mf)
#pragma unroll
        for (int nf = 0; nf < 4; ++nf)
#pragma unroll
            for (int r = 0; r < 4; ++r) acc[mf][nf][r] = 0.f;

    const unsigned* Asw = reinterpret_cast<const unsigned*>(As4);
    const int rr = lane >> 2, kl = lane & 3;

    for (int k0 = 0; k0 < 128; k0 += 64) {
        __syncthreads();
#pragma unroll
        for (int i = 0; i < 8; ++i) {
            int idx = t + 256 * i;
            int m  = idx >> 4;
            int kh = idx & 15;
            int row = n0 + m;
            float4 v = make_float4(0.f, 0.f, 0.f, 0.f);
            if (row < n_rows)
                v = *(const float4*)(A + (size_t)row * 128 + k0 + kh * 4);
            As4[kh * 128 + (m ^ (kh & 7))] =
                make_uint4(f2tf(v.x), f2tf(v.y), f2tf(v.z), f2tf(v.w));
        }
#pragma unroll
        for (int i = 0; i < 4; ++i) {
            int idx = t + 256 * i;
            int kk = idx >> 4;
            int n4 = (idx & 15) << 2;
            float4 v = *(const float4*)(W + (size_t)(k0 + kk) * P + c0 + n4);
            int nsw = n4 ^ ((kk & 3) << 3);
            Ws[kk * 64 + nsw + 0] = f2tf(v.x);
            Ws[kk * 64 + nsw + 1] = f2tf(v.y);
            Ws[kk * 64 + nsw + 2] = f2tf(v.z);
            Ws[kk * 64 + nsw + 3] = f2tf(v.w);
        }
        __syncthreads();

#pragma unroll
        for (int ks = 0; ks < 8; ++ks) {
            const int kh0 = ks * 2;
            unsigned a[2][4];
#pragma unroll
            for (int mf = 0; mf < 2; ++mf) {
                int mb = warp_m * 32 + mf * 16 + rr;
                a[mf][0] = Asw[(kh0 * 128 + (mb ^ (kh0 & 7))) * 4 + kl];
                a[mf][1] = Asw[(kh0 * 128 + ((mb + 8) ^ (kh0 & 7))) * 4 + kl];
                a[mf][2] = Asw[((kh0 + 1) * 128 + (mb ^ ((kh0 + 1) & 7))) * 4 + kl];
                a[mf][3] = Asw[((kh0 + 1) * 128 + ((mb + 8) ^ ((kh0 + 1) & 7))) * 4 + kl];
            }
            unsigned b[4][2];
            const int kA = ks * 8 + kl;
            const int kB = kA + 4;
            const int swc = (kl << 3);
#pragma unroll
            for (int nf = 0; nf < 4; ++nf) {
                int n = warp_n * 32 + nf * 8 + rr;
                b[nf][0] = Ws[kA * 64 + (n ^ swc)];
                b[nf][1] = Ws[kB * 64 + (n ^ swc)];
            }
#pragma unroll
            for (int mf = 0; mf < 2; ++mf)
#pragma unroll
                for (int nf = 0; nf < 4; ++nf)
                    mma_tf32(acc[mf][nf], a[mf], b[nf]);
        }
    }

#pragma unroll
    for (int mf = 0; mf < 2; ++mf) {
        int row = n0 + warp_m * 32 + mf * 16 + rr;
#pragma unroll
        for (int nf = 0; nf < 4; ++nf) {
            int col = c0 + warp_n * 32 + nf * 8 + (lane & 3) * 2;
            float b0v = 0.f, b1v = 0.f;
            if (bias) { b0v = bias[col]; b1v = bias[col + 1]; }
            if (row < n_rows) {
                float e0 = extra ? extra[(size_t)row * P + col] : 0.f;
                float e1 = extra ? extra[(size_t)row * P + col + 1] : 0.f;
                *(float2*)(C + (size_t)row * P + col) =
                    make_float2(acc[mf][nf][0] + b0v + e0,
                                acc[mf][nf][1] + b1v + e1);
            }
            if (row + 8 < n_rows) {
                float e0 = extra ? extra[(size_t)(row + 8) * P + col] : 0.f;
                float e1 = extra ? extra[(size_t)(row + 8) * P + col + 1] : 0.f;
                *(float2*)(C + (size_t)(row + 8) * P + col) =
                    make_float2(acc[mf][nf][2] + b0v + e0,
                                acc[mf][nf][3] + b1v + e1);
            }
        }
    }
}

// ---------------- tf32 GEMM, K=64, half output (conv) ----------------
__global__ void __launch_bounds__(256) gemm64h_tf32_kernel(
    const float* __restrict__ A, const float* __restrict__ W,
    __half* __restrict__ Ch, int n_rows)
{
    __shared__ uint4 As4[16 * 128];
    __shared__ unsigned Ws[64 * 64];

    const int t    = threadIdx.x;
    const int lane = t & 31;
    const int wid  = t >> 5;
    const int warp_m = wid & 3;
    const int warp_n = wid >> 2;
    const int n0 = blockIdx.x * 128;

    const unsigned* Asw = reinterpret_cast<const unsigned*>(As4);
    const int rr = lane >> 2, kl = lane & 3;

#pragma unroll
    for (int i = 0; i < 8; ++i) {
        int idx = t + 256 * i;
        int m  = idx >> 4;
        int kh = idx & 15;
        int row = n0 + m;
        float4 v = make_float4(0.f, 0.f, 0.f, 0.f);
        if (row < n_rows)
            v = *(const float4*)(A + (size_t)row * 64 + kh * 4);
        As4[kh * 128 + (m ^ (kh & 7))] =
            make_uint4(f2tf(v.x), f2tf(v.y), f2tf(v.z), f2tf(v.w));
    }
#pragma unroll
    for (int i = 0; i < 4; ++i) {
        int idx = t + 256 * i;
        int kk = idx >> 4;
        int n4 = (idx & 15) << 2;
        float4 v = *(const float4*)(W + (size_t)kk * 64 + n4);
        int nsw = n4 ^ ((kk & 3) << 3);
        Ws[kk * 64 + nsw + 0] = f2tf(v.x);
        Ws[kk * 64 + nsw + 1] = f2tf(v.y);
        Ws[kk * 64 + nsw + 2] = f2tf(v.z);
        Ws[kk * 64 + nsw + 3] = f2tf(v.w);
    }
    __syncthreads();

    float acc[2][4][4];
#pragma unroll
    for (int mf = 0; mf < 2; ++mf)
#pragma unroll
        for (int nf = 0; nf < 4; ++nf)
#pragma unroll
            for (int r = 0; r < 4; ++r) acc[mf][nf][r] = 0.f;

#pragma unroll
    for (int ks = 0; ks < 8; ++ks) {
        const int kh0 = ks * 2;
        unsigned a[2][4];
#pragma unroll
        for (int mf = 0; mf < 2; ++mf) {
            int mb = warp_m * 32 + mf * 16 + rr;
            a[mf][0] = Asw[(kh0 * 128 + (mb ^ (kh0 & 7))) * 4 + kl];
            a[mf][1] = Asw[(kh0 * 128 + ((mb + 8) ^ (kh0 & 7))) * 4 + kl];
            a[mf][2] = Asw[((kh0 + 1) * 128 + (mb ^ ((kh0 + 1) & 7))) * 4 + kl];
            a[mf][3] = Asw[((kh0 + 1) * 128 + ((mb + 8) ^ ((kh0 + 1) & 7))) * 4 + kl];
        }
        unsigned b[4][2];
        const int kA = ks * 8 + kl;
        const int kB = kA + 4;
        const int swc = (kl << 3);
#pragma unroll
        for (int nf = 0; nf < 4; ++nf) {
            int n = warp_n * 32 + nf * 8 + rr;
            b[nf][0] = Ws[kA * 64 + (n ^ swc)];
            b[nf][1] = Ws[kB * 64 + (n ^ swc)];
        }
#pragma unroll
        for (int mf = 0; mf < 2; ++mf)
#pragma unroll
            for (int nf = 0; nf < 4; ++nf)
                mma_tf32(acc[mf][nf], a[mf], b[nf]);
    }

#pragma unroll
    for (int mf = 0; mf < 2; ++mf) {
        int row = n0 + warp_m * 32 + mf * 16 + rr;
#pragma unroll
        for (int nf = 0; nf < 4; ++nf) {
            int col = warp_n * 32 + nf * 8 + (lane & 3) * 2;
            if (row < n_rows)
                *(__half2*)(Ch + (size_t)row * 64 + col) =
                    __floats2half2_rn(acc[mf][nf][0], acc[mf][nf][1]);
            if (row + 8 < n_rows)
                *(__half2*)(Ch + (size_t)(row + 8) * 64 + col) =
                    __floats2half2_rn(acc[mf][nf][2], acc[mf][nf][3]);
        }
    }
}

// ---------------- fused GRU cell: h = GRU(m, h) -----------------------------
// 64-row blocks, 8 warps (warp_m in {0,1} x 32 rows, warp_n in {0..3} x 16 cols).
// 6 weight-panel passes over a shared 16KB Ws buffer; gi/gh never hit global.
__device__ __forceinline__ void load_ws192(unsigned* Ws, const float* __restrict__ W,
                                           int c0, int t)
{
#pragma unroll
    for (int i = 0; i < 4; ++i) {
        int idx = t + 256 * i;          // 0..1023
        int kk = idx >> 4;              // 0..63
        int n4 = (idx & 15) << 2;
        float4 v = *(const float4*)(W + (size_t)kk * G3 + c0 + n4);
        int nsw = n4 ^ ((kk & 3) << 3);
        Ws[kk * 64 + nsw + 0] = f2tf(v.x);
        Ws[kk * 64 + nsw + 1] = f2tf(v.y);
        Ws[kk * 64 + nsw + 2] = f2tf(v.z);
        Ws[kk * 64 + nsw + 3] = f2tf(v.w);
    }
}

__device__ __forceinline__ void panel_mma64(const unsigned* __restrict__ Asw,
                                            const unsigned* __restrict__ Ws,
                                            float acc[2][2][4],
                                            int warp_m, int warp_n, int rr, int kl)
{
#pragma unroll
    for (int ks = 0; ks < 8; ++ks) {
        const int kh0 = ks * 2;
        unsigned a[2][4];
#pragma unroll
        for (int mf = 0; mf < 2; ++mf) {
            int mb = warp_m * 32 + mf * 16 + rr;
            a[mf][0] = Asw[(kh0 * 64 + (mb ^ (kh0 & 7))) * 4 + kl];
            a[mf][1] = Asw[(kh0 * 64 + ((mb + 8) ^ (kh0 & 7))) * 4 + kl];
            a[mf][2] = Asw[((kh0 + 1) * 64 + (mb ^ ((kh0 + 1) & 7))) * 4 + kl];
            a[mf][3] = Asw[((kh0 + 1) * 64 + ((mb + 8) ^ ((kh0 + 1) & 7))) * 4 + kl];
        }
        unsigned b[2][2];
        const int kA = ks * 8 + kl, kB = kA + 4;
        const int swc = kl << 3;
#pragma unroll
        for (int nf = 0; nf < 2; ++nf) {
            int n = warp_n * 16 + nf * 8 + rr;
            b[nf][0] = Ws[kA * 64 + (n ^ swc)];
            b[nf][1] = Ws[kB * 64 + (n ^ swc)];
        }
#pragma unroll
        for (int mf = 0; mf < 2; ++mf)
#pragma unroll
            for (int nf = 0; nf < 2; ++nf)
                mma_tf32(acc[mf][nf], a[mf], b[nf]);
    }
}

__global__ void __launch_bounds__(256) gru_fused_kernel(
    const float* __restrict__ b_ih, const float* __restrict__ b_hh, int n_rows)
{
    __shared__ uint4 Am4[16 * 64];       // 16KB (m tile, tf32)
    __shared__ uint4 Ah4[16 * 64];       // 16KB (h tile, tf32)
    __shared__ unsigned Ws[64 * 64];     // 16KB (weight panel, reused)

    const int t = threadIdx.x, lane = t & 31, wid = t >> 5;
    const int warp_m = wid & 1;
    const int warp_n = wid >> 1;
    const int n0 = blockIdx.x * 64;
    const int rr = lane >> 2, kl = lane & 3;
    const unsigned* Am = reinterpret_cast<const unsigned*>(Am4);
    const unsigned* Ah = reinterpret_cast<const unsigned*>(Ah4);

    // stage m and h tiles (64 rows x 64 k)
#pragma unroll
    for (int i = 0; i < 4; ++i) {
        int idx = t + 256 * i;          // 0..1023
        int m  = idx >> 4;              // 0..63
        int kh = idx & 15;
        int row = n0 + m;
        float4 vm = make_float4(0.f, 0.f, 0.f, 0.f), vh = vm;
        if (row < n_rows) {
            vm = *(const float4*)(g_m + (size_t)row * 64 + kh * 4);
            vh = *(const float4*)(g_h + (size_t)row * 64 + kh * 4);
        }
        int s = kh * 64 + (m ^ (kh & 7));
        Am4[s] = make_uint4(f2tf(vm.x), f2tf(vm.y), f2tf(vm.z), f2tf(vm.w));
        Ah4[s] = make_uint4(f2tf(vh.x), f2tf(vh.y), f2tf(vh.z), f2tf(vh.w));
    }
    __syncthreads();

    float accr[2][2][4], accn[2][2][4], acct[2][2][4];
#pragma unroll
    for (int mf = 0; mf < 2; ++mf)
#pragma unroll
        for (int nf = 0; nf < 2; ++nf)
#pragma unroll
            for (int q = 0; q < 4; ++q) {
                accr[mf][nf][q] = 0.f; accn[mf][nf][q] = 0.f; acct[mf][nf][q] = 0.f;
            }

    // r gate: m@Wi_r + h@Wh_r (joint accumulation)
    load_ws192(Ws, g_wihT, 0, t); __syncthreads();
    panel_mma64(Am, Ws, accr, warp_m, warp_n, rr, kl); __syncthreads();
    load_ws192(Ws, g_whhT, 0, t); __syncthreads();
    panel_mma64(Ah, Ws, accr, warp_m, warp_n, rr, kl); __syncthreads();

    // n gate halves
    load_ws192(Ws, g_wihT, 128, t); __syncthreads();
    panel_mma64(Am, Ws, accn, warp_m, warp_n, rr, kl); __syncthreads();
    load_ws192(Ws, g_whhT, 128, t); __syncthreads();
    panel_mma64(Ah, Ws, acct, warp_m, warp_n, rr, kl); __syncthreads();

    // n = tanh(gi_n + r * gh_n); store into accr (r dies)
#pragma unroll
    for (int mf = 0; mf < 2; ++mf)
#pragma unroll
        for (int nf = 0; nf < 2; ++nf) {
            int colb = warp_n * 16 + nf * 8 + (lane & 3) * 2;
#pragma unroll
            for (int q = 0; q < 4; ++q) {
                int col = colb + (q & 1);
                float r = sigf(accr[mf][nf][q] + b_ih[col] + b_hh[col]);
                accr[mf][nf][q] = tanhf(accn[mf][nf][q] + b_ih[128 + col] +
                                        r * (acct[mf][nf][q] + b_hh[128 + col]));
                accn[mf][nf][q] = 0.f;   // reuse for z
            }
        }

    // z gate: joint accumulation into accn
    load_ws192(Ws, g_wihT, 64, t); __syncthreads();
    panel_mma64(Am, Ws, accn, warp_m, warp_n, rr, kl); __syncthreads();
    load_ws192(Ws, g_whhT, 64, t); __syncthreads();
    panel_mma64(Ah, Ws, accn, warp_m, warp_n, rr, kl);

    // h' = (1-z)*n + z*h
#pragma unroll
    for (int mf = 0; mf < 2; ++mf) {
#pragma unroll
        for (int nf = 0; nf < 2; ++nf) {
            int colb = warp_n * 16 + nf * 8 + (lane & 3) * 2;
            float bz0 = b_ih[64 + colb] + b_hh[64 + colb];
            float bz1 = b_ih[64 + colb + 1] + b_hh[64 + colb + 1];
#pragma unroll
            for (int half = 0; half < 2; ++half) {
                int row = n0 + warp_m * 32 + mf * 16 + rr + half * 8;
                if (row < n_rows) {
                    float2 h = *(const float2*)(g_h + (size_t)row * 64 + colb);
                    float z0 = sigf(accn[mf][nf][half * 2 + 0] + bz0);
                    float z1 = sigf(accn[mf][nf][half * 2 + 1] + bz1);
                    float n0v = accr[mf][nf][half * 2 + 0];
                    float n1v = accr[mf][nf][half * 2 + 1];
                    *(float2*)(g_h + (size_t)row * 64 + colb) =
                        make_float2((1.f - z0) * n0v + z0 * h.x,
                                    (1.f - z1) * n1v + z1 * h.y);
                }
            }
        }
    }
}

// ---------------- small kernels ----------------
__global__ void init_kernel()
{
    int i = blockIdx.x * blockDim.x + threadIdx.x;
    int T = gridDim.x * blockDim.x;
    for (int k = i; k < NN; k += T) g_cnt[k] = 0;
    if (i < DD) { g_bnsum[i] = 0.f; g_bnsumsq[i] = 0.f; }
}

__global__ void bn_stats_kernel()
{
    int t = blockIdx.x * blockDim.x + threadIdx.x;
    int col = t & 63;
    int r0 = t >> 6;
    int rs = (gridDim.x * blockDim.x) >> 6;
    float s = 0.f, ss = 0.f;
    for (int r = r0; r < NN; r += rs) {
        float v = g_h0[r * DD + col];
        s += v; ss += v * v;
    }
    atomicAdd(&g_bnsum[col], s);
    atomicAdd(&g_bnsumsq[col], ss);
}

__global__ void bn_apply_kernel(const float* __restrict__ bn_g,
                                const float* __restrict__ bn_b)
{
    int i = blockIdx.x * blockDim.x + threadIdx.x;
    int T = gridDim.x * blockDim.x;
    const float invn = 1.f / (float)NN;
    for (int k = i; k < NN * DD; k += T) {
        int c = k & 63;
        float mu  = g_bnsum[c] * invn;
        float var = g_bnsumsq[c] * invn - mu * mu;
        float v = (g_h0[k] - mu) * rsqrtf(var + BN_EPS) * bn_g[c] + bn_b[c];
        g_h[k] = v > 0.f ? v : 0.f;
    }
}

__global__ void transpose_kernel(const float* __restrict__ wih,
                                 const float* __restrict__ whh)
{
    int i = blockIdx.x * blockDim.x + threadIdx.x;
    if (i < G3 * DD) {
        int j = i >> 6, k = i & 63;
        g_wihT[k * G3 + j] = wih[i];
        g_whhT[k * G3 + j] = whh[i];
    }
}

__global__ void hist_kernel(const int* __restrict__ eidx)
{
    int i = blockIdx.x * blockDim.x + threadIdx.x;
    int T = gridDim.x * blockDim.x;
    for (int e = i; e < EE; e += T)
        atomicAdd(&g_cnt[eidx[EE + e]], 1);
}

__global__ void scan_kernel()
{
    __shared__ int sh[1024];
    int t = threadIdx.x;
    const int chunk = (NN + 1023) / 1024;
    int beg = t * chunk;
    int end = beg + chunk; if (end > NN) end = NN;
    int s = 0;
#pragma unroll 4
    for (int i = beg; i < end; ++i) s += g_cnt[i];
    sh[t] = s;
    __syncthreads();
    for (int off = 1; off < 1024; off <<= 1) {
        int v = (t >= off) ? sh[t - off] : 0;
        __syncthreads();
        sh[t] += v;
        __syncthreads();
    }
    int run = (t > 0) ? sh[t - 1] : 0;
    for (int i = beg; i < end; ++i) {
        g_rowstart[i] = run;
        g_cursor[i]   = run;
        run += g_cnt[i];
    }
}

__global__ void scatter_kernel(const int* __restrict__ eidx,
                               const float* __restrict__ edge_attr,
                               const float* __restrict__ att_edge)
{
    float a0 = att_edge[0], a1 = att_edge[1], a2 = att_edge[2];
    int i = blockIdx.x * blockDim.x + threadIdx.x;
    int T = gridDim.x * blockDim.x;
    for (int e = i; e < EE; e += T) {
        int d = eidx[EE + e];
        int s = eidx[e];
        int pos = atomicAdd(&g_cursor[d], 1);
        g_csrc[pos] = s;
        g_ceb[pos] = edge_attr[e * 3 + 0] * a0 + edge_attr[e * 3 + 1] * a1 +
                     edge_attr[e * 3 + 2] * a2;
    }
}

__global__ void attn_node_kernel(const float* __restrict__ att_dst,
                                 const float* __restrict__ att_src)
{
    int n = blockIdx.x * 8 + (threadIdx.x >> 5);
    int lane = threadIdx.x & 31;
    if (n >= NN) return;
    const __half2* x2 = (const __half2*)g_xth;
    float2 v  = __half22float2(x2[n * 32 + lane]);
    float2 ad = ((const float2*)att_dst)[lane];
    float2 as = ((const float2*)att_src)[lane];
    float vd = v.x * ad.x + v.y * ad.y;
    float vs = v.x * as.x + v.y * as.y;
#pragma unroll
    for (int o = 16; o; o >>= 1) {
        vd += __shfl_xor_sync(0xffffffffu, vd, o);
        vs += __shfl_xor_sync(0xffffffffu, vs, o);
    }
    if (lane == 0) { g_adst[n] = vd; g_asrc[n] = vs; }
}

// fused softmax + weighted aggregation, warp per node, smem-resident logits
__global__ void __launch_bounds__(256) attn_agg_kernel()
{
    __shared__ float slog[8 * 128];
    __shared__ int   ssi[8 * 128];

    int wslot = threadIdx.x >> 5;
    int n = blockIdx.x * 8 + wslot;
    int lane = threadIdx.x & 31;
    if (n >= NN) return;
    int deg = g_cnt[n], s0 = g_rowstart[n];
    float adst = g_adst[n];
    const __half2* xh2 = (const __half2*)g_xth;
    float* lw = slog + wslot * 128;
    int*   li = ssi + wslot * 128;
    float ax = 0.f, ay = 0.f, sum = 0.f;

    if (deg <= 128) {
        float vmax = -1e30f;
        for (int j = lane; j < deg; j += 32) {
            int si = g_csrc[s0 + j];
            float l = adst + g_asrc[si] + g_ceb[s0 + j];
            l = l >= 0.f ? l : SLOPE * l;
            li[j] = si;
            lw[j] = l;
            vmax = fmaxf(vmax, l);
        }
#pragma unroll
        for (int o = 16; o; o >>= 1)
            vmax = fmaxf(vmax, __shfl_xor_sync(0xffffffffu, vmax, o));
        for (int j = lane; j < deg; j += 32) {
            float e = __expf(lw[j] - vmax);
            lw[j] = e;
            sum += e;
        }
        __syncwarp();
        int j = 0;
        for (; j + 4 <= deg; j += 4) {
            float w0 = lw[j + 0], w1 = lw[j + 1], w2 = lw[j + 2], w3 = lw[j + 3];
            float2 v0 = __half22float2(xh2[li[j + 0] * 32 + lane]);
            float2 v1 = __half22float2(xh2[li[j + 1] * 32 + lane]);
            float2 v2 = __half22float2(xh2[li[j + 2] * 32 + lane]);
            float2 v3 = __half22float2(xh2[li[j + 3] * 32 + lane]);
            ax += w0 * v0.x + w1 * v1.x + w2 * v2.x + w3 * v3.x;
            ay += w0 * v0.y + w1 * v1.y + w2 * v2.y + w3 * v3.y;
        }
        for (; j < deg; ++j) {
            float2 v = __half22float2(xh2[li[j] * 32 + lane]);
            ax += lw[j] * v.x; ay += lw[j] * v.y;
        }
    } else {
        // fallback: logits staged via global
        float vmax = -1e30f;
        for (int j = lane; j < deg; j += 32) {
            float l = adst + g_asrc[g_csrc[s0 + j]] + g_ceb[s0 + j];
            l = l >= 0.f ? l : SLOPE * l;
            g_expd[s0 + j] = l;
            vmax = fmaxf(vmax, l);
        }
#pragma unroll
        for (int o = 16; o; o >>= 1)
            vmax = fmaxf(vmax, __shfl_xor_sync(0xffffffffu, vmax, o));
        for (int c0 = 0; c0 < deg; c0 += 128) {
            int cnt = deg - c0; if (cnt > 128) cnt = 128;
            __syncwarp();
            for (int u = 0; u < 4; ++u) {
                int j = c0 + lane + 32 * u;
                if (j < deg && lane + 32 * u < 128) {
                    float e = __expf(g_expd[s0 + j] - vmax);
                    sum += e;
                    lw[lane + 32 * u] = e;
                    li[lane + 32 * u] = g_csrc[s0 + j];
                }
            }
            __syncwarp();
            for (int j = 0; j < cnt; ++j) {
                float2 v = __half22float2(xh2[li[j] * 32 + lane]);
                ax += lw[j] * v.x; ay += lw[j] * v.y;
            }
        }
    }

#pragma unroll
    for (int o = 16; o; o >>= 1)
        sum += __shfl_xor_sync(0xffffffffu, sum, o);
    float dinv = (deg > 0) ? 1.f / sum : 0.f;
    float2 o;
    o.x = fmaxf(ax * dinv, 0.f);
    o.y = fmaxf(ay * dinv, 0.f);
    ((float2*)g_m)[n * 32 + lane] = o;
}

// ---------------- launch ----------------
extern "C" void kernel_launch(void* const* d_in, const int* in_sizes, int n_in,
                              void* d_out, int out_size)
{
    const float* x        = (const float*)d_in[0];
    const float* edge_at  = (const float*)d_in[1];
    const float* mlp_w    = (const float*)d_in[2];
    const float* mlp_b    = (const float*)d_in[3];
    const float* bn_g     = (const float*)d_in[4];
    const float* bn_b     = (const float*)d_in[5];
    const float* conv_w   = (const float*)d_in[6];
    const float* att_dst  = (const float*)d_in[7];
    const float* att_src  = (const float*)d_in[8];
    const float* att_edge = (const float*)d_in[9];
    const float* w_ih     = (const float*)d_in[10];
    const float* w_hh     = (const float*)d_in[11];
    const float* b_ih     = (const float*)d_in[12];
    const float* b_hh     = (const float*)d_in[13];
    const float* lin_w    = (const float*)d_in[14];
    const float* lin_b    = (const float*)d_in[15];
    const int*   eidx     = (const int*)d_in[16];   // int32 (JAX x64 disabled)
    float* out = (float*)d_out;

    float *p_h0, *p_h;
    __half *p_xth;
    cudaGetSymbolAddress((void**)&p_h0,  g_h0);
    cudaGetSymbolAddress((void**)&p_h,   g_h);
    cudaGetSymbolAddress((void**)&p_xth, g_xth);

    const int GB  = (NN + 127) / 128;      // 391 row blocks (128-row GEMMs)
    const int GB64 = (NN + 63) / 64;       // 782 row blocks (fused GRU)
    const int WPB = (NN + 7) / 8;          // 6250 warp-per-node blocks

    init_kernel<<<64, 256>>>();
    gemm128_tf32_kernel<<<dim3(GB, 1), 256>>>(x, mlp_w, mlp_b, nullptr, p_h0, NN, DD);
    bn_stats_kernel<<<256, 256>>>();
    bn_apply_kernel<<<512, 256>>>(bn_g, bn_b);
    transpose_kernel<<<(G3 * DD + 255) / 256, 256>>>(w_ih, w_hh);
    hist_kernel<<<2048, 256>>>(eidx);
    scan_kernel<<<1, 1024>>>();
    scatter_kernel<<<2048, 256>>>(eidx, edge_at, att_edge);

    for (int step = 0; step < 3; ++step) {
        gemm64h_tf32_kernel<<<GB, 256>>>(p_h, conv_w, p_xth, NN);
        attn_node_kernel<<<WPB, 256>>>(att_dst, att_src);
        attn_agg_kernel<<<WPB, 256>>>();
        gru_fused_kernel<<<GB64, 256>>>(b_ih, b_hh, NN);
    }

    // final: x @ lin_w + lin_b + h  (tf32, fused epilogue add)
    gemm128_tf32_kernel<<<dim3(GB, 1), 256>>>(x, lin_w, lin_b, p_h, out, NN, DD);
}

// round 6
// speedup vs baseline: 2.3377x; 1.0284x over previous
#include <cuda_runtime.h>
#include <cuda_fp16.h>
#include <math.h>
#include <stdint.h>

#define NN 50000
#define EE 1600000
#define IND 128
#define DD 64
#define G3 192
#define BN_EPS 1e-5f
#define SLOPE 0.2f

// ---------------- scratch (static __device__: no allocation) ----------------
__device__ float  g_h0[NN * DD];
__device__ float  g_h[NN * DD];
__device__ __half g_xth[NN * DD];
__device__ float  g_m[NN * DD];
__device__ float  g_adst[NN];
__device__ float  g_asrc[NN];
__device__ int    g_cnt[NN];
__device__ int    g_rowstart[NN];
__device__ int    g_cursor[NN];
__device__ int2   g_edge[EE];        // {src, __float_as_int(edge_bias)}
__device__ float  g_expd[EE];
__device__ float  g_wihT[DD * G3];
__device__ float  g_whhT[DD * G3];
__device__ float  g_bnsum[DD];
__device__ float  g_bnsumsq[DD];

// ---------------- tf32 helpers ----------------
__device__ __forceinline__ unsigned f2tf(float x) {
    unsigned r;
    asm("cvt.rna.tf32.f32 %0, %1;" : "=r"(r) : "f"(x));
    return r;
}

__device__ __forceinline__ void mma_tf32(float c[4], const unsigned a[4],
                                         const unsigned b[2]) {
    asm volatile(
        "mma.sync.aligned.m16n8k8.row.col.f32.tf32.tf32.f32 "
        "{%0,%1,%2,%3}, {%4,%5,%6,%7}, {%8,%9}, {%0,%1,%2,%3};"
        : "+f"(c[0]), "+f"(c[1]), "+f"(c[2]), "+f"(c[3])
        : "r"(a[0]), "r"(a[1]), "r"(a[2]), "r"(a[3]),
          "r"(b[0]), "r"(b[1]));
}

__device__ __forceinline__ float sigf(float x) {
    return 1.f / (1.f + __expf(-x));
}

// ---------------- tf32 GEMM, K=128 (embed & final) ----------------
__global__ void __launch_bounds__(256) gemm128_tf32_kernel(
    const float* __restrict__ A, const float* __restrict__ W,
    const float* __restrict__ bias, const float* __restrict__ extra,
    float* __restrict__ C, int n_rows, int P)
{
    __shared__ uint4 As4[16 * 128];
    __shared__ unsigned Ws[64 * 64];

    const int t    = threadIdx.x;
    const int lane = t & 31;
    const int wid  = t >> 5;
    const int warp_m = wid & 3;
    const int warp_n = wid >> 2;
    const int n0 = blockIdx.x * 128;
    const int c0 = blockIdx.y * 64;

    float acc[2][4][4];
#pragma unroll
    for (int mf = 0; mf < 2; ++mf)
#pragma unroll
        for (int nf = 0; nf < 4; ++nf)
#pragma unroll
            for (int r = 0; r < 4; ++r) acc[mf][nf][r] = 0.f;

    const unsigned* Asw = reinterpret_cast<const unsigned*>(As4);
    const int rr = lane >> 2, kl = lane & 3;

    for (int k0 = 0; k0 < 128; k0 += 64) {
        __syncthreads();
#pragma unroll
        for (int i = 0; i < 8; ++i) {
            int idx = t + 256 * i;
            int m  = idx >> 4;
            int kh = idx & 15;
            int row = n0 + m;
            float4 v = make_float4(0.f, 0.f, 0.f, 0.f);
            if (row < n_rows)
                v = *(const float4*)(A + (size_t)row * 128 + k0 + kh * 4);
            As4[kh * 128 + (m ^ (kh & 7))] =
                make_uint4(f2tf(v.x), f2tf(v.y), f2tf(v.z), f2tf(v.w));
        }
#pragma unroll
        for (int i = 0; i < 4; ++i) {
            int idx = t + 256 * i;
            int kk = idx >> 4;
            int n4 = (idx & 15) << 2;
            float4 v = *(const float4*)(W + (size_t)(k0 + kk) * P + c0 + n4);
            int nsw = n4 ^ ((kk & 3) << 3);
            Ws[kk * 64 + nsw + 0] = f2tf(v.x);
            Ws[kk * 64 + nsw + 1] = f2tf(v.y);
            Ws[kk * 64 + nsw + 2] = f2tf(v.z);
            Ws[kk * 64 + nsw + 3] = f2tf(v.w);
        }
        __syncthreads();

#pragma unroll
        for (int ks = 0; ks < 8; ++ks) {
            const int kh0 = ks * 2;
            unsigned a[2][4];
#pragma unroll
            for (int mf = 0; mf < 2; ++mf) {
                int mb = warp_m * 32 + mf * 16 + rr;
                a[mf][0] = Asw[(kh0 * 128 + (mb ^ (kh0 & 7))) * 4 + kl];
                a[mf][1] = Asw[(kh0 * 128 + ((mb + 8) ^ (kh0 & 7))) * 4 + kl];
                a[mf][2] = Asw[((kh0 + 1) * 128 + (mb ^ ((kh0 + 1) & 7))) * 4 + kl];
                a[mf][3] = Asw[((kh0 + 1) * 128 + ((mb + 8) ^ ((kh0 + 1) & 7))) * 4 + kl];
            }
            unsigned b[4][2];
            const int kA = ks * 8 + kl;
            const int kB = kA + 4;
            const int swc = (kl << 3);
#pragma unroll
            for (int nf = 0; nf < 4; ++nf) {
                int n = warp_n * 32 + nf * 8 + rr;
                b[nf][0] = Ws[kA * 64 + (n ^ swc)];
                b[nf][1] = Ws[kB * 64 + (n ^ swc)];
            }
#pragma unroll
            for (int mf = 0; mf < 2; ++mf)
#pragma unroll
                for (int nf = 0; nf < 4; ++nf)
                    mma_tf32(acc[mf][nf], a[mf], b[nf]);
        }
    }

#pragma unroll
    for (int mf = 0; mf < 2; ++mf) {
        int row = n0 + warp_m * 32 + mf * 16 + rr;
#pragma unroll
        for (int nf = 0; nf < 4; ++nf) {
            int col = c0 + warp_n * 32 + nf * 8 + (lane & 3) * 2;
            float b0v = 0.f, b1v = 0.f;
            if (bias) { b0v = bias[col]; b1v = bias[col + 1]; }
            if (row < n_rows) {
                float e0 = extra ? extra[(size_t)row * P + col] : 0.f;
                float e1 = extra ? extra[(size_t)row * P + col + 1] : 0.f;
                *(float2*)(C + (size_t)row * P + col) =
                    make_float2(acc[mf][nf][0] + b0v + e0,
                                acc[mf][nf][1] + b1v + e1);
            }
            if (row + 8 < n_rows) {
                float e0 = extra ? extra[(size_t)(row + 8) * P + col] : 0.f;
                float e1 = extra ? extra[(size_t)(row + 8) * P + col + 1] : 0.f;
                *(float2*)(C + (size_t)(row + 8) * P + col) =
                    make_float2(acc[mf][nf][2] + b0v + e0,
                                acc[mf][nf][3] + b1v + e1);
            }
        }
    }
}

// ---------------- tf32 GEMM, K=64, half output (conv) ----------------
__global__ void __launch_bounds__(256) gemm64h_tf32_kernel(
    const float* __restrict__ A, const float* __restrict__ W,
    __half* __restrict__ Ch, int n_rows)
{
    __shared__ uint4 As4[16 * 128];
    __shared__ unsigned Ws[64 * 64];

    const int t    = threadIdx.x;
    const int lane = t & 31;
    const int wid  = t >> 5;
    const int warp_m = wid & 3;
    const int warp_n = wid >> 2;
    const int n0 = blockIdx.x * 128;

    const unsigned* Asw = reinterpret_cast<const unsigned*>(As4);
    const int rr = lane >> 2, kl = lane & 3;

#pragma unroll
    for (int i = 0; i < 8; ++i) {
        int idx = t + 256 * i;
        int m  = idx >> 4;
        int kh = idx & 15;
        int row = n0 + m;
        float4 v = make_float4(0.f, 0.f, 0.f, 0.f);
        if (row < n_rows)
            v = *(const float4*)(A + (size_t)row * 64 + kh * 4);
        As4[kh * 128 + (m ^ (kh & 7))] =
            make_uint4(f2tf(v.x), f2tf(v.y), f2tf(v.z), f2tf(v.w));
    }
#pragma unroll
    for (int i = 0; i < 4; ++i) {
        int idx = t + 256 * i;
        int kk = idx >> 4;
        int n4 = (idx & 15) << 2;
        float4 v = *(const float4*)(W + (size_t)kk * 64 + n4);
        int nsw = n4 ^ ((kk & 3) << 3);
        Ws[kk * 64 + nsw + 0] = f2tf(v.x);
        Ws[kk * 64 + nsw + 1] = f2tf(v.y);
        Ws[kk * 64 + nsw + 2] = f2tf(v.z);
        Ws[kk * 64 + nsw + 3] = f2tf(v.w);
    }
    __syncthreads();

    float acc[2][4][4];
#pragma unroll
    for (int mf = 0; mf < 2; ++mf)
#pragma unroll
        for (int nf = 0; nf < 4; ++nf)
#pragma unroll
            for (int r = 0; r < 4; ++r) acc[mf][nf][r] = 0.f;

#pragma unroll
    for (int ks = 0; ks < 8; ++ks) {
        const int kh0 = ks * 2;
        unsigned a[2][4];
#pragma unroll
        for (int mf = 0; mf < 2; ++mf) {
            int mb = warp_m * 32 + mf * 16 + rr;
            a[mf][0] = Asw[(kh0 * 128 + (mb ^ (kh0 & 7))) * 4 + kl];
            a[mf][1] = Asw[(kh0 * 128 + ((mb + 8) ^ (kh0 & 7))) * 4 + kl];
            a[mf][2] = Asw[((kh0 + 1) * 128 + (mb ^ ((kh0 + 1) & 7))) * 4 + kl];
            a[mf][3] = Asw[((kh0 + 1) * 128 + ((mb + 8) ^ ((kh0 + 1) & 7))) * 4 + kl];
        }
        unsigned b[4][2];
        const int kA = ks * 8 + kl;
        const int kB = kA + 4;
        const int swc = (kl << 3);
#pragma unroll
        for (int nf = 0; nf < 4; ++nf) {
            int n = warp_n * 32 + nf * 8 + rr;
            b[nf][0] = Ws[kA * 64 + (n ^ swc)];
            b[nf][1] = Ws[kB * 64 + (n ^ swc)];
        }
#pragma unroll
        for (int mf = 0; mf < 2; ++mf)
#pragma unroll
            for (int nf = 0; nf < 4; ++nf)
                mma_tf32(acc[mf][nf], a[mf], b[nf]);
    }

#pragma unroll
    for (int mf = 0; mf < 2; ++mf) {
        int row = n0 + warp_m * 32 + mf * 16 + rr;
#pragma unroll
        for (int nf = 0; nf < 4; ++nf) {
            int col = warp_n * 32 + nf * 8 + (lane & 3) * 2;
            if (row < n_rows)
                *(__half2*)(Ch + (size_t)row * 64 + col) =
                    __floats2half2_rn(acc[mf][nf][0], acc[mf][nf][1]);
            if (row + 8 < n_rows)
                *(__half2*)(Ch + (size_t)(row + 8) * 64 + col) =
                    __floats2half2_rn(acc[mf][nf][2], acc[mf][nf][3]);
        }
    }
}

// ---------------- fused GRU cell ----------------
__device__ __forceinline__ void load_ws192(unsigned* Ws, const float* __restrict__ W,
                                           int c0, int t)
{
#pragma unroll
    for (int i = 0; i < 4; ++i) {
        int idx = t + 256 * i;
        int kk = idx >> 4;
        int n4 = (idx & 15) << 2;
        float4 v = *(const float4*)(W + (size_t)kk * G3 + c0 + n4);
        int nsw = n4 ^ ((kk & 3) << 3);
        Ws[kk * 64 + nsw + 0] = f2tf(v.x);
        Ws[kk * 64 + nsw + 1] = f2tf(v.y);
        Ws[kk * 64 + nsw + 2] = f2tf(v.z);
        Ws[kk * 64 + nsw + 3] = f2tf(v.w);
    }
}

__device__ __forceinline__ void panel_mma64(const unsigned* __restrict__ Asw,
                                            const unsigned* __restrict__ Ws,
                                            float acc[2][2][4],
                                            int warp_m, int warp_n, int rr, int kl)
{
#pragma unroll
    for (int ks = 0; ks < 8; ++ks) {
        const int kh0 = ks * 2;
        unsigned a[2][4];
#pragma unroll
        for (int mf = 0; mf < 2; ++mf) {
            int mb = warp_m * 32 + mf * 16 + rr;
            a[mf][0] = Asw[(kh0 * 64 + (mb ^ (kh0 & 7))) * 4 + kl];
            a[mf][1] = Asw[(kh0 * 64 + ((mb + 8) ^ (kh0 & 7))) * 4 + kl];
            a[mf][2] = Asw[((kh0 + 1) * 64 + (mb ^ ((kh0 + 1) & 7))) * 4 + kl];
            a[mf][3] = Asw[((kh0 + 1) * 64 + ((mb + 8) ^ ((kh0 + 1) & 7))) * 4 + kl];
        }
        unsigned b[2][2];
        const int kA = ks * 8 + kl, kB = kA + 4;
        const int swc = kl << 3;
#pragma unroll
        for (int nf = 0; nf < 2; ++nf) {
            int n = warp_n * 16 + nf * 8 + rr;
            b[nf][0] = Ws[kA * 64 + (n ^ swc)];
            b[nf][1] = Ws[kB * 64 + (n ^ swc)];
        }
#pragma unroll
        for (int mf = 0; mf < 2; ++mf)
#pragma unroll
            for (int nf = 0; nf < 2; ++nf)
                mma_tf32(acc[mf][nf], a[mf], b[nf]);
    }
}

__global__ void __launch_bounds__(256) gru_fused_kernel(
    const float* __restrict__ b_ih, const float* __restrict__ b_hh, int n_rows)
{
    __shared__ uint4 Am4[16 * 64];
    __shared__ uint4 Ah4[16 * 64];
    __shared__ unsigned Ws[64 * 64];

    const int t = threadIdx.x, lane = t & 31, wid = t >> 5;
    const int warp_m = wid & 1;
    const int warp_n = wid >> 1;
    const int n0 = blockIdx.x * 64;
    const int rr = lane >> 2, kl = lane & 3;
    const unsigned* Am = reinterpret_cast<const unsigned*>(Am4);
    const unsigned* Ah = reinterpret_cast<const unsigned*>(Ah4);

#pragma unroll
    for (int i = 0; i < 4; ++i) {
        int idx = t + 256 * i;
        int m  = idx >> 4;
        int kh = idx & 15;
        int row = n0 + m;
        float4 vm = make_float4(0.f, 0.f, 0.f, 0.f), vh = vm;
        if (row < n_rows) {
            vm = *(const float4*)(g_m + (size_t)row * 64 + kh * 4);
            vh = *(const float4*)(g_h + (size_t)row * 64 + kh * 4);
        }
        int s = kh * 64 + (m ^ (kh & 7));
        Am4[s] = make_uint4(f2tf(vm.x), f2tf(vm.y), f2tf(vm.z), f2tf(vm.w));
        Ah4[s] = make_uint4(f2tf(vh.x), f2tf(vh.y), f2tf(vh.z), f2tf(vh.w));
    }
    __syncthreads();

    float accr[2][2][4], accn[2][2][4], acct[2][2][4];
#pragma unroll
    for (int mf = 0; mf < 2; ++mf)
#pragma unroll
        for (int nf = 0; nf < 2; ++nf)
#pragma unroll
            for (int q = 0; q < 4; ++q) {
                accr[mf][nf][q] = 0.f; accn[mf][nf][q] = 0.f; acct[mf][nf][q] = 0.f;
            }

    load_ws192(Ws, g_wihT, 0, t); __syncthreads();
    panel_mma64(Am, Ws, accr, warp_m, warp_n, rr, kl); __syncthreads();
    load_ws192(Ws, g_whhT, 0, t); __syncthreads();
    panel_mma64(Ah, Ws, accr, warp_m, warp_n, rr, kl); __syncthreads();

    load_ws192(Ws, g_wihT, 128, t); __syncthreads();
    panel_mma64(Am, Ws, accn, warp_m, warp_n, rr, kl); __syncthreads();
    load_ws192(Ws, g_whhT, 128, t); __syncthreads();
    panel_mma64(Ah, Ws, acct, warp_m, warp_n, rr, kl); __syncthreads();

#pragma unroll
    for (int mf = 0; mf < 2; ++mf)
#pragma unroll
        for (int nf = 0; nf < 2; ++nf) {
            int colb = warp_n * 16 + nf * 8 + (lane & 3) * 2;
#pragma unroll
            for (int q = 0; q < 4; ++q) {
                int col = colb + (q & 1);
                float r = sigf(accr[mf][nf][q] + b_ih[col] + b_hh[col]);
                accr[mf][nf][q] = tanhf(accn[mf][nf][q] + b_ih[128 + col] +
                                        r * (acct[mf][nf][q] + b_hh[128 + col]));
                accn[mf][nf][q] = 0.f;
            }
        }

    load_ws192(Ws, g_wihT, 64, t); __syncthreads();
    panel_mma64(Am, Ws, accn, warp_m, warp_n, rr, kl); __syncthreads();
    load_ws192(Ws, g_whhT, 64, t); __syncthreads();
    panel_mma64(Ah, Ws, accn, warp_m, warp_n, rr, kl);

#pragma unroll
    for (int mf = 0; mf < 2; ++mf) {
#pragma unroll
        for (int nf = 0; nf < 2; ++nf) {
            int colb = warp_n * 16 + nf * 8 + (lane & 3) * 2;
            float bz0 = b_ih[64 + colb] + b_hh[64 + colb];
            float bz1 = b_ih[64 + colb + 1] + b_hh[64 + colb + 1];
#pragma unroll
            for (int half = 0; half < 2; ++half) {
                int row = n0 + warp_m * 32 + mf * 16 + rr + half * 8;
                if (row < n_rows) {
                    float2 h = *(const float2*)(g_h + (size_t)row * 64 + colb);
                    float z0 = sigf(accn[mf][nf][half * 2 + 0] + bz0);
                    float z1 = sigf(accn[mf][nf][half * 2 + 1] + bz1);
                    float n0v = accr[mf][nf][half * 2 + 0];
                    float n1v = accr[mf][nf][half * 2 + 1];
                    *(float2*)(g_h + (size_t)row * 64 + colb) =
                        make_float2((1.f - z0) * n0v + z0 * h.x,
                                    (1.f - z1) * n1v + z1 * h.y);
                }
            }
        }
    }
}

// ---------------- small kernels ----------------
__global__ void init_kernel()
{
    int i = blockIdx.x * blockDim.x + threadIdx.x;
    int T = gridDim.x * blockDim.x;
    for (int k = i; k < NN; k += T) g_cnt[k] = 0;
    if (i < DD) { g_bnsum[i] = 0.f; g_bnsumsq[i] = 0.f; }
}

__global__ void bn_stats_kernel()
{
    int t = blockIdx.x * blockDim.x + threadIdx.x;
    int col = t & 63;
    int r0 = t >> 6;
    int rs = (gridDim.x * blockDim.x) >> 6;
    float s = 0.f, ss = 0.f;
    for (int r = r0; r < NN; r += rs) {
        float v = g_h0[r * DD + col];
        s += v; ss += v * v;
    }
    atomicAdd(&g_bnsum[col], s);
    atomicAdd(&g_bnsumsq[col], ss);
}

__global__ void bn_apply_kernel(const float* __restrict__ bn_g,
                                const float* __restrict__ bn_b)
{
    int i = blockIdx.x * blockDim.x + threadIdx.x;
    int T = gridDim.x * blockDim.x;
    const float invn = 1.f / (float)NN;
    for (int k = i; k < NN * DD; k += T) {
        int c = k & 63;
        float mu  = g_bnsum[c] * invn;
        float var = g_bnsumsq[c] * invn - mu * mu;
        float v = (g_h0[k] - mu) * rsqrtf(var + BN_EPS) * bn_g[c] + bn_b[c];
        g_h[k] = v > 0.f ? v : 0.f;
    }
}

__global__ void transpose_kernel(const float* __restrict__ wih,
                                 const float* __restrict__ whh)
{
    int i = blockIdx.x * blockDim.x + threadIdx.x;
    if (i < G3 * DD) {
        int j = i >> 6, k = i & 63;
        g_wihT[k * G3 + j] = wih[i];
        g_whhT[k * G3 + j] = whh[i];
    }
}

__global__ void hist_kernel(const int* __restrict__ eidx)
{
    int i = blockIdx.x * blockDim.x + threadIdx.x;
    int T = gridDim.x * blockDim.x;
    for (int e = i; e < EE; e += T)
        atomicAdd(&g_cnt[eidx[EE + e]], 1);
}

__global__ void scan_kernel()
{
    __shared__ int sh[1024];
    int t = threadIdx.x;
    const int chunk = (NN + 1023) / 1024;
    int beg = t * chunk;
    int end = beg + chunk; if (end > NN) end = NN;
    int s = 0;
#pragma unroll 4
    for (int i = beg; i < end; ++i) s += g_cnt[i];
    sh[t] = s;
    __syncthreads();
    for (int off = 1; off < 1024; off <<= 1) {
        int v = (t >= off) ? sh[t - off] : 0;
        __syncthreads();
        sh[t] += v;
        __syncthreads();
    }
    int run = (t > 0) ? sh[t - 1] : 0;
    for (int i = beg; i < end; ++i) {
        g_rowstart[i] = run;
        g_cursor[i]   = run;
        run += g_cnt[i];
    }
}

__global__ void scatter_kernel(const int* __restrict__ eidx,
                               const float* __restrict__ edge_attr,
                               const float* __restrict__ att_edge)
{
    float a0 = att_edge[0], a1 = att_edge[1], a2 = att_edge[2];
    int i = blockIdx.x * blockDim.x + threadIdx.x;
    int T = gridDim.x * blockDim.x;
    for (int e = i; e < EE; e += T) {
        int d = eidx[EE + e];
        int s = eidx[e];
        int pos = atomicAdd(&g_cursor[d], 1);
        float eb = edge_attr[e * 3 + 0] * a0 + edge_attr[e * 3 + 1] * a1 +
                   edge_attr[e * 3 + 2] * a2;
        g_edge[pos] = make_int2(s, __float_as_int(eb));
    }
}

__global__ void attn_node_kernel(const float* __restrict__ att_dst,
                                 const float* __restrict__ att_src)
{
    int n = blockIdx.x * 8 + (threadIdx.x >> 5);
    int lane = threadIdx.x & 31;
    if (n >= NN) return;
    const __half2* x2 = (const __half2*)g_xth;
    float2 v  = __half22float2(x2[n * 32 + lane]);
    float2 ad = ((const float2*)att_dst)[lane];
    float2 as = ((const float2*)att_src)[lane];
    float vd = v.x * ad.x + v.y * ad.y;
    float vs = v.x * as.x + v.y * as.y;
#pragma unroll
    for (int o = 16; o; o >>= 1) {
        vd += __shfl_xor_sync(0xffffffffu, vd, o);
        vs += __shfl_xor_sync(0xffffffffu, vs, o);
    }
    if (lane == 0) { g_adst[n] = vd; g_asrc[n] = vs; }
}

// fused softmax + weighted aggregation, warp per node, smem-resident logits
__global__ void __launch_bounds__(256) attn_agg_kernel()
{
    __shared__ float slog[8 * 128];
    __shared__ int   ssi[8 * 128];

    int wslot = threadIdx.x >> 5;
    int n = blockIdx.x * 8 + wslot;
    int lane = threadIdx.x & 31;
    if (n >= NN) return;
    int deg = g_cnt[n], s0 = g_rowstart[n];
    float adst = g_adst[n];
    const __half2* xh2 = (const __half2*)g_xth;
    float* lw = slog + wslot * 128;
    int*   li = ssi + wslot * 128;
    float ax0 = 0.f, ay0 = 0.f, ax1 = 0.f, ay1 = 0.f, sum = 0.f;

    if (deg <= 128) {
        float vmax = -1e30f;
        for (int j = lane; j < deg; j += 32) {
            int2 e = g_edge[s0 + j];
            float l = adst + g_asrc[e.x] + __int_as_float(e.y);
            l = l >= 0.f ? l : SLOPE * l;
            li[j] = e.x;
            lw[j] = l;
            vmax = fmaxf(vmax, l);
        }
#pragma unroll
        for (int o = 16; o; o >>= 1)
            vmax = fmaxf(vmax, __shfl_xor_sync(0xffffffffu, vmax, o));
        for (int j = lane; j < deg; j += 32) {
            float e = __expf(lw[j] - vmax);
            lw[j] = e;
            sum += e;
        }
        __syncwarp();
        int j = 0;
        for (; j + 8 <= deg; j += 8) {
            float w0 = lw[j + 0], w1 = lw[j + 1], w2 = lw[j + 2], w3 = lw[j + 3];
            float w4 = lw[j + 4], w5 = lw[j + 5], w6 = lw[j + 6], w7 = lw[j + 7];
            float2 v0 = __half22float2(xh2[li[j + 0] * 32 + lane]);
            float2 v1 = __half22float2(xh2[li[j + 1] * 32 + lane]);
            float2 v2 = __half22float2(xh2[li[j + 2] * 32 + lane]);
            float2 v3 = __half22float2(xh2[li[j + 3] * 32 + lane]);
            float2 v4 = __half22float2(xh2[li[j + 4] * 32 + lane]);
            float2 v5 = __half22float2(xh2[li[j + 5] * 32 + lane]);
            float2 v6 = __half22float2(xh2[li[j + 6] * 32 + lane]);
            float2 v7 = __half22float2(xh2[li[j + 7] * 32 + lane]);
            ax0 += w0 * v0.x + w1 * v1.x + w2 * v2.x + w3 * v3.x;
            ay0 += w0 * v0.y + w1 * v1.y + w2 * v2.y + w3 * v3.y;
            ax1 += w4 * v4.x + w5 * v5.x + w6 * v6.x + w7 * v7.x;
            ay1 += w4 * v4.y + w5 * v5.y + w6 * v6.y + w7 * v7.y;
        }
        for (; j < deg; ++j) {
            float2 v = __half22float2(xh2[li[j] * 32 + lane]);
            ax0 += lw[j] * v.x; ay0 += lw[j] * v.y;
        }
    } else {
        float vmax = -1e30f;
        for (int j = lane; j < deg; j += 32) {
            int2 e = g_edge[s0 + j];
            float l = adst + g_asrc[e.x] + __int_as_float(e.y);
            l = l >= 0.f ? l : SLOPE * l;
            g_expd[s0 + j] = l;
            vmax = fmaxf(vmax, l);
        }
#pragma unroll
        for (int o = 16; o; o >>= 1)
            vmax = fmaxf(vmax, __shfl_xor_sync(0xffffffffu, vmax, o));
        for (int c0 = 0; c0 < deg; c0 += 128) {
            int cnt = deg - c0; if (cnt > 128) cnt = 128;
            __syncwarp();
            for (int u = 0; u < 4; ++u) {
                int j = c0 + lane + 32 * u;
                if (j < deg && lane + 32 * u < 128) {
                    float e = __expf(g_expd[s0 + j] - vmax);
                    sum += e;
                    lw[lane + 32 * u] = e;
                    li[lane + 32 * u] = g_edge[s0 + j].x;
                }
            }
            __syncwarp();
            for (int j = 0; j < cnt; ++j) {
                float2 v = __half22float2(xh2[li[j] * 32 + lane]);
                ax0 += lw[j] * v.x; ay0 += lw[j] * v.y;
            }
        }
    }

    float ax = ax0 + ax1, ay = ay0 + ay1;
#pragma unroll
    for (int o = 16; o; o >>= 1)
        sum += __shfl_xor_sync(0xffffffffu, sum, o);
    float dinv = (deg > 0) ? 1.f / sum : 0.f;
    float2 o;
    o.x = fmaxf(ax * dinv, 0.f);
    o.y = fmaxf(ay * dinv, 0.f);
    ((float2*)g_m)[n * 32 + lane] = o;
}

// ---------------- launch ----------------
extern "C" void kernel_launch(void* const* d_in, const int* in_sizes, int n_in,
                              void* d_out, int out_size)
{
    const float* x        = (const float*)d_in[0];
    const float* edge_at  = (const float*)d_in[1];
    const float* mlp_w    = (const float*)d_in[2];
    const float* mlp_b    = (const float*)d_in[3];
    const float* bn_g     = (const float*)d_in[4];
    const float* bn_b     = (const float*)d_in[5];
    const float* conv_w   = (const float*)d_in[6];
    const float* att_dst  = (const float*)d_in[7];
    const float* att_src  = (const float*)d_in[8];
    const float* att_edge = (const float*)d_in[9];
    const float* w_ih     = (const float*)d_in[10];
    const float* w_hh     = (const float*)d_in[11];
    const float* b_ih     = (const float*)d_in[12];
    const float* b_hh     = (const float*)d_in[13];
    const float* lin_w    = (const float*)d_in[14];
    const float* lin_b    = (const float*)d_in[15];
    const int*   eidx     = (const int*)d_in[16];   // int32 (JAX x64 disabled)
    float* out = (float*)d_out;

    float *p_h0, *p_h;
    __half *p_xth;
    cudaGetSymbolAddress((void**)&p_h0,  g_h0);
    cudaGetSymbolAddress((void**)&p_h,   g_h);
    cudaGetSymbolAddress((void**)&p_xth, g_xth);

    const int GB   = (NN + 127) / 128;
    const int GB64 = (NN + 63) / 64;
    const int WPB  = (NN + 7) / 8;

    init_kernel<<<64, 256>>>();
    gemm128_tf32_kernel<<<dim3(GB, 1), 256>>>(x, mlp_w, mlp_b, nullptr, p_h0, NN, DD);
    bn_stats_kernel<<<256, 256>>>();
    bn_apply_kernel<<<512, 256>>>(bn_g, bn_b);
    transpose_kernel<<<(G3 * DD + 255) / 256, 256>>>(w_ih, w_hh);
    hist_kernel<<<2048, 256>>>(eidx);
    scan_kernel<<<1, 1024>>>();
    scatter_kernel<<<2048, 256>>>(eidx, edge_at, att_edge);

    for (int step = 0; step < 3; ++step) {
        gemm64h_tf32_kernel<<<GB, 256>>>(p_h, conv_w, p_xth, NN);
        attn_node_kernel<<<WPB, 256>>>(att_dst, att_src);
        attn_agg_kernel<<<WPB, 256>>>();
        gru_fused_kernel<<<GB64, 256>>>(b_ih, b_hh, NN);
    }

    gemm128_tf32_kernel<<<dim3(GB, 1), 256>>>(x, lin_w, lin_b, p_h, out, NN, DD);
}

// round 7
// speedup vs baseline: 2.5815x; 1.1043x over previous
#include <cuda_runtime.h>
#include <cuda_fp16.h>
#include <math.h>
#include <stdint.h>

#define NN 50000
#define EE 1600000
#define IND 128
#define DD 64
#define G3 192
#define BN_EPS 1e-5f
#define SLOPE 0.2f

// ---------------- scratch (static __device__: no allocation) ----------------
__device__ float  g_h0[NN * DD];
__device__ float  g_h[NN * DD];
__device__ __half g_xth[NN * DD];
__device__ float  g_m[NN * DD];
__device__ float  g_adst[NN];
__device__ float  g_asrc[NN];
__device__ int    g_cnt[NN];
__device__ int    g_rowstart[NN];
__device__ int    g_cursor[NN];
__device__ int2   g_edge[EE];        // {src, __float_as_int(edge_bias)}
__device__ float  g_wihT[DD * G3];
__device__ float  g_whhT[DD * G3];
__device__ float  g_bnsum[DD];
__device__ float  g_bnsumsq[DD];

// ---------------- tf32 helpers ----------------
__device__ __forceinline__ unsigned f2tf(float x) {
    unsigned r;
    asm("cvt.rna.tf32.f32 %0, %1;" : "=r"(r) : "f"(x));
    return r;
}

__device__ __forceinline__ void mma_tf32(float c[4], const unsigned a[4],
                                         const unsigned b[2]) {
    asm volatile(
        "mma.sync.aligned.m16n8k8.row.col.f32.tf32.tf32.f32 "
        "{%0,%1,%2,%3}, {%4,%5,%6,%7}, {%8,%9}, {%0,%1,%2,%3};"
        : "+f"(c[0]), "+f"(c[1]), "+f"(c[2]), "+f"(c[3])
        : "r"(a[0]), "r"(a[1]), "r"(a[2]), "r"(a[3]),
          "r"(b[0]), "r"(b[1]));
}

__device__ __forceinline__ float sigf(float x) {
    return 1.f / (1.f + __expf(-x));
}

// 128-row-tile mainloop body shared by gemm kernels (A stride 128 in smem)
__device__ __forceinline__ void panel_mma128(const unsigned* __restrict__ Asw,
                                             const unsigned* __restrict__ Ws,
                                             float acc[2][4][4],
                                             int warp_m, int warp_n, int rr, int kl)
{
#pragma unroll
    for (int ks = 0; ks < 8; ++ks) {
        const int kh0 = ks * 2;
        unsigned a[2][4];
#pragma unroll
        for (int mf = 0; mf < 2; ++mf) {
            int mb = warp_m * 32 + mf * 16 + rr;
            a[mf][0] = Asw[(kh0 * 128 + (mb ^ (kh0 & 7))) * 4 + kl];
            a[mf][1] = Asw[(kh0 * 128 + ((mb + 8) ^ (kh0 & 7))) * 4 + kl];
            a[mf][2] = Asw[((kh0 + 1) * 128 + (mb ^ ((kh0 + 1) & 7))) * 4 + kl];
            a[mf][3] = Asw[((kh0 + 1) * 128 + ((mb + 8) ^ ((kh0 + 1) & 7))) * 4 + kl];
        }
        unsigned b[4][2];
        const int kA = ks * 8 + kl;
        const int kB = kA + 4;
        const int swc = (kl << 3);
#pragma unroll
        for (int nf = 0; nf < 4; ++nf) {
            int n = warp_n * 32 + nf * 8 + rr;
            b[nf][0] = Ws[kA * 64 + (n ^ swc)];
            b[nf][1] = Ws[kB * 64 + (n ^ swc)];
        }
#pragma unroll
        for (int mf = 0; mf < 2; ++mf)
#pragma unroll
            for (int nf = 0; nf < 4; ++nf)
                mma_tf32(acc[mf][nf], a[mf], b[nf]);
    }
}

// ---------------- tf32 GEMM, K=128 (embed & final) ----------------
__global__ void __launch_bounds__(256) gemm128_tf32_kernel(
    const float* __restrict__ A, const float* __restrict__ W,
    const float* __restrict__ bias, const float* __restrict__ extra,
    float* __restrict__ C, int n_rows, int P)
{
    __shared__ uint4 As4[16 * 128];
    __shared__ unsigned Ws[64 * 64];

    const int t    = threadIdx.x;
    const int lane = t & 31;
    const int wid  = t >> 5;
    const int warp_m = wid & 3;
    const int warp_n = wid >> 2;
    const int n0 = blockIdx.x * 128;
    const int c0 = blockIdx.y * 64;

    float acc[2][4][4];
#pragma unroll
    for (int mf = 0; mf < 2; ++mf)
#pragma unroll
        for (int nf = 0; nf < 4; ++nf)
#pragma unroll
            for (int r = 0; r < 4; ++r) acc[mf][nf][r] = 0.f;

    const unsigned* Asw = reinterpret_cast<const unsigned*>(As4);
    const int rr = lane >> 2, kl = lane & 3;

    for (int k0 = 0; k0 < 128; k0 += 64) {
        __syncthreads();
#pragma unroll
        for (int i = 0; i < 8; ++i) {
            int idx = t + 256 * i;
            int m  = idx >> 4;
            int kh = idx & 15;
            int row = n0 + m;
            float4 v = make_float4(0.f, 0.f, 0.f, 0.f);
            if (row < n_rows)
                v = *(const float4*)(A + (size_t)row * 128 + k0 + kh * 4);
            As4[kh * 128 + (m ^ (kh & 7))] =
                make_uint4(f2tf(v.x), f2tf(v.y), f2tf(v.z), f2tf(v.w));
        }
#pragma unroll
        for (int i = 0; i < 4; ++i) {
            int idx = t + 256 * i;
            int kk = idx >> 4;
            int n4 = (idx & 15) << 2;
            float4 v = *(const float4*)(W + (size_t)(k0 + kk) * P + c0 + n4);
            int nsw = n4 ^ ((kk & 3) << 3);
            Ws[kk * 64 + nsw + 0] = f2tf(v.x);
            Ws[kk * 64 + nsw + 1] = f2tf(v.y);
            Ws[kk * 64 + nsw + 2] = f2tf(v.z);
            Ws[kk * 64 + nsw + 3] = f2tf(v.w);
        }
        __syncthreads();
        panel_mma128(Asw, Ws, acc, warp_m, warp_n, rr, kl);
    }

#pragma unroll
    for (int mf = 0; mf < 2; ++mf) {
        int row = n0 + warp_m * 32 + mf * 16 + rr;
#pragma unroll
        for (int nf = 0; nf < 4; ++nf) {
            int col = c0 + warp_n * 32 + nf * 8 + (lane & 3) * 2;
            float b0v = 0.f, b1v = 0.f;
            if (bias) { b0v = bias[col]; b1v = bias[col + 1]; }
            if (row < n_rows) {
                float e0 = extra ? extra[(size_t)row * P + col] : 0.f;
                float e1 = extra ? extra[(size_t)row * P + col + 1] : 0.f;
                *(float2*)(C + (size_t)row * P + col) =
                    make_float2(acc[mf][nf][0] + b0v + e0,
                                acc[mf][nf][1] + b1v + e1);
            }
            if (row + 8 < n_rows) {
                float e0 = extra ? extra[(size_t)(row + 8) * P + col] : 0.f;
                float e1 = extra ? extra[(size_t)(row + 8) * P + col + 1] : 0.f;
                *(float2*)(C + (size_t)(row + 8) * P + col) =
                    make_float2(acc[mf][nf][2] + b0v + e0,
                                acc[mf][nf][3] + b1v + e1);
            }
        }
    }
}

// ---- conv GEMM (K=64) with fused half-store + attention-score epilogue ----
__global__ void __launch_bounds__(256) gemm64h_attn_kernel(
    const float* __restrict__ A, const float* __restrict__ W,
    const float* __restrict__ att_dst, const float* __restrict__ att_src,
    __half* __restrict__ Ch, int n_rows)
{
    __shared__ uint4 As4[16 * 128];
    __shared__ unsigned Ws[64 * 64];

    const int t    = threadIdx.x;
    const int lane = t & 31;
    const int wid  = t >> 5;
    const int warp_m = wid & 3;
    const int warp_n = wid >> 2;
    const int n0 = blockIdx.x * 128;

    const unsigned* Asw = reinterpret_cast<const unsigned*>(As4);
    const int rr = lane >> 2, kl = lane & 3;

#pragma unroll
    for (int i = 0; i < 8; ++i) {
        int idx = t + 256 * i;
        int m  = idx >> 4;
        int kh = idx & 15;
        int row = n0 + m;
        float4 v = make_float4(0.f, 0.f, 0.f, 0.f);
        if (row < n_rows)
            v = *(const float4*)(A + (size_t)row * 64 + kh * 4);
        As4[kh * 128 + (m ^ (kh & 7))] =
            make_uint4(f2tf(v.x), f2tf(v.y), f2tf(v.z), f2tf(v.w));
    }
#pragma unroll
    for (int i = 0; i < 4; ++i) {
        int idx = t + 256 * i;
        int kk = idx >> 4;
        int n4 = (idx & 15) << 2;
        float4 v = *(const float4*)(W + (size_t)kk * 64 + n4);
        int nsw = n4 ^ ((kk & 3) << 3);
        Ws[kk * 64 + nsw + 0] = f2tf(v.x);
        Ws[kk * 64 + nsw + 1] = f2tf(v.y);
        Ws[kk * 64 + nsw + 2] = f2tf(v.z);
        Ws[kk * 64 + nsw + 3] = f2tf(v.w);
    }
    __syncthreads();

    float acc[2][4][4];
#pragma unroll
    for (int mf = 0; mf < 2; ++mf)
#pragma unroll
        for (int nf = 0; nf < 4; ++nf)
#pragma unroll
            for (int r = 0; r < 4; ++r) acc[mf][nf][r] = 0.f;

    panel_mma128(Asw, Ws, acc, warp_m, warp_n, rr, kl);

    // store xt as half
#pragma unroll
    for (int mf = 0; mf < 2; ++mf) {
        int row = n0 + warp_m * 32 + mf * 16 + rr;
#pragma unroll
        for (int nf = 0; nf < 4; ++nf) {
            int col = warp_n * 32 + nf * 8 + (lane & 3) * 2;
            if (row < n_rows)
                *(__half2*)(Ch + (size_t)row * 64 + col) =
                    __floats2half2_rn(acc[mf][nf][0], acc[mf][nf][1]);
            if (row + 8 < n_rows)
                *(__half2*)(Ch + (size_t)(row + 8) * 64 + col) =
                    __floats2half2_rn(acc[mf][nf][2], acc[mf][nf][3]);
        }
    }

    // fused attention scores: a_dst[row], a_src[row]
    float vd[2][2] = {{0.f, 0.f}, {0.f, 0.f}};
    float vs[2][2] = {{0.f, 0.f}, {0.f, 0.f}};
#pragma unroll
    for (int nf = 0; nf < 4; ++nf) {
        int colb = warp_n * 32 + nf * 8 + (lane & 3) * 2;
        float d0 = att_dst[colb], d1 = att_dst[colb + 1];
        float s0v = att_src[colb], s1v = att_src[colb + 1];
#pragma unroll
        for (int mf = 0; mf < 2; ++mf)
#pragma unroll
            for (int hf = 0; hf < 2; ++hf) {
                float a0 = acc[mf][nf][hf * 2 + 0];
                float a1 = acc[mf][nf][hf * 2 + 1];
                vd[mf][hf] += a0 * d0 + a1 * d1;
                vs[mf][hf] += a0 * s0v + a1 * s1v;
            }
    }
#pragma unroll
    for (int o = 1; o <= 2; o <<= 1)
#pragma unroll
        for (int mf = 0; mf < 2; ++mf)
#pragma unroll
            for (int hf = 0; hf < 2; ++hf) {
                vd[mf][hf] += __shfl_xor_sync(0xffffffffu, vd[mf][hf], o);
                vs[mf][hf] += __shfl_xor_sync(0xffffffffu, vs[mf][hf], o);
            }

    __syncthreads();                       // As4 reads done, reuse as scratch
    float* sred = (float*)As4;             // 256 floats used
    if (warp_n == 1 && kl == 0) {
#pragma unroll
        for (int mf = 0; mf < 2; ++mf)
#pragma unroll
            for (int hf = 0; hf < 2; ++hf) {
                int rl = warp_m * 32 + mf * 16 + hf * 8 + rr;
                sred[rl] = vd[mf][hf];
                sred[128 + rl] = vs[mf][hf];
            }
    }
    __syncthreads();
    if (warp_n == 0 && kl == 0) {
#pragma unroll
        for (int mf = 0; mf < 2; ++mf)
#pragma unroll
            for (int hf = 0; hf < 2; ++hf) {
                int rl = warp_m * 32 + mf * 16 + hf * 8 + rr;
                int row = n0 + rl;
                if (row < n_rows) {
                    g_adst[row] = vd[mf][hf] + sred[rl];
                    g_asrc[row] = vs[mf][hf] + sred[128 + rl];
                }
            }
    }
}

// ---------------- fused GRU cell, 128-row blocks, 80KB dynamic smem --------
__device__ __forceinline__ void load_ws192(unsigned* Ws, const float* __restrict__ W,
                                           int c0, int t)
{
#pragma unroll
    for (int i = 0; i < 4; ++i) {
        int idx = t + 256 * i;
        int kk = idx >> 4;
        int n4 = (idx & 15) << 2;
        float4 v = *(const float4*)(W + (size_t)kk * G3 + c0 + n4);
        int nsw = n4 ^ ((kk & 3) << 3);
        Ws[kk * 64 + nsw + 0] = f2tf(v.x);
        Ws[kk * 64 + nsw + 1] = f2tf(v.y);
        Ws[kk * 64 + nsw + 2] = f2tf(v.z);
        Ws[kk * 64 + nsw + 3] = f2tf(v.w);
    }
}

__global__ void __launch_bounds__(256) gru_fused_kernel(
    const float* __restrict__ b_ih, const float* __restrict__ b_hh, int n_rows)
{
    extern __shared__ char dsm[];
    uint4* Am4 = (uint4*)dsm;                     // 16*128 = 32KB
    uint4* Ah4 = (uint4*)(dsm + 32768);           // 32KB
    unsigned* Ws = (unsigned*)(dsm + 65536);      // 16KB

    const int t = threadIdx.x, lane = t & 31, wid = t >> 5;
    const int warp_m = wid & 3;
    const int warp_n = wid >> 2;
    const int n0 = blockIdx.x * 128;
    const int rr = lane >> 2, kl = lane & 3;
    const unsigned* Am = reinterpret_cast<const unsigned*>(Am4);
    const unsigned* Ah = reinterpret_cast<const unsigned*>(Ah4);

#pragma unroll
    for (int i = 0; i < 8; ++i) {
        int idx = t + 256 * i;                    // 0..2047
        int m  = idx >> 4;                        // 0..127
        int kh = idx & 15;
        int row = n0 + m;
        float4 vm = make_float4(0.f, 0.f, 0.f, 0.f), vh = vm;
        if (row < n_rows) {
            vm = *(const float4*)(g_m + (size_t)row * 64 + kh * 4);
            vh = *(const float4*)(g_h + (size_t)row * 64 + kh * 4);
        }
        int s = kh * 128 + (m ^ (kh & 7));
        Am4[s] = make_uint4(f2tf(vm.x), f2tf(vm.y), f2tf(vm.z), f2tf(vm.w));
        Ah4[s] = make_uint4(f2tf(vh.x), f2tf(vh.y), f2tf(vh.z), f2tf(vh.w));
    }
    __syncthreads();

    float accr[2][4][4], accn[2][4][4], acct[2][4][4];
#pragma unroll
    for (int mf = 0; mf < 2; ++mf)
#pragma unroll
        for (int nf = 0; nf < 4; ++nf)
#pragma unroll
            for (int q = 0; q < 4; ++q) {
                accr[mf][nf][q] = 0.f; accn[mf][nf][q] = 0.f; acct[mf][nf][q] = 0.f;
            }

    // r gate (joint), then n halves
    load_ws192(Ws, g_wihT, 0, t); __syncthreads();
    panel_mma128(Am, Ws, accr, warp_m, warp_n, rr, kl); __syncthreads();
    load_ws192(Ws, g_whhT, 0, t); __syncthreads();
    panel_mma128(Ah, Ws, accr, warp_m, warp_n, rr, kl); __syncthreads();

    load_ws192(Ws, g_wihT, 128, t); __syncthreads();
    panel_mma128(Am, Ws, accn, warp_m, warp_n, rr, kl); __syncthreads();
    load_ws192(Ws, g_whhT, 128, t); __syncthreads();
    panel_mma128(Ah, Ws, acct, warp_m, warp_n, rr, kl); __syncthreads();

#pragma unroll
    for (int mf = 0; mf < 2; ++mf)
#pragma unroll
        for (int nf = 0; nf < 4; ++nf) {
            int colb = warp_n * 32 + nf * 8 + (lane & 3) * 2;
#pragma unroll
            for (int q = 0; q < 4; ++q) {
                int col = colb + (q & 1);
                float r = sigf(accr[mf][nf][q] + b_ih[col] + b_hh[col]);
                accr[mf][nf][q] = tanhf(accn[mf][nf][q] + b_ih[128 + col] +
                                        r * (acct[mf][nf][q] + b_hh[128 + col]));
                accn[mf][nf][q] = 0.f;
            }
        }

    // z gate (joint)
    load_ws192(Ws, g_wihT, 64, t); __syncthreads();
    panel_mma128(Am, Ws, accn, warp_m, warp_n, rr, kl); __syncthreads();
    load_ws192(Ws, g_whhT, 64, t); __syncthreads();
    panel_mma128(Ah, Ws, accn, warp_m, warp_n, rr, kl);

#pragma unroll
    for (int mf = 0; mf < 2; ++mf) {
#pragma unroll
        for (int nf = 0; nf < 4; ++nf) {
            int colb = warp_n * 32 + nf * 8 + (lane & 3) * 2;
            float bz0 = b_ih[64 + colb] + b_hh[64 + colb];
            float bz1 = b_ih[64 + colb + 1] + b_hh[64 + colb + 1];
#pragma unroll
            for (int hf = 0; hf < 2; ++hf) {
                int row = n0 + warp_m * 32 + mf * 16 + rr + hf * 8;
                if (row < n_rows) {
                    float2 h = *(const float2*)(g_h + (size_t)row * 64 + colb);
                    float z0 = sigf(accn[mf][nf][hf * 2 + 0] + bz0);
                    float z1 = sigf(accn[mf][nf][hf * 2 + 1] + bz1);
                    float n0v = accr[mf][nf][hf * 2 + 0];
                    float n1v = accr[mf][nf][hf * 2 + 1];
                    *(float2*)(g_h + (size_t)row * 64 + colb) =
                        make_float2((1.f - z0) * n0v + z0 * h.x,
                                    (1.f - z1) * n1v + z1 * h.y);
                }
            }
        }
    }
}

// ---------------- small kernels ----------------
__global__ void init_kernel()
{
    int i = blockIdx.x * blockDim.x + threadIdx.x;
    int T = gridDim.x * blockDim.x;
    for (int k = i; k < NN; k += T) g_cnt[k] = 0;
    if (i < DD) { g_bnsum[i] = 0.f; g_bnsumsq[i] = 0.f; }
}

__global__ void __launch_bounds__(256) bn_stats_kernel()
{
    __shared__ float ssum[DD], ssq[DD];
    int t = threadIdx.x;
    if (t < DD) { ssum[t] = 0.f; ssq[t] = 0.f; }
    __syncthreads();

    int cg = (t & 15) * 4;
    int rpos = (blockIdx.x * 256 + t) >> 4;
    int rstride = (gridDim.x * 256) >> 4;
    float s[4] = {0.f, 0.f, 0.f, 0.f}, q[4] = {0.f, 0.f, 0.f, 0.f};
    for (int r = rpos; r < NN; r += rstride) {
        float4 v = *(const float4*)(g_h0 + (size_t)r * 64 + cg);
        s[0] += v.x; q[0] += v.x * v.x;
        s[1] += v.y; q[1] += v.y * v.y;
        s[2] += v.z; q[2] += v.z * v.z;
        s[3] += v.w; q[3] += v.w * v.w;
    }
#pragma unroll
    for (int k = 0; k < 4; ++k) {
        s[k] += __shfl_xor_sync(0xffffffffu, s[k], 16);
        q[k] += __shfl_xor_sync(0xffffffffu, q[k], 16);
    }
    if ((t & 31) < 16) {
#pragma unroll
        for (int k = 0; k < 4; ++k) {
            atomicAdd(&ssum[cg + k], s[k]);
            atomicAdd(&ssq[cg + k], q[k]);
        }
    }
    __syncthreads();
    if (t < DD) {
        atomicAdd(&g_bnsum[t], ssum[t]);
        atomicAdd(&g_bnsumsq[t], ssq[t]);
    }
}

__global__ void __launch_bounds__(256) bn_apply_kernel(
    const float* __restrict__ bn_g, const float* __restrict__ bn_b)
{
    int i = blockIdx.x * blockDim.x + threadIdx.x;
    int T = gridDim.x * blockDim.x;
    const float invn = 1.f / (float)NN;
    const float4* h04 = (const float4*)g_h0;
    float4* h4 = (float4*)g_h;
    for (int k = i; k < NN * 16; k += T) {
        int cg = (k & 15) * 4;
        float4 v = h04[k];
        float o[4] = {v.x, v.y, v.z, v.w};
#pragma unroll
        for (int j = 0; j < 4; ++j) {
            float mu  = g_bnsum[cg + j] * invn;
            float var = g_bnsumsq[cg + j] * invn - mu * mu;
            float w = (o[j] - mu) * rsqrtf(var + BN_EPS) * bn_g[cg + j] + bn_b[cg + j];
            o[j] = w > 0.f ? w : 0.f;
        }
        h4[k] = make_float4(o[0], o[1], o[2], o[3]);
    }
}

__global__ void transpose_kernel(const float* __restrict__ wih,
                                 const float* __restrict__ whh)
{
    int i = blockIdx.x * blockDim.x + threadIdx.x;
    if (i < G3 * DD) {
        int j = i >> 6, k = i & 63;
        g_wihT[k * G3 + j] = wih[i];
        g_whhT[k * G3 + j] = whh[i];
    }
}

__global__ void hist_kernel(const int* __restrict__ eidx)
{
    int i = blockIdx.x * blockDim.x + threadIdx.x;
    int T = gridDim.x * blockDim.x;
    for (int e = i; e < EE; e += T)
        atomicAdd(&g_cnt[eidx[EE + e]], 1);
}

__global__ void scan_kernel()
{
    __shared__ int sh[1024];
    int t = threadIdx.x;
    const int chunk = (NN + 1023) / 1024;
    int beg = t * chunk;
    int end = beg + chunk; if (end > NN) end = NN;
    int s = 0;
#pragma unroll 4
    for (int i = beg; i < end; ++i) s += g_cnt[i];
    sh[t] = s;
    __syncthreads();
    for (int off = 1; off < 1024; off <<= 1) {
        int v = (t >= off) ? sh[t - off] : 0;
        __syncthreads();
        sh[t] += v;
        __syncthreads();
    }
    int run = (t > 0) ? sh[t - 1] : 0;
    for (int i = beg; i < end; ++i) {
        g_rowstart[i] = run;
        g_cursor[i]   = run;
        run += g_cnt[i];
    }
}

__global__ void scatter_kernel(const int* __restrict__ eidx,
                               const float* __restrict__ edge_attr,
                               const float* __restrict__ att_edge)
{
    float a0 = att_edge[0], a1 = att_edge[1], a2 = att_edge[2];
    int i = blockIdx.x * blockDim.x + threadIdx.x;
    int T = gridDim.x * blockDim.x;
    for (int e = i; e < EE; e += T) {
        int d = eidx[EE + e];
        int s = eidx[e];
        int pos = atomicAdd(&g_cursor[d], 1);
        float eb = edge_attr[e * 3 + 0] * a0 + edge_attr[e * 3 + 1] * a1 +
                   edge_attr[e * 3 + 2] * a2;
        g_edge[pos] = make_int2(s, __float_as_int(eb));
    }
}

// fused softmax + aggregation: single-pass exp (no max sub), warp per node
__global__ void __launch_bounds__(256) attn_agg_kernel()
{
    __shared__ float slog[8 * 128];
    __shared__ int   ssi[8 * 128];

    int wslot = threadIdx.x >> 5;
    int n = blockIdx.x * 8 + wslot;
    int lane = threadIdx.x & 31;
    if (n >= NN) return;
    int deg = g_cnt[n], s0 = g_rowstart[n];
    float adst = g_adst[n];
    const __half2* xh2 = (const __half2*)g_xth;
    float* lw = slog + wslot * 128;
    int*   li = ssi + wslot * 128;
    float ax0 = 0.f, ay0 = 0.f, ax1 = 0.f, ay1 = 0.f, sum = 0.f;

    if (deg <= 128) {
        for (int j = lane; j < deg; j += 32) {
            int2 e = g_edge[s0 + j];
            float l = adst + g_asrc[e.x] + __int_as_float(e.y);
            l = l >= 0.f ? l : SLOPE * l;
            float ex = __expf(l);
            li[j] = e.x;
            lw[j] = ex;
            sum += ex;
        }
        __syncwarp();
        int j = 0;
        for (; j + 8 <= deg; j += 8) {
            float w0 = lw[j + 0], w1 = lw[j + 1], w2 = lw[j + 2], w3 = lw[j + 3];
            float w4 = lw[j + 4], w5 = lw[j + 5], w6 = lw[j + 6], w7 = lw[j + 7];
            float2 v0 = __half22float2(xh2[li[j + 0] * 32 + lane]);
            float2 v1 = __half22float2(xh2[li[j + 1] * 32 + lane]);
            float2 v2 = __half22float2(xh2[li[j + 2] * 32 + lane]);
            float2 v3 = __half22float2(xh2[li[j + 3] * 32 + lane]);
            float2 v4 = __half22float2(xh2[li[j + 4] * 32 + lane]);
            float2 v5 = __half22float2(xh2[li[j + 5] * 32 + lane]);
            float2 v6 = __half22float2(xh2[li[j + 6] * 32 + lane]);
            float2 v7 = __half22float2(xh2[li[j + 7] * 32 + lane]);
            ax0 += w0 * v0.x + w1 * v1.x + w2 * v2.x + w3 * v3.x;
            ay0 += w0 * v0.y + w1 * v1.y + w2 * v2.y + w3 * v3.y;
            ax1 += w4 * v4.x + w5 * v5.x + w6 * v6.x + w7 * v7.x;
            ay1 += w4 * v4.y + w5 * v5.y + w6 * v6.y + w7 * v7.y;
        }
        for (; j < deg; ++j) {
            float2 v = __half22float2(xh2[li[j] * 32 + lane]);
            ax0 += lw[j] * v.x; ay0 += lw[j] * v.y;
        }
    } else {
        for (int c0 = 0; c0 < deg; c0 += 128) {
            int cnt = deg - c0; if (cnt > 128) cnt = 128;
            __syncwarp();
#pragma unroll
            for (int u = 0; u < 4; ++u) {
                int sl = lane + 32 * u;
                int j = c0 + sl;
                if (sl < cnt) {
                    int2 e = g_edge[s0 + j];
                    float l = adst + g_asrc[e.x] + __int_as_float(e.y);
                    l = l >= 0.f ? l : SLOPE * l;
                    float ex = __expf(l);
                    sum += ex;
                    lw[sl] = ex;
                    li[sl] = e.x;
                }
            }
            __syncwarp();
            for (int j = 0; j < cnt; ++j) {
                float2 v = __half22float2(xh2[li[j] * 32 + lane]);
                ax0 += lw[j] * v.x; ay0 += lw[j] * v.y;
            }
        }
    }

    float ax = ax0 + ax1, ay = ay0 + ay1;
#pragma unroll
    for (int o = 16; o; o >>= 1)
        sum += __shfl_xor_sync(0xffffffffu, sum, o);
    float dinv = (deg > 0) ? 1.f / sum : 0.f;
    float2 o;
    o.x = fmaxf(ax * dinv, 0.f);
    o.y = fmaxf(ay * dinv, 0.f);
    ((float2*)g_m)[n * 32 + lane] = o;
}

// ---------------- launch ----------------
extern "C" void kernel_launch(void* const* d_in, const int* in_sizes, int n_in,
                              void* d_out, int out_size)
{
    const float* x        = (const float*)d_in[0];
    const float* edge_at  = (const float*)d_in[1];
    const float* mlp_w    = (const float*)d_in[2];
    const float* mlp_b    = (const float*)d_in[3];
    const float* bn_g     = (const float*)d_in[4];
    const float* bn_b     = (const float*)d_in[5];
    const float* conv_w   = (const float*)d_in[6];
    const float* att_dst  = (const float*)d_in[7];
    const float* att_src  = (const float*)d_in[8];
    const float* att_edge = (const float*)d_in[9];
    const float* w_ih     = (const float*)d_in[10];
    const float* w_hh     = (const float*)d_in[11];
    const float* b_ih     = (const float*)d_in[12];
    const float* b_hh     = (const float*)d_in[13];
    const float* lin_w    = (const float*)d_in[14];
    const float* lin_b    = (const float*)d_in[15];
    const int*   eidx     = (const int*)d_in[16];   // int32 (JAX x64 disabled)
    float* out = (float*)d_out;

    float *p_h0, *p_h;
    __half *p_xth;
    cudaGetSymbolAddress((void**)&p_h0,  g_h0);
    cudaGetSymbolAddress((void**)&p_h,   g_h);
    cudaGetSymbolAddress((void**)&p_xth, g_xth);

    cudaFuncSetAttribute(gru_fused_kernel,
                         cudaFuncAttributeMaxDynamicSharedMemorySize, 81920);

    const int GB  = (NN + 127) / 128;   // 391
    const int WPB = (NN + 7) / 8;       // 6250

    init_kernel<<<64, 256>>>();
    gemm128_tf32_kernel<<<dim3(GB, 1), 256>>>(x, mlp_w, mlp_b, nullptr, p_h0, NN, DD);
    bn_stats_kernel<<<256, 256>>>();
    bn_apply_kernel<<<512, 256>>>(bn_g, bn_b);
    transpose_kernel<<<(G3 * DD + 255) / 256, 256>>>(w_ih, w_hh);
    hist_kernel<<<2048, 256>>>(eidx);
    scan_kernel<<<1, 1024>>>();
    scatter_kernel<<<2048, 256>>>(eidx, edge_at, att_edge);

    for (int step = 0; step < 3; ++step) {
        gemm64h_attn_kernel<<<GB, 256>>>(p_h, conv_w, att_dst, att_src, p_xth, NN);
        attn_agg_kernel<<<WPB, 256>>>();
        gru_fused_kernel<<<GB, 256, 81920>>>(b_ih, b_hh, NN);
    }

    gemm128_tf32_kernel<<<dim3(GB, 1), 256>>>(x, lin_w, lin_b, p_h, out, NN, DD);
}

// round 8
// speedup vs baseline: 2.6314x; 1.0193x over previous
#include <cuda_runtime.h>
#include <cuda_fp16.h>
#include <math.h>
#include <stdint.h>

#define NN 50000
#define EE 1600000
#define IND 128
#define DD 64
#define G3 192
#define BN_EPS 1e-5f
#define SLOPE 0.2f

// ---------------- scratch (static __device__: no allocation) ----------------
__device__ float  g_h0[NN * DD];
__device__ float  g_h[NN * DD];
__device__ __half g_xth[NN * DD];
__device__ float  g_m[NN * DD];
__device__ float  g_adst[NN];
__device__ float  g_asrc[NN];
__device__ int    g_cnt[NN];
__device__ int    g_rowstart[NN];
__device__ int    g_cursor[NN];
__device__ int2   g_edge[EE];        // {src, __float_as_int(edge_bias)}
__device__ float  g_wihT[DD * G3];
__device__ float  g_whhT[DD * G3];
__device__ float  g_bnsum[DD];
__device__ float  g_bnsumsq[DD];

// ---------------- tf32 helpers ----------------
__device__ __forceinline__ unsigned f2tf(float x) {
    unsigned r;
    asm("cvt.rna.tf32.f32 %0, %1;" : "=r"(r) : "f"(x));
    return r;
}

__device__ __forceinline__ void mma_tf32(float c[4], const unsigned a[4],
                                         const unsigned b[2]) {
    asm volatile(
        "mma.sync.aligned.m16n8k8.row.col.f32.tf32.tf32.f32 "
        "{%0,%1,%2,%3}, {%4,%5,%6,%7}, {%8,%9}, {%0,%1,%2,%3};"
        : "+f"(c[0]), "+f"(c[1]), "+f"(c[2]), "+f"(c[3])
        : "r"(a[0]), "r"(a[1]), "r"(a[2]), "r"(a[3]),
          "r"(b[0]), "r"(b[1]));
}

__device__ __forceinline__ float sigf(float x) {
    return 1.f / (1.f + __expf(-x));
}

// 128-row-tile mainloop body (A stride 128 in smem)
__device__ __forceinline__ void panel_mma128(const unsigned* __restrict__ Asw,
                                             const unsigned* __restrict__ Ws,
                                             float acc[2][4][4],
                                             int warp_m, int warp_n, int rr, int kl)
{
#pragma unroll
    for (int ks = 0; ks < 8; ++ks) {
        const int kh0 = ks * 2;
        unsigned a[2][4];
#pragma unroll
        for (int mf = 0; mf < 2; ++mf) {
            int mb = warp_m * 32 + mf * 16 + rr;
            a[mf][0] = Asw[(kh0 * 128 + (mb ^ (kh0 & 7))) * 4 + kl];
            a[mf][1] = Asw[(kh0 * 128 + ((mb + 8) ^ (kh0 & 7))) * 4 + kl];
            a[mf][2] = Asw[((kh0 + 1) * 128 + (mb ^ ((kh0 + 1) & 7))) * 4 + kl];
            a[mf][3] = Asw[((kh0 + 1) * 128 + ((mb + 8) ^ ((kh0 + 1) & 7))) * 4 + kl];
        }
        unsigned b[4][2];
        const int kA = ks * 8 + kl;
        const int kB = kA + 4;
        const int swc = (kl << 3);
#pragma unroll
        for (int nf = 0; nf < 4; ++nf) {
            int n = warp_n * 32 + nf * 8 + rr;
            b[nf][0] = Ws[kA * 64 + (n ^ swc)];
            b[nf][1] = Ws[kB * 64 + (n ^ swc)];
        }
#pragma unroll
        for (int mf = 0; mf < 2; ++mf)
#pragma unroll
            for (int nf = 0; nf < 4; ++nf)
                mma_tf32(acc[mf][nf], a[mf], b[nf]);
    }
}

// load 64x64 fp32 weight panel (row stride P) into swizzled tf32 smem
__device__ __forceinline__ void load_wsP(unsigned* Ws, const float* __restrict__ W,
                                         int P, int c0, int t)
{
#pragma unroll
    for (int i = 0; i < 4; ++i) {
        int idx = t + 256 * i;
        int kk = idx >> 4;
        int n4 = (idx & 15) << 2;
        float4 v = *(const float4*)(W + (size_t)kk * P + c0 + n4);
        int nsw = n4 ^ ((kk & 3) << 3);
        Ws[kk * 64 + nsw + 0] = f2tf(v.x);
        Ws[kk * 64 + nsw + 1] = f2tf(v.y);
        Ws[kk * 64 + nsw + 2] = f2tf(v.z);
        Ws[kk * 64 + nsw + 3] = f2tf(v.w);
    }
}

// xt half-store + fused attention-score epilogue (all 256 threads enter)
__device__ __forceinline__ void xt_attn_epilogue(
    float acc[2][4][4], const float* __restrict__ att_dst,
    const float* __restrict__ att_src, float* sred, __half* __restrict__ Ch,
    int n0, int n_rows, int warp_m, int warp_n, int lane)
{
    const int rr = lane >> 2, kl = lane & 3;

#pragma unroll
    for (int mf = 0; mf < 2; ++mf) {
        int row = n0 + warp_m * 32 + mf * 16 + rr;
#pragma unroll
        for (int nf = 0; nf < 4; ++nf) {
            int col = warp_n * 32 + nf * 8 + (lane & 3) * 2;
            if (row < n_rows)
                *(__half2*)(Ch + (size_t)row * 64 + col) =
                    __floats2half2_rn(acc[mf][nf][0], acc[mf][nf][1]);
            if (row + 8 < n_rows)
                *(__half2*)(Ch + (size_t)(row + 8) * 64 + col) =
                    __floats2half2_rn(acc[mf][nf][2], acc[mf][nf][3]);
        }
    }

    float vd[2][2] = {{0.f, 0.f}, {0.f, 0.f}};
    float vs[2][2] = {{0.f, 0.f}, {0.f, 0.f}};
#pragma unroll
    for (int nf = 0; nf < 4; ++nf) {
        int colb = warp_n * 32 + nf * 8 + (lane & 3) * 2;
        float d0 = att_dst[colb], d1 = att_dst[colb + 1];
        float s0v = att_src[colb], s1v = att_src[colb + 1];
#pragma unroll
        for (int mf = 0; mf < 2; ++mf)
#pragma unroll
            for (int hf = 0; hf < 2; ++hf) {
                float a0 = acc[mf][nf][hf * 2 + 0];
                float a1 = acc[mf][nf][hf * 2 + 1];
                vd[mf][hf] += a0 * d0 + a1 * d1;
                vs[mf][hf] += a0 * s0v + a1 * s1v;
            }
    }
#pragma unroll
    for (int o = 1; o <= 2; o <<= 1)
#pragma unroll
        for (int mf = 0; mf < 2; ++mf)
#pragma unroll
            for (int hf = 0; hf < 2; ++hf) {
                vd[mf][hf] += __shfl_xor_sync(0xffffffffu, vd[mf][hf], o);
                vs[mf][hf] += __shfl_xor_sync(0xffffffffu, vs[mf][hf], o);
            }

    __syncthreads();
    if (warp_n == 1 && kl == 0) {
#pragma unroll
        for (int mf = 0; mf < 2; ++mf)
#pragma unroll
            for (int hf = 0; hf < 2; ++hf) {
                int rl = warp_m * 32 + mf * 16 + hf * 8 + rr;
                sred[rl] = vd[mf][hf];
                sred[128 + rl] = vs[mf][hf];
            }
    }
    __syncthreads();
    if (warp_n == 0 && kl == 0) {
#pragma unroll
        for (int mf = 0; mf < 2; ++mf)
#pragma unroll
            for (int hf = 0; hf < 2; ++hf) {
                int rl = warp_m * 32 + mf * 16 + hf * 8 + rr;
                int row = n0 + rl;
                if (row < n_rows) {
                    g_adst[row] = vd[mf][hf] + sred[rl];
                    g_asrc[row] = vs[mf][hf] + sred[128 + rl];
                }
            }
    }
}

// ---------------- tf32 GEMM, K=128 (embed & final) ----------------
__global__ void __launch_bounds__(256) gemm128_tf32_kernel(
    const float* __restrict__ A, const float* __restrict__ W,
    const float* __restrict__ bias, const float* __restrict__ extra,
    float* __restrict__ C, int n_rows, int P)
{
    __shared__ uint4 As4[16 * 128];
    __shared__ unsigned Ws[64 * 64];

    const int t    = threadIdx.x;
    const int lane = t & 31;
    const int wid  = t >> 5;
    const int warp_m = wid & 3;
    const int warp_n = wid >> 2;
    const int n0 = blockIdx.x * 128;
    const int c0 = blockIdx.y * 64;

    float acc[2][4][4];
#pragma unroll
    for (int mf = 0; mf < 2; ++mf)
#pragma unroll
        for (int nf = 0; nf < 4; ++nf)
#pragma unroll
            for (int r = 0; r < 4; ++r) acc[mf][nf][r] = 0.f;

    const unsigned* Asw = reinterpret_cast<const unsigned*>(As4);
    const int rr = lane >> 2, kl = lane & 3;

    for (int k0 = 0; k0 < 128; k0 += 64) {
        __syncthreads();
#pragma unroll
        for (int i = 0; i < 8; ++i) {
            int idx = t + 256 * i;
            int m  = idx >> 4;
            int kh = idx & 15;
            int row = n0 + m;
            float4 v = make_float4(0.f, 0.f, 0.f, 0.f);
            if (row < n_rows)
                v = *(const float4*)(A + (size_t)row * 128 + k0 + kh * 4);
            As4[kh * 128 + (m ^ (kh & 7))] =
                make_uint4(f2tf(v.x), f2tf(v.y), f2tf(v.z), f2tf(v.w));
        }
        load_wsP(Ws, W + (size_t)k0 * P, P, c0, t);
        __syncthreads();
        panel_mma128(Asw, Ws, acc, warp_m, warp_n, rr, kl);
    }

#pragma unroll
    for (int mf = 0; mf < 2; ++mf) {
        int row = n0 + warp_m * 32 + mf * 16 + rr;
#pragma unroll
        for (int nf = 0; nf < 4; ++nf) {
            int col = c0 + warp_n * 32 + nf * 8 + (lane & 3) * 2;
            float b0v = 0.f, b1v = 0.f;
            if (bias) { b0v = bias[col]; b1v = bias[col + 1]; }
            if (row < n_rows) {
                float e0 = extra ? extra[(size_t)row * P + col] : 0.f;
                float e1 = extra ? extra[(size_t)row * P + col + 1] : 0.f;
                *(float2*)(C + (size_t)row * P + col) =
                    make_float2(acc[mf][nf][0] + b0v + e0,
                                acc[mf][nf][1] + b1v + e1);
            }
            if (row + 8 < n_rows) {
                float e0 = extra ? extra[(size_t)(row + 8) * P + col] : 0.f;
                float e1 = extra ? extra[(size_t)(row + 8) * P + col + 1] : 0.f;
                *(float2*)(C + (size_t)(row + 8) * P + col) =
                    make_float2(acc[mf][nf][2] + b0v + e0,
                                acc[mf][nf][3] + b1v + e1);
            }
        }
    }
}

// ---- standalone conv GEMM (K=64) with fused xt/attn epilogue (step 0) ----
__global__ void __launch_bounds__(256) gemm64h_attn_kernel(
    const float* __restrict__ A, const float* __restrict__ W,
    const float* __restrict__ att_dst, const float* __restrict__ att_src,
    __half* __restrict__ Ch, int n_rows)
{
    __shared__ uint4 As4[16 * 128];
    __shared__ unsigned Ws[64 * 64];

    const int t    = threadIdx.x;
    const int lane = t & 31;
    const int wid  = t >> 5;
    const int warp_m = wid & 3;
    const int warp_n = wid >> 2;
    const int n0 = blockIdx.x * 128;

    const unsigned* Asw = reinterpret_cast<const unsigned*>(As4);
    const int rr = lane >> 2, kl = lane & 3;

#pragma unroll
    for (int i = 0; i < 8; ++i) {
        int idx = t + 256 * i;
        int m  = idx >> 4;
        int kh = idx & 15;
        int row = n0 + m;
        float4 v = make_float4(0.f, 0.f, 0.f, 0.f);
        if (row < n_rows)
            v = *(const float4*)(A + (size_t)row * 64 + kh * 4);
        As4[kh * 128 + (m ^ (kh & 7))] =
            make_uint4(f2tf(v.x), f2tf(v.y), f2tf(v.z), f2tf(v.w));
    }
    load_wsP(Ws, W, 64, 0, t);
    __syncthreads();

    float acc[2][4][4];
#pragma unroll
    for (int mf = 0; mf < 2; ++mf)
#pragma unroll
        for (int nf = 0; nf < 4; ++nf)
#pragma unroll
            for (int r = 0; r < 4; ++r) acc[mf][nf][r] = 0.f;

    panel_mma128(Asw, Ws, acc, warp_m, warp_n, rr, kl);

    xt_attn_epilogue(acc, att_dst, att_src, (float*)As4, Ch,
                     n0, n_rows, warp_m, warp_n, lane);
}

// ---------------- fused GRU (+ optional next-step conv), 128-row blocks ----
template <bool DO_CONV>
__global__ void __launch_bounds__(256) gru_fused_kernel(
    const float* __restrict__ b_ih, const float* __restrict__ b_hh,
    const float* __restrict__ conv_w, const float* __restrict__ att_dst,
    const float* __restrict__ att_src, __half* __restrict__ Ch, int n_rows)
{
    extern __shared__ char dsm[];
    uint4* Am4 = (uint4*)dsm;                     // 32KB (m tile / later h' tile)
    uint4* Ah4 = (uint4*)(dsm + 32768);           // 32KB (h tile / later scratch)
    unsigned* Ws = (unsigned*)(dsm + 65536);      // 16KB

    const int t = threadIdx.x, lane = t & 31, wid = t >> 5;
    const int warp_m = wid & 3;
    const int warp_n = wid >> 2;
    const int n0 = blockIdx.x * 128;
    const int rr = lane >> 2, kl = lane & 3;
    const unsigned* Am = reinterpret_cast<const unsigned*>(Am4);
    const unsigned* Ah = reinterpret_cast<const unsigned*>(Ah4);

#pragma unroll
    for (int i = 0; i < 8; ++i) {
        int idx = t + 256 * i;
        int m  = idx >> 4;
        int kh = idx & 15;
        int row = n0 + m;
        float4 vm = make_float4(0.f, 0.f, 0.f, 0.f), vh = vm;
        if (row < n_rows) {
            vm = *(const float4*)(g_m + (size_t)row * 64 + kh * 4);
            vh = *(const float4*)(g_h + (size_t)row * 64 + kh * 4);
        }
        int s = kh * 128 + (m ^ (kh & 7));
        Am4[s] = make_uint4(f2tf(vm.x), f2tf(vm.y), f2tf(vm.z), f2tf(vm.w));
        Ah4[s] = make_uint4(f2tf(vh.x), f2tf(vh.y), f2tf(vh.z), f2tf(vh.w));
    }
    __syncthreads();

    float accr[2][4][4], accn[2][4][4], acct[2][4][4];
#pragma unroll
    for (int mf = 0; mf < 2; ++mf)
#pragma unroll
        for (int nf = 0; nf < 4; ++nf)
#pragma unroll
            for (int q = 0; q < 4; ++q) {
                accr[mf][nf][q] = 0.f; accn[mf][nf][q] = 0.f; acct[mf][nf][q] = 0.f;
            }

    load_wsP(Ws, g_wihT, G3, 0, t); __syncthreads();
    panel_mma128(Am, Ws, accr, warp_m, warp_n, rr, kl); __syncthreads();
    load_wsP(Ws, g_whhT, G3, 0, t); __syncthreads();
    panel_mma128(Ah, Ws, accr, warp_m, warp_n, rr, kl); __syncthreads();

    load_wsP(Ws, g_wihT, G3, 128, t); __syncthreads();
    panel_mma128(Am, Ws, accn, warp_m, warp_n, rr, kl); __syncthreads();
    load_wsP(Ws, g_whhT, G3, 128, t); __syncthreads();
    panel_mma128(Ah, Ws, acct, warp_m, warp_n, rr, kl); __syncthreads();

#pragma unroll
    for (int mf = 0; mf < 2; ++mf)
#pragma unroll
        for (int nf = 0; nf < 4; ++nf) {
            int colb = warp_n * 32 + nf * 8 + (lane & 3) * 2;
#pragma unroll
            for (int q = 0; q < 4; ++q) {
                int col = colb + (q & 1);
                float r = sigf(accr[mf][nf][q] + b_ih[col] + b_hh[col]);
                accr[mf][nf][q] = tanhf(accn[mf][nf][q] + b_ih[128 + col] +
                                        r * (acct[mf][nf][q] + b_hh[128 + col]));
                accn[mf][nf][q] = 0.f;
            }
        }

    load_wsP(Ws, g_wihT, G3, 64, t); __syncthreads();
    panel_mma128(Am, Ws, accn, warp_m, warp_n, rr, kl); __syncthreads();
    load_wsP(Ws, g_whhT, G3, 64, t); __syncthreads();
    panel_mma128(Ah, Ws, accn, warp_m, warp_n, rr, kl);

    // h' = (1-z)*n + z*h  (kept in accr for optional conv stage)
#pragma unroll
    for (int mf = 0; mf < 2; ++mf) {
#pragma unroll
        for (int nf = 0; nf < 4; ++nf) {
            int colb = warp_n * 32 + nf * 8 + (lane & 3) * 2;
            float bz0 = b_ih[64 + colb] + b_hh[64 + colb];
            float bz1 = b_ih[64 + colb + 1] + b_hh[64 + colb + 1];
#pragma unroll
            for (int hf = 0; hf < 2; ++hf) {
                int row = n0 + warp_m * 32 + mf * 16 + rr + hf * 8;
                float2 h = make_float2(0.f, 0.f);
                if (row < n_rows)
                    h = *(const float2*)(g_h + (size_t)row * 64 + colb);
                float z0 = sigf(accn[mf][nf][hf * 2 + 0] + bz0);
                float z1 = sigf(accn[mf][nf][hf * 2 + 1] + bz1);
                float hn0 = (1.f - z0) * accr[mf][nf][hf * 2 + 0] + z0 * h.x;
                float hn1 = (1.f - z1) * accr[mf][nf][hf * 2 + 1] + z1 * h.y;
                if (row < n_rows)
                    *(float2*)(g_h + (size_t)row * 64 + colb) =
                        make_float2(hn0, hn1);
                accr[mf][nf][hf * 2 + 0] = hn0;
                accr[mf][nf][hf * 2 + 1] = hn1;
            }
        }
    }

    if (DO_CONV) {
        __syncthreads();   // everyone done reading Am/Ah/Ws
        // store h' tile (tf32) into Am region; A-tile layout for panel_mma128
        unsigned* Amw = (unsigned*)Am4;
#pragma unroll
        for (int mf = 0; mf < 2; ++mf)
#pragma unroll
            for (int nf = 0; nf < 4; ++nf)
#pragma unroll
                for (int q = 0; q < 4; ++q) {
                    int m  = warp_m * 32 + mf * 16 + (q >> 1) * 8 + rr;
                    int c  = warp_n * 32 + nf * 8 + (lane & 3) * 2 + (q & 1);
                    int kh = c >> 2;
                    Amw[(kh * 128 + (m ^ (kh & 7))) * 4 + (c & 3)] =
                        f2tf(accr[mf][nf][q]);
                }
        load_wsP(Ws, conv_w, 64, 0, t);
        __syncthreads();

        float acc[2][4][4];
#pragma unroll
        for (int mf = 0; mf < 2; ++mf)
#pragma unroll
            for (int nf = 0; nf < 4; ++nf)
#pragma unroll
                for (int r = 0; r < 4; ++r) acc[mf][nf][r] = 0.f;

        panel_mma128(Am, Ws, acc, warp_m, warp_n, rr, kl);

        xt_attn_epilogue(acc, att_dst, att_src, (float*)Ah4, Ch,
                         n0, n_rows, warp_m, warp_n, lane);
    }
}

// ---------------- small kernels ----------------
__global__ void init_kernel()
{
    int i = blockIdx.x * blockDim.x + threadIdx.x;
    int T = gridDim.x * blockDim.x;
    for (int k = i; k < NN; k += T) g_cnt[k] = 0;
    if (i < DD) { g_bnsum[i] = 0.f; g_bnsumsq[i] = 0.f; }
}

__global__ void __launch_bounds__(256) bn_stats_kernel()
{
    __shared__ float ssum[DD], ssq[DD];
    int t = threadIdx.x;
    if (t < DD) { ssum[t] = 0.f; ssq[t] = 0.f; }
    __syncthreads();

    int cg = (t & 15) * 4;
    int rpos = (blockIdx.x * 256 + t) >> 4;
    int rstride = (gridDim.x * 256) >> 4;
    float s[4] = {0.f, 0.f, 0.f, 0.f}, q[4] = {0.f, 0.f, 0.f, 0.f};
    for (int r = rpos; r < NN; r += rstride) {
        float4 v = *(const float4*)(g_h0 + (size_t)r * 64 + cg);
        s[0] += v.x; q[0] += v.x * v.x;
        s[1] += v.y; q[1] += v.y * v.y;
        s[2] += v.z; q[2] += v.z * v.z;
        s[3] += v.w; q[3] += v.w * v.w;
    }
#pragma unroll
    for (int k = 0; k < 4; ++k) {
        s[k] += __shfl_xor_sync(0xffffffffu, s[k], 16);
        q[k] += __shfl_xor_sync(0xffffffffu, q[k], 16);
    }
    if ((t & 31) < 16) {
#pragma unroll
        for (int k = 0; k < 4; ++k) {
            atomicAdd(&ssum[cg + k], s[k]);
            atomicAdd(&ssq[cg + k], q[k]);
        }
    }
    __syncthreads();
    if (t < DD) {
        atomicAdd(&g_bnsum[t], ssum[t]);
        atomicAdd(&g_bnsumsq[t], ssq[t]);
    }
}

__global__ void __launch_bounds__(256) bn_apply_kernel(
    const float* __restrict__ bn_g, const float* __restrict__ bn_b)
{
    int i = blockIdx.x * blockDim.x + threadIdx.x;
    int T = gridDim.x * blockDim.x;
    const float invn = 1.f / (float)NN;
    const float4* h04 = (const float4*)g_h0;
    float4* h4 = (float4*)g_h;
    for (int k = i; k < NN * 16; k += T) {
        int cg = (k & 15) * 4;
        float4 v = h04[k];
        float o[4] = {v.x, v.y, v.z, v.w};
#pragma unroll
        for (int j = 0; j < 4; ++j) {
            float mu  = g_bnsum[cg + j] * invn;
            float var = g_bnsumsq[cg + j] * invn - mu * mu;
            float w = (o[j] - mu) * rsqrtf(var + BN_EPS) * bn_g[cg + j] + bn_b[cg + j];
            o[j] = w > 0.f ? w : 0.f;
        }
        h4[k] = make_float4(o[0], o[1], o[2], o[3]);
    }
}

__global__ void transpose_kernel(const float* __restrict__ wih,
                                 const float* __restrict__ whh)
{
    int i = blockIdx.x * blockDim.x + threadIdx.x;
    if (i < G3 * DD) {
        int j = i >> 6, k = i & 63;
        g_wihT[k * G3 + j] = wih[i];
        g_whhT[k * G3 + j] = whh[i];
    }
}

__global__ void hist_kernel(const int* __restrict__ eidx)
{
    const int4* d4 = (const int4*)(eidx + EE);
    int i = blockIdx.x * blockDim.x + threadIdx.x;
    int T = gridDim.x * blockDim.x;
    for (int e = i; e < EE / 4; e += T) {
        int4 v = d4[e];
        atomicAdd(&g_cnt[v.x], 1);
        atomicAdd(&g_cnt[v.y], 1);
        atomicAdd(&g_cnt[v.z], 1);
        atomicAdd(&g_cnt[v.w], 1);
    }
}

__global__ void scan_kernel()
{
    __shared__ int sh[1024];
    int t = threadIdx.x;
    const int chunk = (NN + 1023) / 1024;
    int beg = t * chunk;
    int end = beg + chunk; if (end > NN) end = NN;
    int s = 0;
#pragma unroll 4
    for (int i = beg; i < end; ++i) s += g_cnt[i];
    sh[t] = s;
    __syncthreads();
    for (int off = 1; off < 1024; off <<= 1) {
        int v = (t >= off) ? sh[t - off] : 0;
        __syncthreads();
        sh[t] += v;
        __syncthreads();
    }
    int run = (t > 0) ? sh[t - 1] : 0;
    for (int i = beg; i < end; ++i) {
        g_rowstart[i] = run;
        g_cursor[i]   = run;
        run += g_cnt[i];
    }
}

__global__ void scatter_kernel(const int* __restrict__ eidx,
                               const float* __restrict__ edge_attr,
                               const float* __restrict__ att_edge)
{
    float a0 = att_edge[0], a1 = att_edge[1], a2 = att_edge[2];
    const int4* s4 = (const int4*)eidx;
    const int4* d4 = (const int4*)(eidx + EE);
    const float4* ea4 = (const float4*)edge_attr;
    int i = blockIdx.x * blockDim.x + threadIdx.x;
    int T = gridDim.x * blockDim.x;
    for (int e = i; e < EE / 4; e += T) {
        int4 s = s4[e];
        int4 d = d4[e];
        float4 q0 = ea4[e * 3 + 0];
        float4 q1 = ea4[e * 3 + 1];
        float4 q2 = ea4[e * 3 + 2];
        float eb0 = q0.x * a0 + q0.y * a1 + q0.z * a2;
        float eb1 = q0.w * a0 + q1.x * a1 + q1.y * a2;
        float eb2 = q1.z * a0 + q1.w * a1 + q2.x * a2;
        float eb3 = q2.y * a0 + q2.z * a1 + q2.w * a2;
        g_edge[atomicAdd(&g_cursor[d.x], 1)] = make_int2(s.x, __float_as_int(eb0));
        g_edge[atomicAdd(&g_cursor[d.y], 1)] = make_int2(s.y, __float_as_int(eb1));
        g_edge[atomicAdd(&g_cursor[d.z], 1)] = make_int2(s.z, __float_as_int(eb2));
        g_edge[atomicAdd(&g_cursor[d.w], 1)] = make_int2(s.w, __float_as_int(eb3));
    }
}

// fused softmax + aggregation: single-pass exp, 4-edges-per-instruction gather
__global__ void __launch_bounds__(256) attn_agg_kernel()
{
    __shared__ float slog[8 * 128];
    __shared__ int   ssi[8 * 128];

    int wslot = threadIdx.x >> 5;
    int n = blockIdx.x * 8 + wslot;
    int lane = threadIdx.x & 31;
    if (n >= NN) return;
    int deg = g_cnt[n], s0 = g_rowstart[n];
    float adst = g_adst[n];
    float* lw = slog + wslot * 128;
    int*   li = ssi + wslot * 128;
    float sum = 0.f;

    if (deg <= 128) {
        for (int j = lane; j < deg; j += 32) {
            int2 e = g_edge[s0 + j];
            float l = adst + g_asrc[e.x] + __int_as_float(e.y);
            l = l >= 0.f ? l : SLOPE * l;
            float ex = __expf(l);
            li[j] = e.x;
            lw[j] = ex;
            sum += ex;
        }
        __syncwarp();

        const uint4* xh4 = (const uint4*)g_xth;   // row = 8 uint4
        const int f = lane & 7;                   // feature octet
        const int g = lane >> 3;                  // edge slot
        float acc8[8];
#pragma unroll
        for (int k = 0; k < 8; ++k) acc8[k] = 0.f;

        int j = 0;
        for (; j + 8 <= deg; j += 8) {
            int   i0 = li[j + g],      i1 = li[j + 4 + g];
            float w0 = lw[j + g],      w1 = lw[j + 4 + g];
            uint4 u0 = xh4[(size_t)i0 * 8 + f];
            uint4 u1 = xh4[(size_t)i1 * 8 + f];
            float2 p;
            p = __half22float2(*(__half2*)&u0.x); acc8[0] += w0 * p.x; acc8[1] += w0 * p.y;
            p = __half22float2(*(__half2*)&u0.y); acc8[2] += w0 * p.x; acc8[3] += w0 * p.y;
            p = __half22float2(*(__half2*)&u0.z); acc8[4] += w0 * p.x; acc8[5] += w0 * p.y;
            p = __half22float2(*(__half2*)&u0.w); acc8[6] += w0 * p.x; acc8[7] += w0 * p.y;
            p = __half22float2(*(__half2*)&u1.x); acc8[0] += w1 * p.x; acc8[1] += w1 * p.y;
            p = __half22float2(*(__half2*)&u1.y); acc8[2] += w1 * p.x; acc8[3] += w1 * p.y;
            p = __half22float2(*(__half2*)&u1.z); acc8[4] += w1 * p.x; acc8[5] += w1 * p.y;
            p = __half22float2(*(__half2*)&u1.w); acc8[6] += w1 * p.x; acc8[7] += w1 * p.y;
        }
        for (; j < deg; j += 4) {
            int jj = j + g;
            bool valid = jj < deg;
            int   idx = valid ? li[jj] : li[0];
            float w   = valid ? lw[jj] : 0.f;
            uint4 u = xh4[(size_t)idx * 8 + f];
            float2 p;
            p = __half22float2(*(__half2*)&u.x); acc8[0] += w * p.x; acc8[1] += w * p.y;
            p = __half22float2(*(__half2*)&u.y); acc8[2] += w * p.x; acc8[3] += w * p.y;
            p = __half22float2(*(__half2*)&u.z); acc8[4] += w * p.x; acc8[5] += w * p.y;
            p = __half22float2(*(__half2*)&u.w); acc8[6] += w * p.x; acc8[7] += w * p.y;
        }
#pragma unroll
        for (int k = 0; k < 8; ++k) {
            acc8[k] += __shfl_xor_sync(0xffffffffu, acc8[k], 8);
            acc8[k] += __shfl_xor_sync(0xffffffffu, acc8[k], 16);
        }
#pragma unroll
        for (int o = 16; o; o >>= 1)
            sum += __shfl_xor_sync(0xffffffffu, sum, o);
        float dinv = (deg > 0) ? 1.f / sum : 0.f;
        if (lane < 8) {
            float4 o1 = make_float4(fmaxf(acc8[0] * dinv, 0.f),
                                    fmaxf(acc8[1] * dinv, 0.f),
                                    fmaxf(acc8[2] * dinv, 0.f),
                                    fmaxf(acc8[3] * dinv, 0.f));
            float4 o2 = make_float4(fmaxf(acc8[4] * dinv, 0.f),
                                    fmaxf(acc8[5] * dinv, 0.f),
                                    fmaxf(acc8[6] * dinv, 0.f),
                                    fmaxf(acc8[7] * dinv, 0.f));
            *(float4*)(g_m + (size_t)n * 64 + lane * 8) = o1;
            *(float4*)(g_m + (size_t)n * 64 + lane * 8 + 4) = o2;
        }
    } else {
        const __half2* xh2 = (const __half2*)g_xth;
        float ax = 0.f, ay = 0.f;
        for (int c0 = 0; c0 < deg; c0 += 128) {
            int cnt = deg - c0; if (cnt > 128) cnt = 128;
            __syncwarp();
#pragma unroll
            for (int u = 0; u < 4; ++u) {
                int sl = lane + 32 * u;
                int j = c0 + sl;
                if (sl < cnt) {
                    int2 e = g_edge[s0 + j];
                    float l = adst + g_asrc[e.x] + __int_as_float(e.y);
                    l = l >= 0.f ? l : SLOPE * l;
                    float ex = __expf(l);
                    sum += ex;
                    lw[sl] = ex;
                    li[sl] = e.x;
                }
            }
            __syncwarp();
            for (int j = 0; j < cnt; ++j) {
                float2 v = __half22float2(xh2[li[j] * 32 + lane]);
                ax += lw[j] * v.x; ay += lw[j] * v.y;
            }
        }
#pragma unroll
        for (int o = 16; o; o >>= 1)
            sum += __shfl_xor_sync(0xffffffffu, sum, o);
        float dinv = 1.f / sum;
        float2 o;
        o.x = fmaxf(ax * dinv, 0.f);
        o.y = fmaxf(ay * dinv, 0.f);
        ((float2*)g_m)[n * 32 + lane] = o;
    }
}

// ---------------- launch ----------------
extern "C" void kernel_launch(void* const* d_in, const int* in_sizes, int n_in,
                              void* d_out, int out_size)
{
    const float* x        = (const float*)d_in[0];
    const float* edge_at  = (const float*)d_in[1];
    const float* mlp_w    = (const float*)d_in[2];
    const float* mlp_b    = (const float*)d_in[3];
    const float* bn_g     = (const float*)d_in[4];
    const float* bn_b     = (const float*)d_in[5];
    const float* conv_w   = (const float*)d_in[6];
    const float* att_dst  = (const float*)d_in[7];
    const float* att_src  = (const float*)d_in[8];
    const float* att_edge = (const float*)d_in[9];
    const float* w_ih     = (const float*)d_in[10];
    const float* w_hh     = (const float*)d_in[11];
    const float* b_ih     = (const float*)d_in[12];
    const float* b_hh     = (const float*)d_in[13];
    const float* lin_w    = (const float*)d_in[14];
    const float* lin_b    = (const float*)d_in[15];
    const int*   eidx     = (const int*)d_in[16];   // int32 (JAX x64 disabled)
    float* out = (float*)d_out;

    float *p_h0, *p_h;
    __half *p_xth;
    cudaGetSymbolAddress((void**)&p_h0,  g_h0);
    cudaGetSymbolAddress((void**)&p_h,   g_h);
    cudaGetSymbolAddress((void**)&p_xth, g_xth);

    cudaFuncSetAttribute(gru_fused_kernel<true>,
                         cudaFuncAttributeMaxDynamicSharedMemorySize, 81920);
    cudaFuncSetAttribute(gru_fused_kernel<false>,
                         cudaFuncAttributeMaxDynamicSharedMemorySize, 81920);

    const int GB  = (NN + 127) / 128;   // 391
    const int WPB = (NN + 7) / 8;       // 6250

    init_kernel<<<64, 256>>>();
    gemm128_tf32_kernel<<<dim3(GB, 1), 256>>>(x, mlp_w, mlp_b, nullptr, p_h0, NN, DD);
    bn_stats_kernel<<<256, 256>>>();
    bn_apply_kernel<<<512, 256>>>(bn_g, bn_b);
    transpose_kernel<<<(G3 * DD + 255) / 256, 256>>>(w_ih, w_hh);
    hist_kernel<<<1024, 256>>>(eidx);
    scan_kernel<<<1, 1024>>>();
    scatter_kernel<<<1024, 256>>>(eidx, edge_at, att_edge);

    // step 0 conv (from BN output)
    gemm64h_attn_kernel<<<GB, 256>>>(p_h, conv_w, att_dst, att_src, p_xth, NN);

    // step 0
    attn_agg_kernel<<<WPB, 256>>>();
    gru_fused_kernel<true><<<GB, 256, 81920>>>(b_ih, b_hh, conv_w,
                                               att_dst, att_src, p_xth, NN);
    // step 1
    attn_agg_kernel<<<WPB, 256>>>();
    gru_fused_kernel<true><<<GB, 256, 81920>>>(b_ih, b_hh, conv_w,
                                               att_dst, att_src, p_xth, NN);
    // step 2 (no conv needed after)
    attn_agg_kernel<<<WPB, 256>>>();
    gru_fused_kernel<false><<<GB, 256, 81920>>>(b_ih, b_hh, nullptr,
                                                nullptr, nullptr, nullptr, NN);

    gemm128_tf32_kernel<<<dim3(GB, 1), 256>>>(x, lin_w, lin_b, p_h, out, NN, DD);
}

// round 9
// speedup vs baseline: 2.9825x; 1.1334x over previous
#include <cuda_runtime.h>
#include <cuda_fp16.h>
#include <math.h>
#include <stdint.h>

#define NN 50000
#define EE 1600000
#define IND 128
#define DD 64
#define G3 192
#define BN_EPS 1e-5f
#define SLOPE 0.2f

// ---------------- scratch (static __device__: no allocation) ----------------
__device__ float  g_h0[NN * DD];
__device__ float  g_h[NN * DD];
__device__ __half g_xth[NN * DD];
__device__ float  g_m[NN * DD];
__device__ float  g_adst[NN];
__device__ float  g_asrc[NN];
__device__ int    g_cnt[NN];
__device__ int    g_rowstart[NN];
__device__ int    g_cursor[NN];
__device__ int2   g_edge[EE];        // {src, __float_as_int(edge_bias)}
__device__ float  g_wihT[DD * G3];
__device__ float  g_whhT[DD * G3];
__device__ float  g_bnsum[DD];
__device__ float  g_bnsumsq[DD];

// ---------------- tf32 helpers ----------------
__device__ __forceinline__ unsigned f2tf(float x) {
    unsigned r;
    asm("cvt.rna.tf32.f32 %0, %1;" : "=r"(r) : "f"(x));
    return r;
}

__device__ __forceinline__ void mma_tf32(float c[4], const unsigned a[4],
                                         const unsigned b[2]) {
    asm volatile(
        "mma.sync.aligned.m16n8k8.row.col.f32.tf32.tf32.f32 "
        "{%0,%1,%2,%3}, {%4,%5,%6,%7}, {%8,%9}, {%0,%1,%2,%3};"
        : "+f"(c[0]), "+f"(c[1]), "+f"(c[2]), "+f"(c[3])
        : "r"(a[0]), "r"(a[1]), "r"(a[2]), "r"(a[3]),
          "r"(b[0]), "r"(b[1]));
}

__device__ __forceinline__ float sigf(float x) {
    return 1.f / (1.f + __expf(-x));
}

// 128-row-tile mainloop body (A stride 128 in smem)
__device__ __forceinline__ void panel_mma128(const unsigned* __restrict__ Asw,
                                             const unsigned* __restrict__ Ws,
                                             float acc[2][4][4],
                                             int warp_m, int warp_n, int rr, int kl)
{
#pragma unroll
    for (int ks = 0; ks < 8; ++ks) {
        const int kh0 = ks * 2;
        unsigned a[2][4];
#pragma unroll
        for (int mf = 0; mf < 2; ++mf) {
            int mb = warp_m * 32 + mf * 16 + rr;
            a[mf][0] = Asw[(kh0 * 128 + (mb ^ (kh0 & 7))) * 4 + kl];
            a[mf][1] = Asw[(kh0 * 128 + ((mb + 8) ^ (kh0 & 7))) * 4 + kl];
            a[mf][2] = Asw[((kh0 + 1) * 128 + (mb ^ ((kh0 + 1) & 7))) * 4 + kl];
            a[mf][3] = Asw[((kh0 + 1) * 128 + ((mb + 8) ^ ((kh0 + 1) & 7))) * 4 + kl];
        }
        unsigned b[4][2];
        const int kA = ks * 8 + kl;
        const int kB = kA + 4;
        const int swc = (kl << 3);
#pragma unroll
        for (int nf = 0; nf < 4; ++nf) {
            int n = warp_n * 32 + nf * 8 + rr;
            b[nf][0] = Ws[kA * 64 + (n ^ swc)];
            b[nf][1] = Ws[kB * 64 + (n ^ swc)];
        }
#pragma unroll
        for (int mf = 0; mf < 2; ++mf)
#pragma unroll
            for (int nf = 0; nf < 4; ++nf)
                mma_tf32(acc[mf][nf], a[mf], b[nf]);
    }
}

// weight panel: split load (LDG->regs) and store (cvt+STS) for pipelining
__device__ __forceinline__ void ws_ld(float4* pf, const float* __restrict__ W,
                                      int P, int c0, int t)
{
#pragma unroll
    for (int i = 0; i < 4; ++i) {
        int idx = t + 256 * i;
        int kk = idx >> 4;
        int n4 = (idx & 15) << 2;
        pf[i] = *(const float4*)(W + (size_t)kk * P + c0 + n4);
    }
}

__device__ __forceinline__ void ws_st(unsigned* Ws, const float4* pf, int t)
{
#pragma unroll
    for (int i = 0; i < 4; ++i) {
        int idx = t + 256 * i;
        int kk = idx >> 4;
        int n4 = (idx & 15) << 2;
        int nsw = n4 ^ ((kk & 3) << 3);
        Ws[kk * 64 + nsw + 0] = f2tf(pf[i].x);
        Ws[kk * 64 + nsw + 1] = f2tf(pf[i].y);
        Ws[kk * 64 + nsw + 2] = f2tf(pf[i].z);
        Ws[kk * 64 + nsw + 3] = f2tf(pf[i].w);
    }
}

__device__ __forceinline__ void load_wsP(unsigned* Ws, const float* __restrict__ W,
                                         int P, int c0, int t)
{
    float4 pf[4];
    ws_ld(pf, W, P, c0, t);
    ws_st(Ws, pf, t);
}

// xt half-store + fused attention-score epilogue (all 256 threads enter)
__device__ __forceinline__ void xt_attn_epilogue(
    float acc[2][4][4], const float* __restrict__ att_dst,
    const float* __restrict__ att_src, float* sred, __half* __restrict__ Ch,
    int n0, int n_rows, int warp_m, int warp_n, int lane)
{
    const int rr = lane >> 2, kl = lane & 3;

#pragma unroll
    for (int mf = 0; mf < 2; ++mf) {
        int row = n0 + warp_m * 32 + mf * 16 + rr;
#pragma unroll
        for (int nf = 0; nf < 4; ++nf) {
            int col = warp_n * 32 + nf * 8 + (lane & 3) * 2;
            if (row < n_rows)
                *(__half2*)(Ch + (size_t)row * 64 + col) =
                    __floats2half2_rn(acc[mf][nf][0], acc[mf][nf][1]);
            if (row + 8 < n_rows)
                *(__half2*)(Ch + (size_t)(row + 8) * 64 + col) =
                    __floats2half2_rn(acc[mf][nf][2], acc[mf][nf][3]);
        }
    }

    float vd[2][2] = {{0.f, 0.f}, {0.f, 0.f}};
    float vs[2][2] = {{0.f, 0.f}, {0.f, 0.f}};
#pragma unroll
    for (int nf = 0; nf < 4; ++nf) {
        int colb = warp_n * 32 + nf * 8 + (lane & 3) * 2;
        float d0 = att_dst[colb], d1 = att_dst[colb + 1];
        float s0v = att_src[colb], s1v = att_src[colb + 1];
#pragma unroll
        for (int mf = 0; mf < 2; ++mf)
#pragma unroll
            for (int hf = 0; hf < 2; ++hf) {
                float a0 = acc[mf][nf][hf * 2 + 0];
                float a1 = acc[mf][nf][hf * 2 + 1];
                vd[mf][hf] += a0 * d0 + a1 * d1;
                vs[mf][hf] += a0 * s0v + a1 * s1v;
            }
    }
#pragma unroll
    for (int o = 1; o <= 2; o <<= 1)
#pragma unroll
        for (int mf = 0; mf < 2; ++mf)
#pragma unroll
            for (int hf = 0; hf < 2; ++hf) {
                vd[mf][hf] += __shfl_xor_sync(0xffffffffu, vd[mf][hf], o);
                vs[mf][hf] += __shfl_xor_sync(0xffffffffu, vs[mf][hf], o);
            }

    __syncthreads();
    if (warp_n == 1 && kl == 0) {
#pragma unroll
        for (int mf = 0; mf < 2; ++mf)
#pragma unroll
            for (int hf = 0; hf < 2; ++hf) {
                int rl = warp_m * 32 + mf * 16 + hf * 8 + rr;
                sred[rl] = vd[mf][hf];
                sred[128 + rl] = vs[mf][hf];
            }
    }
    __syncthreads();
    if (warp_n == 0 && kl == 0) {
#pragma unroll
        for (int mf = 0; mf < 2; ++mf)
#pragma unroll
            for (int hf = 0; hf < 2; ++hf) {
                int rl = warp_m * 32 + mf * 16 + hf * 8 + rr;
                int row = n0 + rl;
                if (row < n_rows) {
                    g_adst[row] = vd[mf][hf] + sred[rl];
                    g_asrc[row] = vs[mf][hf] + sred[128 + rl];
                }
            }
    }
}

// ---------------- tf32 GEMM, K=128 (embed & final) ----------------
__global__ void __launch_bounds__(256) gemm128_tf32_kernel(
    const float* __restrict__ A, const float* __restrict__ W,
    const float* __restrict__ bias, const float* __restrict__ extra,
    float* __restrict__ C, int n_rows, int P)
{
    __shared__ uint4 As4[16 * 128];
    __shared__ unsigned Ws[64 * 64];

    const int t    = threadIdx.x;
    const int lane = t & 31;
    const int wid  = t >> 5;
    const int warp_m = wid & 3;
    const int warp_n = wid >> 2;
    const int n0 = blockIdx.x * 128;
    const int c0 = blockIdx.y * 64;

    float acc[2][4][4];
#pragma unroll
    for (int mf = 0; mf < 2; ++mf)
#pragma unroll
        for (int nf = 0; nf < 4; ++nf)
#pragma unroll
            for (int r = 0; r < 4; ++r) acc[mf][nf][r] = 0.f;

    const unsigned* Asw = reinterpret_cast<const unsigned*>(As4);
    const int rr = lane >> 2, kl = lane & 3;

    for (int k0 = 0; k0 < 128; k0 += 64) {
        __syncthreads();
#pragma unroll
        for (int i = 0; i < 8; ++i) {
            int idx = t + 256 * i;
            int m  = idx >> 4;
            int kh = idx & 15;
            int row = n0 + m;
            float4 v = make_float4(0.f, 0.f, 0.f, 0.f);
            if (row < n_rows)
                v = *(const float4*)(A + (size_t)row * 128 + k0 + kh * 4);
            As4[kh * 128 + (m ^ (kh & 7))] =
                make_uint4(f2tf(v.x), f2tf(v.y), f2tf(v.z), f2tf(v.w));
        }
        load_wsP(Ws, W + (size_t)k0 * P, P, c0, t);
        __syncthreads();
        panel_mma128(Asw, Ws, acc, warp_m, warp_n, rr, kl);
    }

#pragma unroll
    for (int mf = 0; mf < 2; ++mf) {
        int row = n0 + warp_m * 32 + mf * 16 + rr;
#pragma unroll
        for (int nf = 0; nf < 4; ++nf) {
            int col = c0 + warp_n * 32 + nf * 8 + (lane & 3) * 2;
            float b0v = 0.f, b1v = 0.f;
            if (bias) { b0v = bias[col]; b1v = bias[col + 1]; }
            if (row < n_rows) {
                float e0 = extra ? extra[(size_t)row * P + col] : 0.f;
                float e1 = extra ? extra[(size_t)row * P + col + 1] : 0.f;
                *(float2*)(C + (size_t)row * P + col) =
                    make_float2(acc[mf][nf][0] + b0v + e0,
                                acc[mf][nf][1] + b1v + e1);
            }
            if (row + 8 < n_rows) {
                float e0 = extra ? extra[(size_t)(row + 8) * P + col] : 0.f;
                float e1 = extra ? extra[(size_t)(row + 8) * P + col + 1] : 0.f;
                *(float2*)(C + (size_t)(row + 8) * P + col) =
                    make_float2(acc[mf][nf][2] + b0v + e0,
                                acc[mf][nf][3] + b1v + e1);
            }
        }
    }
}

// ---- step-0 conv GEMM with fused BN-apply on input + xt/attn epilogue ----
__global__ void __launch_bounds__(256) gemm64h_bn_attn_kernel(
    const float* __restrict__ W,
    const float* __restrict__ att_dst, const float* __restrict__ att_src,
    const float* __restrict__ bn_g, const float* __restrict__ bn_b,
    __half* __restrict__ Ch, int n_rows)
{
    __shared__ uint4 As4[16 * 128];
    __shared__ unsigned Ws[64 * 64];
    __shared__ float sscale[64], sshift[64];

    const int t    = threadIdx.x;
    const int lane = t & 31;
    const int wid  = t >> 5;
    const int warp_m = wid & 3;
    const int warp_n = wid >> 2;
    const int n0 = blockIdx.x * 128;

    if (t < 64) {
        const float invn = 1.f / (float)NN;
        float mu  = g_bnsum[t] * invn;
        float var = g_bnsumsq[t] * invn - mu * mu;
        float sc  = bn_g[t] * rsqrtf(var + BN_EPS);
        sscale[t] = sc;
        sshift[t] = fmaf(-mu, sc, bn_b[t]);
    }
    __syncthreads();

    const unsigned* Asw = reinterpret_cast<const unsigned*>(As4);
    const int rr = lane >> 2, kl = lane & 3;

#pragma unroll
    for (int i = 0; i < 8; ++i) {
        int idx = t + 256 * i;
        int m  = idx >> 4;
        int kh = idx & 15;
        int row = n0 + m;
        int c = kh * 4;
        float4 v = make_float4(0.f, 0.f, 0.f, 0.f);
        if (row < n_rows)
            v = *(const float4*)(g_h0 + (size_t)row * 64 + c);
        float o0 = fmaxf(fmaf(v.x, sscale[c + 0], sshift[c + 0]), 0.f);
        float o1 = fmaxf(fmaf(v.y, sscale[c + 1], sshift[c + 1]), 0.f);
        float o2 = fmaxf(fmaf(v.z, sscale[c + 2], sshift[c + 2]), 0.f);
        float o3 = fmaxf(fmaf(v.w, sscale[c + 3], sshift[c + 3]), 0.f);
        if (row < n_rows)
            *(float4*)(g_h + (size_t)row * 64 + c) = make_float4(o0, o1, o2, o3);
        As4[kh * 128 + (m ^ (kh & 7))] =
            make_uint4(f2tf(o0), f2tf(o1), f2tf(o2), f2tf(o3));
    }
    load_wsP(Ws, W, 64, 0, t);
    __syncthreads();

    float acc[2][4][4];
#pragma unroll
    for (int mf = 0; mf < 2; ++mf)
#pragma unroll
        for (int nf = 0; nf < 4; ++nf)
#pragma unroll
            for (int r = 0; r < 4; ++r) acc[mf][nf][r] = 0.f;

    panel_mma128(Asw, Ws, acc, warp_m, warp_n, rr, kl);

    xt_attn_epilogue(acc, att_dst, att_src, (float*)As4, Ch,
                     n0, n_rows, warp_m, warp_n, lane);
}

// ---------------- fused GRU (+ optional next-step conv), pipelined panels ---
template <bool DO_CONV>
__global__ void __launch_bounds__(256) gru_fused_kernel(
    const float* __restrict__ b_ih, const float* __restrict__ b_hh,
    const float* __restrict__ conv_w, const float* __restrict__ att_dst,
    const float* __restrict__ att_src, __half* __restrict__ Ch, int n_rows)
{
    extern __shared__ char dsm[];
    uint4* Am4 = (uint4*)dsm;                       // 32KB (m tile / h' tile)
    uint4* Ah4 = (uint4*)(dsm + 32768);             // 32KB (h tile / scratch)
    unsigned* Ws0 = (unsigned*)(dsm + 65536);       // 16KB
    unsigned* Ws1 = (unsigned*)(dsm + 81920);       // 16KB

    const int t = threadIdx.x, lane = t & 31, wid = t >> 5;
    const int warp_m = wid & 3;
    const int warp_n = wid >> 2;
    const int n0 = blockIdx.x * 128;
    const int rr = lane >> 2, kl = lane & 3;
    const unsigned* Am = reinterpret_cast<const unsigned*>(Am4);
    const unsigned* Ah = reinterpret_cast<const unsigned*>(Ah4);

    float4 pf[4];
    ws_ld(pf, g_wihT, G3, 0, t);          // panel 0 in flight during staging

#pragma unroll
    for (int i = 0; i < 8; ++i) {
        int idx = t + 256 * i;
        int m  = idx >> 4;
        int kh = idx & 15;
        int row = n0 + m;
        float4 vm = make_float4(0.f, 0.f, 0.f, 0.f), vh = vm;
        if (row < n_rows) {
            vm = *(const float4*)(g_m + (size_t)row * 64 + kh * 4);
            vh = *(const float4*)(g_h + (size_t)row * 64 + kh * 4);
        }
        int s = kh * 128 + (m ^ (kh & 7));
        Am4[s] = make_uint4(f2tf(vm.x), f2tf(vm.y), f2tf(vm.z), f2tf(vm.w));
        Ah4[s] = make_uint4(f2tf(vh.x), f2tf(vh.y), f2tf(vh.z), f2tf(vh.w));
    }
    ws_st(Ws0, pf, t);
    __syncthreads();

    float accr[2][4][4], accn[2][4][4], acct[2][4][4];
#pragma unroll
    for (int mf = 0; mf < 2; ++mf)
#pragma unroll
        for (int nf = 0; nf < 4; ++nf)
#pragma unroll
            for (int q = 0; q < 4; ++q) {
                accr[mf][nf][q] = 0.f; accn[mf][nf][q] = 0.f; acct[mf][nf][q] = 0.f;
            }

    ws_ld(pf, g_whhT, G3, 0, t);
    panel_mma128(Am, Ws0, accr, warp_m, warp_n, rr, kl);
    ws_st(Ws1, pf, t); __syncthreads();

    ws_ld(pf, g_wihT, G3, 128, t);
    panel_mma128(Ah, Ws1, accr, warp_m, warp_n, rr, kl);
    ws_st(Ws0, pf, t); __syncthreads();

    ws_ld(pf, g_whhT, G3, 128, t);
    panel_mma128(Am, Ws0, accn, warp_m, warp_n, rr, kl);
    ws_st(Ws1, pf, t); __syncthreads();

    ws_ld(pf, g_wihT, G3, 64, t);
    panel_mma128(Ah, Ws1, acct, warp_m, warp_n, rr, kl);
    ws_st(Ws0, pf, t);

    // n = tanh(gi_n + r*gh_n)  (per-thread, overlaps other warps' work)
#pragma unroll
    for (int mf = 0; mf < 2; ++mf)
#pragma unroll
        for (int nf = 0; nf < 4; ++nf) {
            int colb = warp_n * 32 + nf * 8 + (lane & 3) * 2;
#pragma unroll
            for (int q = 0; q < 4; ++q) {
                int col = colb + (q & 1);
                float r = sigf(accr[mf][nf][q] + b_ih[col] + b_hh[col]);
                accr[mf][nf][q] = tanhf(accn[mf][nf][q] + b_ih[128 + col] +
                                        r * (acct[mf][nf][q] + b_hh[128 + col]));
                accn[mf][nf][q] = 0.f;
            }
        }
    __syncthreads();

    ws_ld(pf, g_whhT, G3, 64, t);
    panel_mma128(Am, Ws0, accn, warp_m, warp_n, rr, kl);
    ws_st(Ws1, pf, t); __syncthreads();

    panel_mma128(Ah, Ws1, accn, warp_m, warp_n, rr, kl);

    // h' = (1-z)*n + z*h  (kept in accr for optional conv stage)
#pragma unroll
    for (int mf = 0; mf < 2; ++mf) {
#pragma unroll
        for (int nf = 0; nf < 4; ++nf) {
            int colb = warp_n * 32 + nf * 8 + (lane & 3) * 2;
            float bz0 = b_ih[64 + colb] + b_hh[64 + colb];
            float bz1 = b_ih[64 + colb + 1] + b_hh[64 + colb + 1];
#pragma unroll
            for (int hf = 0; hf < 2; ++hf) {
                int row = n0 + warp_m * 32 + mf * 16 + rr + hf * 8;
                float2 h = make_float2(0.f, 0.f);
                if (row < n_rows)
                    h = *(const float2*)(g_h + (size_t)row * 64 + colb);
                float z0 = sigf(accn[mf][nf][hf * 2 + 0] + bz0);
                float z1 = sigf(accn[mf][nf][hf * 2 + 1] + bz1);
                float hn0 = (1.f - z0) * accr[mf][nf][hf * 2 + 0] + z0 * h.x;
                float hn1 = (1.f - z1) * accr[mf][nf][hf * 2 + 1] + z1 * h.y;
                if (row < n_rows)
                    *(float2*)(g_h + (size_t)row * 64 + colb) =
                        make_float2(hn0, hn1);
                accr[mf][nf][hf * 2 + 0] = hn0;
                accr[mf][nf][hf * 2 + 1] = hn1;
            }
        }
    }

    if (DO_CONV) {
        // Am free (last read drained by sync before final mma); Ws0 free too.
        ws_ld(pf, conv_w, 64, 0, t);
        unsigned* Amw = (unsigned*)Am4;
#pragma unroll
        for (int mf = 0; mf < 2; ++mf)
#pragma unroll
            for (int nf = 0; nf < 4; ++nf)
#pragma unroll
                for (int q = 0; q < 4; ++q) {
                    int m  = warp_m * 32 + mf * 16 + (q >> 1) * 8 + rr;
                    int c  = warp_n * 32 + nf * 8 + (lane & 3) * 2 + (q & 1);
                    int kh = c >> 2;
                    Amw[(kh * 128 + (m ^ (kh & 7))) * 4 + (c & 3)] =
                        f2tf(accr[mf][nf][q]);
                }
        ws_st(Ws0, pf, t);
        __syncthreads();

        float acc[2][4][4];
#pragma unroll
        for (int mf = 0; mf < 2; ++mf)
#pragma unroll
            for (int nf = 0; nf < 4; ++nf)
#pragma unroll
                for (int r = 0; r < 4; ++r) acc[mf][nf][r] = 0.f;

        panel_mma128(Am, Ws0, acc, warp_m, warp_n, rr, kl);

        xt_attn_epilogue(acc, att_dst, att_src, (float*)Ah4, Ch,
                         n0, n_rows, warp_m, warp_n, lane);
    }
}

// ---------------- small kernels ----------------
__global__ void init_transpose_kernel(const float* __restrict__ wih,
                                      const float* __restrict__ whh)
{
    int i = blockIdx.x * blockDim.x + threadIdx.x;
    int T = gridDim.x * blockDim.x;
    for (int k = i; k < NN; k += T) g_cnt[k] = 0;
    if (i < DD) { g_bnsum[i] = 0.f; g_bnsumsq[i] = 0.f; }
    for (int k = i; k < G3 * DD; k += T) {
        int j = k >> 6, c = k & 63;
        g_wihT[c * G3 + j] = wih[k];
        g_whhT[c * G3 + j] = whh[k];
    }
}

__global__ void __launch_bounds__(256) bn_stats_kernel()
{
    __shared__ float ssum[DD], ssq[DD];
    int t = threadIdx.x;
    if (t < DD) { ssum[t] = 0.f; ssq[t] = 0.f; }
    __syncthreads();

    int cg = (t & 15) * 4;
    int rpos = (blockIdx.x * 256 + t) >> 4;
    int rstride = (gridDim.x * 256) >> 4;
    float s[4] = {0.f, 0.f, 0.f, 0.f}, q[4] = {0.f, 0.f, 0.f, 0.f};
    for (int r = rpos; r < NN; r += rstride) {
        float4 v = *(const float4*)(g_h0 + (size_t)r * 64 + cg);
        s[0] += v.x; q[0] += v.x * v.x;
        s[1] += v.y; q[1] += v.y * v.y;
        s[2] += v.z; q[2] += v.z * v.z;
        s[3] += v.w; q[3] += v.w * v.w;
    }
#pragma unroll
    for (int k = 0; k < 4; ++k) {
        s[k] += __shfl_xor_sync(0xffffffffu, s[k], 16);
        q[k] += __shfl_xor_sync(0xffffffffu, q[k], 16);
    }
    if ((t & 31) < 16) {
#pragma unroll
        for (int k = 0; k < 4; ++k) {
            atomicAdd(&ssum[cg + k], s[k]);
            atomicAdd(&ssq[cg + k], q[k]);
        }
    }
    __syncthreads();
    if (t < DD) {
        atomicAdd(&g_bnsum[t], ssum[t]);
        atomicAdd(&g_bnsumsq[t], ssq[t]);
    }
}

__global__ void hist_kernel(const int* __restrict__ eidx)
{
    const int4* d4 = (const int4*)(eidx + EE);
    int i = blockIdx.x * blockDim.x + threadIdx.x;
    int T = gridDim.x * blockDim.x;
    for (int e = i; e < EE / 4; e += T) {
        int4 v = d4[e];
        atomicAdd(&g_cnt[v.x], 1);
        atomicAdd(&g_cnt[v.y], 1);
        atomicAdd(&g_cnt[v.z], 1);
        atomicAdd(&g_cnt[v.w], 1);
    }
}

// coalesced shuffle-based block scan over tiles of 1024
__global__ void scan_kernel()
{
    __shared__ int warpsum[32];
    __shared__ int carry_s;
    int t = threadIdx.x;
    int lane = t & 31, wid = t >> 5;
    if (t == 0) carry_s = 0;
    __syncthreads();
    for (int base = 0; base < NN; base += 1024) {
        int i = base + t;
        int v = (i < NN) ? g_cnt[i] : 0;
        int x = v;
#pragma unroll
        for (int o = 1; o < 32; o <<= 1) {
            int u = __shfl_up_sync(0xffffffffu, x, o);
            if (lane >= o) x += u;
        }
        if (lane == 31) warpsum[wid] = x;
        __syncthreads();
        if (wid == 0) {
            int w = warpsum[lane];
#pragma unroll
            for (int o = 1; o < 32; o <<= 1) {
                int u = __shfl_up_sync(0xffffffffu, w, o);
                if (lane >= o) w += u;
            }
            warpsum[lane] = w;
        }
        __syncthreads();
        int wprefix = (wid > 0) ? warpsum[wid - 1] : 0;
        int excl = carry_s + wprefix + x - v;
        if (i < NN) { g_rowstart[i] = excl; g_cursor[i] = excl; }
        __syncthreads();
        if (t == 1023) carry_s += warpsum[31];
        __syncthreads();
    }
}

__global__ void scatter_kernel(const int* __restrict__ eidx,
                               const float* __restrict__ edge_attr,
                               const float* __restrict__ att_edge)
{
    float a0 = att_edge[0], a1 = att_edge[1], a2 = att_edge[2];
    const int4* s4 = (const int4*)eidx;
    const int4* d4 = (const int4*)(eidx + EE);
    const float4* ea4 = (const float4*)edge_attr;
    int i = blockIdx.x * blockDim.x + threadIdx.x;
    int T = gridDim.x * blockDim.x;
    for (int e = i; e < EE / 4; e += T) {
        int4 s = s4[e];
        int4 d = d4[e];
        float4 q0 = ea4[e * 3 + 0];
        float4 q1 = ea4[e * 3 + 1];
        float4 q2 = ea4[e * 3 + 2];
        float eb0 = q0.x * a0 + q0.y * a1 + q0.z * a2;
        float eb1 = q0.w * a0 + q1.x * a1 + q1.y * a2;
        float eb2 = q1.z * a0 + q1.w * a1 + q2.x * a2;
        float eb3 = q2.y * a0 + q2.z * a1 + q2.w * a2;
        g_edge[atomicAdd(&g_cursor[d.x], 1)] = make_int2(s.x, __float_as_int(eb0));
        g_edge[atomicAdd(&g_cursor[d.y], 1)] = make_int2(s.y, __float_as_int(eb1));
        g_edge[atomicAdd(&g_cursor[d.z], 1)] = make_int2(s.z, __float_as_int(eb2));
        g_edge[atomicAdd(&g_cursor[d.w], 1)] = make_int2(s.w, __float_as_int(eb3));
    }
}

// fused softmax + aggregation: single-pass exp, 8-wide half2 gather
__global__ void __launch_bounds__(256) attn_agg_kernel()
{
    __shared__ float slog[8 * 128];
    __shared__ int   ssi[8 * 128];

    int wslot = threadIdx.x >> 5;
    int n = blockIdx.x * 8 + wslot;
    int lane = threadIdx.x & 31;
    if (n >= NN) return;
    int deg = g_cnt[n], s0 = g_rowstart[n];
    float adst = g_adst[n];
    const __half2* xh2 = (const __half2*)g_xth;
    float* lw = slog + wslot * 128;
    int*   li = ssi + wslot * 128;
    float ax0 = 0.f, ay0 = 0.f, ax1 = 0.f, ay1 = 0.f, sum = 0.f;

    if (deg <= 128) {
        for (int j = lane; j < deg; j += 32) {
            int2 e = g_edge[s0 + j];
            float l = adst + g_asrc[e.x] + __int_as_float(e.y);
            l = l >= 0.f ? l : SLOPE * l;
            float ex = __expf(l);
            li[j] = e.x;
            lw[j] = ex;
            sum += ex;
        }
        __syncwarp();
        int j = 0;
        for (; j + 8 <= deg; j += 8) {
            float w0 = lw[j + 0], w1 = lw[j + 1], w2 = lw[j + 2], w3 = lw[j + 3];
            float w4 = lw[j + 4], w5 = lw[j + 5], w6 = lw[j + 6], w7 = lw[j + 7];
            float2 v0 = __half22float2(xh2[li[j + 0] * 32 + lane]);
            float2 v1 = __half22float2(xh2[li[j + 1] * 32 + lane]);
            float2 v2 = __half22float2(xh2[li[j + 2] * 32 + lane]);
            float2 v3 = __half22float2(xh2[li[j + 3] * 32 + lane]);
            float2 v4 = __half22float2(xh2[li[j + 4] * 32 + lane]);
            float2 v5 = __half22float2(xh2[li[j + 5] * 32 + lane]);
            float2 v6 = __half22float2(xh2[li[j + 6] * 32 + lane]);
            float2 v7 = __half22float2(xh2[li[j + 7] * 32 + lane]);
            ax0 += w0 * v0.x + w1 * v1.x + w2 * v2.x + w3 * v3.x;
            ay0 += w0 * v0.y + w1 * v1.y + w2 * v2.y + w3 * v3.y;
            ax1 += w4 * v4.x + w5 * v5.x + w6 * v6.x + w7 * v7.x;
            ay1 += w4 * v4.y + w5 * v5.y + w6 * v6.y + w7 * v7.y;
        }
        for (; j < deg; ++j) {
            float2 v = __half22float2(xh2[li[j] * 32 + lane]);
            ax0 += lw[j] * v.x; ay0 += lw[j] * v.y;
        }
    } else {
        for (int c0 = 0; c0 < deg; c0 += 128) {
            int cnt = deg - c0; if (cnt > 128) cnt = 128;
            __syncwarp();
#pragma unroll
            for (int u = 0; u < 4; ++u) {
                int sl = lane + 32 * u;
                int j = c0 + sl;
                if (sl < cnt) {
                    int2 e = g_edge[s0 + j];
                    float l = adst + g_asrc[e.x] + __int_as_float(e.y);
                    l = l >= 0.f ? l : SLOPE * l;
                    float ex = __expf(l);
                    sum += ex;
                    lw[sl] = ex;
                    li[sl] = e.x;
                }
            }
            __syncwarp();
            for (int j = 0; j < cnt; ++j) {
                float2 v = __half22float2(xh2[li[j] * 32 + lane]);
                ax0 += lw[j] * v.x; ay0 += lw[j] * v.y;
            }
        }
    }

    float ax = ax0 + ax1, ay = ay0 + ay1;
#pragma unroll
    for (int o = 16; o; o >>= 1)
        sum += __shfl_xor_sync(0xffffffffu, sum, o);
    float dinv = (deg > 0) ? 1.f / sum : 0.f;
    float2 o;
    o.x = fmaxf(ax * dinv, 0.f);
    o.y = fmaxf(ay * dinv, 0.f);
    ((float2*)g_m)[n * 32 + lane] = o;
}

// ---------------- launch ----------------
extern "C" void kernel_launch(void* const* d_in, const int* in_sizes, int n_in,
                              void* d_out, int out_size)
{
    const float* x        = (const float*)d_in[0];
    const float* edge_at  = (const float*)d_in[1];
    const float* mlp_w    = (const float*)d_in[2];
    const float* mlp_b    = (const float*)d_in[3];
    const float* bn_g     = (const float*)d_in[4];
    const float* bn_b     = (const float*)d_in[5];
    const float* conv_w   = (const float*)d_in[6];
    const float* att_dst  = (const float*)d_in[7];
    const float* att_src  = (const float*)d_in[8];
    const float* att_edge = (const float*)d_in[9];
    const float* w_ih     = (const float*)d_in[10];
    const float* w_hh     = (const float*)d_in[11];
    const float* b_ih     = (const float*)d_in[12];
    const float* b_hh     = (const float*)d_in[13];
    const float* lin_w    = (const float*)d_in[14];
    const float* lin_b    = (const float*)d_in[15];
    const int*   eidx     = (const int*)d_in[16];   // int32 (JAX x64 disabled)
    float* out = (float*)d_out;

    float *p_h0, *p_h;
    __half *p_xth;
    cudaGetSymbolAddress((void**)&p_h0,  g_h0);
    cudaGetSymbolAddress((void**)&p_h,   g_h);
    cudaGetSymbolAddress((void**)&p_xth, g_xth);

    cudaFuncSetAttribute(gru_fused_kernel<true>,
                         cudaFuncAttributeMaxDynamicSharedMemorySize, 98304);
    cudaFuncSetAttribute(gru_fused_kernel<false>,
                         cudaFuncAttributeMaxDynamicSharedMemorySize, 98304);

    const int GB  = (NN + 127) / 128;   // 391
    const int WPB = (NN + 7) / 8;       // 6250

    init_transpose_kernel<<<64, 256>>>(w_ih, w_hh);
    gemm128_tf32_kernel<<<dim3(GB, 1), 256>>>(x, mlp_w, mlp_b, nullptr, p_h0, NN, DD);
    bn_stats_kernel<<<256, 256>>>();
    hist_kernel<<<1024, 256>>>(eidx);
    scan_kernel<<<1, 1024>>>();
    scatter_kernel<<<1024, 256>>>(eidx, edge_at, att_edge);

    // step 0 conv with fused BN apply (reads h0, writes h and xt/attn scores)
    gemm64h_bn_attn_kernel<<<GB, 256>>>(conv_w, att_dst, att_src,
                                        bn_g, bn_b, p_xth, NN);

    // step 0
    attn_agg_kernel<<<WPB, 256>>>();
    gru_fused_kernel<true><<<GB, 256, 98304>>>(b_ih, b_hh, conv_w,
                                               att_dst, att_src, p_xth, NN);
    // step 1
    attn_agg_kernel<<<WPB, 256>>>();
    gru_fused_kernel<true><<<GB, 256, 98304>>>(b_ih, b_hh, conv_w,
                                               att_dst, att_src, p_xth, NN);
    // step 2 (no conv needed after)
    attn_agg_kernel<<<WPB, 256>>>();
    gru_fused_kernel<false><<<GB, 256, 98304>>>(b_ih, b_hh, nullptr,
                                                nullptr, nullptr, nullptr, NN);

    gemm128_tf32_kernel<<<dim3(GB, 1), 256>>>(x, lin_w, lin_b, p_h, out, NN, DD);
}